// round 1
// baseline (speedup 1.0000x reference)
#include <cuda_runtime.h>
#include <cuda_bf16.h>
#include <math.h>

// Problem constants
#define BB  2
#define SS  2048
#define HH  1024
#define NHD 16      // num heads
#define HDD 64      // head dim
#define RHH 4       // kv heads
#define MM  (BB*SS) // 4096 token rows

// ---------------- scratch (static device memory; no allocs allowed) ----------
__device__ float g_gates[MM];
__device__ float g_q[(size_t)MM * HH];       // 16 MB
__device__ float g_k[(size_t)MM * (RHH*HDD)]; // 4 MB
__device__ float g_v[(size_t)MM * (RHH*HDD)]; // 4 MB
__device__ float g_attn[(size_t)MM * HH];    // 16 MB

// ---------------- gate: LN + dot(wg) + sigmoid(clamp) -----------------------
__global__ void gate_kernel(const float* __restrict__ x,
                            const float* __restrict__ wg,
                            const float* __restrict__ bg,
                            const float* __restrict__ gamma,
                            const float* __restrict__ beta,
                            float* __restrict__ gates) {
    int token = blockIdx.x;
    const float* row = x + (size_t)token * HH;
    __shared__ float red[256];
    int tid = threadIdx.x;

    // cache this thread's 4 elements
    float xr[4];
#pragma unroll
    for (int i = 0; i < 4; i++) xr[i] = row[tid + i * 256];

    float s = xr[0] + xr[1] + xr[2] + xr[3];
    red[tid] = s; __syncthreads();
    for (int o = 128; o > 0; o >>= 1) { if (tid < o) red[tid] += red[tid + o]; __syncthreads(); }
    float mu = red[0] * (1.0f / HH);
    __syncthreads();

    float v = 0.f;
#pragma unroll
    for (int i = 0; i < 4; i++) { float d = xr[i] - mu; v = fmaf(d, d, v); }
    red[tid] = v; __syncthreads();
    for (int o = 128; o > 0; o >>= 1) { if (tid < o) red[tid] += red[tid + o]; __syncthreads(); }
    float rstd = rsqrtf(red[0] * (1.0f / HH) + 1e-5f);
    __syncthreads();

    float dot = 0.f;
#pragma unroll
    for (int i = 0; i < 4; i++) {
        int h = tid + i * 256;
        float y = fmaf((xr[i] - mu) * rstd, gamma[h], beta[h]);
        dot = fmaf(y, wg[h], dot);
    }
    red[tid] = dot; __syncthreads();
    for (int o = 128; o > 0; o >>= 1) { if (tid < o) red[tid] += red[tid + o]; __syncthreads(); }
    if (tid == 0) {
        float z = red[0] + bg[0];
        z = fminf(10.f, fmaxf(-10.f, z));
        gates[token] = 1.f / (1.f + expf(-z));
    }
}

// ---------------- generic GEMM: C[M,N] = A[M,K] @ B[N,K]^T -------------------
#define GTS 64
#define GBK 32
__global__ void gemm_nt(const float* __restrict__ A, const float* __restrict__ Bm,
                        float* __restrict__ C, int M, int N, int K) {
    __shared__ float As[GTS][GBK + 1];
    __shared__ float Bs[GTS][GBK + 1];
    int bx = blockIdx.x, by = blockIdx.y;
    int tid = threadIdx.x;
    int tx = tid & 15, ty = tid >> 4;
    int rowBase = by * GTS, colBase = bx * GTS;
    float acc[4][4] = {};

    for (int k0 = 0; k0 < K; k0 += GBK) {
        for (int e = tid; e < GTS * GBK; e += 256) {
            int r = e >> 5, kk = e & 31;
            As[r][kk] = A[(size_t)(rowBase + r) * K + k0 + kk];
            Bs[r][kk] = Bm[(size_t)(colBase + r) * K + k0 + kk];
        }
        __syncthreads();
#pragma unroll
        for (int kk = 0; kk < GBK; kk++) {
            float a[4], b[4];
#pragma unroll
            for (int i = 0; i < 4; i++) a[i] = As[ty * 4 + i][kk];
#pragma unroll
            for (int j = 0; j < 4; j++) b[j] = Bs[tx * 4 + j][kk];
#pragma unroll
            for (int i = 0; i < 4; i++)
#pragma unroll
                for (int j = 0; j < 4; j++)
                    acc[i][j] = fmaf(a[i], b[j], acc[i][j]);
        }
        __syncthreads();
    }
#pragma unroll
    for (int i = 0; i < 4; i++)
#pragma unroll
        for (int j = 0; j < 4; j++)
            C[(size_t)(rowBase + ty * 4 + i) * N + colBase + tx * 4 + j] = acc[i][j];
}

// ---------------- flash attention with dual (gate-selected) mask -------------
// Tiles: 64 q-rows x 64 k-cols, HD=64. 256 threads: row = tid/4, sub = tid%4.
// Each thread: 16 score cols (col = jj*4+sub) and 16 output dims (d = dd*4+sub).
#define ATTN_SMEM (4 * 64 * 65 * 4)
__global__ void attn_kernel(const float* __restrict__ q, const float* __restrict__ k,
                            const float* __restrict__ v, const float* __restrict__ gates,
                            float* __restrict__ attn) {
    extern __shared__ float sm[];
    float* sQ = sm;
    float* sK = sQ + 64 * 65;
    float* sV = sK + 64 * 65;
    float* sP = sV + 64 * 65;

    int qb = blockIdx.x;   // 0..31
    int h  = blockIdx.y;   // 0..15
    int b  = blockIdx.z;   // 0..1
    int q0 = qb * 64;
    int tid = threadIdx.x;
    int r = tid >> 2, sub = tid & 3;

    for (int e = tid; e < 64 * 64; e += 256) {
        int rr = e >> 6, d = e & 63;
        sQ[rr * 65 + d] = q[((size_t)(b * SS + q0 + rr)) * HH + h * HDD + d];
    }

    int i = q0 + r;
    bool islocal = gates[b * SS + i] <= 0.5f;
    int kvh = h & 3;

    float m = -INFINITY, l = 0.f;
    float o[16];
#pragma unroll
    for (int dd = 0; dd < 16; dd++) o[dd] = 0.f;

    int kbEnd = min(qb + 2, SS / 64);
    for (int kb = 0; kb < kbEnd; kb++) {
        __syncthreads();   // previous iter finished consuming sK/sV/sP
        for (int e = tid; e < 64 * 64; e += 256) {
            int rr = e >> 6, d = e & 63;
            size_t idx = ((size_t)(b * SS + kb * 64 + rr)) * (RHH * HDD) + kvh * HDD + d;
            sK[rr * 65 + d] = k[idx];
            sV[rr * 65 + d] = v[idx];
        }
        __syncthreads();

        float s[16];
#pragma unroll
        for (int jj = 0; jj < 16; jj++) s[jj] = 0.f;
#pragma unroll
        for (int d = 0; d < 64; d++) {
            float qd = sQ[r * 65 + d];
#pragma unroll
            for (int jj = 0; jj < 16; jj++)
                s[jj] = fmaf(qd, sK[(jj * 4 + sub) * 65 + d], s[jj]);
        }

        float rmax = -INFINITY;
#pragma unroll
        for (int jj = 0; jj < 16; jj++) {
            int jg = kb * 64 + jj * 4 + sub;
            bool valid = islocal ? (abs(i - jg) <= 64) : (jg <= i);
            s[jj] = valid ? s[jj] * 0.125f : -INFINITY;
            rmax = fmaxf(rmax, s[jj]);
        }
        rmax = fmaxf(rmax, __shfl_xor_sync(0xffffffffu, rmax, 1));
        rmax = fmaxf(rmax, __shfl_xor_sync(0xffffffffu, rmax, 2));

        float mnew = fmaxf(m, rmax);
        // -inf-safe: fmaxf(nan,-80)=-80 when all masked so far
        float alpha = __expf(fmaxf(m - mnew, -80.f));
        float rsum = 0.f;
#pragma unroll
        for (int jj = 0; jj < 16; jj++) {
            float p = __expf(fmaxf(s[jj] - mnew, -80.f));
            // fully-masked entries contribute exp(-80) ~ 1.8e-35: negligible
            rsum += p;
            sP[r * 65 + jj * 4 + sub] = p;
        }
        rsum += __shfl_xor_sync(0xffffffffu, rsum, 1);
        rsum += __shfl_xor_sync(0xffffffffu, rsum, 2);

        // correct the all-masked-block case: if mnew still -inf, p above is exp(-80)
        // per entry; that inflates l by 64*1.8e-35 which is harmless, and o by
        // p*V ~ 1e-33 which is harmless relative to later real contributions.
        m = mnew;
        l = l * alpha + rsum;
#pragma unroll
        for (int dd = 0; dd < 16; dd++) o[dd] *= alpha;

        __syncthreads();  // sP visible to whole row group
#pragma unroll
        for (int j = 0; j < 64; j++) {
            float pj = sP[r * 65 + j];
#pragma unroll
            for (int dd = 0; dd < 16; dd++)
                o[dd] = fmaf(pj, sV[j * 65 + dd * 4 + sub], o[dd]);
        }
    }

    float inv = (l > 0.f) ? 1.f / l : 0.f;
#pragma unroll
    for (int dd = 0; dd < 16; dd++)
        attn[((size_t)(b * SS + i)) * HH + h * HDD + dd * 4 + sub] = o[dd] * inv;
}

// ---------------- gate regularization loss (deterministic reduction) ---------
__global__ void regloss_kernel(const float* __restrict__ gates, float* __restrict__ out,
                               int writeIdx) {
    __shared__ float red[256];
    int tid = threadIdx.x;
    float acc = 0.f;
    for (int t = tid; t < MM; t += 256) {
        float g = gates[t];
        float gs = fminf(fmaxf(g, 1e-5f), 1.f - 1e-5f);
        float binary = g * (1.f - g);
        float ent = g * logf(gs) + (1.f - g) * logf(1.f - gs);
        acc += 0.1f * binary - 0.01f * ent + 0.1f * g;
    }
    red[tid] = acc; __syncthreads();
    for (int o = 128; o > 0; o >>= 1) { if (tid < o) red[tid] += red[tid + o]; __syncthreads(); }
    if (tid == 0) out[writeIdx] = red[0] * (1.0f / MM);
}

// ---------------- launch ------------------------------------------------------
extern "C" void kernel_launch(void* const* d_in, const int* in_sizes, int n_in,
                              void* d_out, int out_size) {
    const float* x     = (const float*)d_in[0];
    const float* Wq    = (const float*)d_in[1];
    const float* Wk    = (const float*)d_in[2];
    const float* Wv    = (const float*)d_in[3];
    const float* Wo    = (const float*)d_in[4];
    const float* Wg    = (const float*)d_in[5];
    const float* bg    = (const float*)d_in[6];
    const float* gamma = (const float*)d_in[7];
    const float* beta  = (const float*)d_in[8];
    float* out = (float*)d_out;

    float *pGates, *pQ, *pK, *pV, *pAttn;
    cudaGetSymbolAddress((void**)&pGates, g_gates);
    cudaGetSymbolAddress((void**)&pQ,     g_q);
    cudaGetSymbolAddress((void**)&pK,     g_k);
    cudaGetSymbolAddress((void**)&pV,     g_v);
    cudaGetSymbolAddress((void**)&pAttn,  g_attn);

    cudaFuncSetAttribute(attn_kernel, cudaFuncAttributeMaxDynamicSharedMemorySize, ATTN_SMEM);

    gate_kernel<<<MM, 256>>>(x, Wg, bg, gamma, beta, pGates);

    gemm_nt<<<dim3(HH / GTS, MM / GTS), 256>>>(x, Wq, pQ, MM, HH, HH);
    gemm_nt<<<dim3((RHH * HDD) / GTS, MM / GTS), 256>>>(x, Wk, pK, MM, RHH * HDD, HH);
    gemm_nt<<<dim3((RHH * HDD) / GTS, MM / GTS), 256>>>(x, Wv, pV, MM, RHH * HDD, HH);

    attn_kernel<<<dim3(SS / 64, NHD, BB), 256, ATTN_SMEM>>>(pQ, pK, pV, pGates, pAttn);

    gemm_nt<<<dim3(HH / GTS, MM / GTS), 256>>>(pAttn, Wo, out, MM, HH, HH);

    if (out_size > MM * HH)
        regloss_kernel<<<1, 256>>>(pGates, out, MM * HH);
}

// round 3
// speedup vs baseline: 1.7607x; 1.7607x over previous
#include <cuda_runtime.h>
#include <cuda_bf16.h>
#include <math.h>
#include <stdint.h>

// Problem constants
#define BB  2
#define SS  2048
#define HH  1024
#define NHD 16      // num heads
#define HDD 64      // head dim
#define RHH 4       // kv heads
#define MM  (BB*SS) // 4096 token rows

// ---------------- scratch (static device memory; no allocs allowed) ----------
__device__ float g_gates[MM];
__device__ float g_q[(size_t)MM * HH];
__device__ float g_k[(size_t)MM * (RHH*HDD)];
__device__ float g_v[(size_t)MM * (RHH*HDD)];
__device__ float g_attn[(size_t)MM * HH];

// ---------------- tf32 helpers ----------------------------------------------
__device__ __forceinline__ float to_tf32(float x) {
    uint32_t u;
    asm("cvt.rna.tf32.f32 %0, %1;" : "=r"(u) : "f"(x));
    return __uint_as_float(u);
}
__device__ __forceinline__ void tf32_split(float x, float& hi, float& lo) {
    hi = to_tf32(x);
    lo = to_tf32(x - hi);
}
__device__ __forceinline__ void mma_tf32(float* c, float a0, float a1, float a2, float a3,
                                         float b0, float b1) {
    asm volatile(
        "mma.sync.aligned.m16n8k8.row.col.f32.tf32.tf32.f32 "
        "{%0,%1,%2,%3}, {%4,%5,%6,%7}, {%8,%9}, {%0,%1,%2,%3};"
        : "+f"(c[0]), "+f"(c[1]), "+f"(c[2]), "+f"(c[3])
        : "r"(__float_as_uint(a0)), "r"(__float_as_uint(a1)),
          "r"(__float_as_uint(a2)), "r"(__float_as_uint(a3)),
          "r"(__float_as_uint(b0)), "r"(__float_as_uint(b1)));
}

// ==================== tensor-core tf32x3 GEMM ================================
// C[M,N] = A[M,K] @ B[N,K]^T. CTA tile 128x128, BK=16, double-buffered SMEM.
// 256 thr = 8 warps in 4(M) x 2(N); warp tile 32x64 = 2 x 8 m16n8 tiles.
#define BKC 16
#define PADW 20                       // row pitch in floats (bank-conflict-free)
#define STG (4 * 128 * PADW)          // floats per stage (Ahi,Alo,Bhi,Blo)
#define GM_SMEM (2 * STG * 4)         // bytes

__device__ __forceinline__ void gemm_body(const float* __restrict__ A,
                                          const float* __restrict__ B,
                                          float* __restrict__ C,
                                          int N, int K,
                                          int rowBase, int colBase, float* sm) {
    int tid = threadIdx.x, lane = tid & 31, wid = tid >> 5;
    int gid = lane >> 2, tig = lane & 3;
    int wM = wid >> 1, wN = wid & 1;

    const float* Aptr = A + (size_t)(rowBase + (tid >> 1)) * K + (tid & 1) * 8;
    const float* Bptr = B + (size_t)(colBase + (tid >> 1)) * K + (tid & 1) * 8;
    int srow = tid >> 1, scol = (tid & 1) * 8;

    float acc[2][8][4];
#pragma unroll
    for (int mt = 0; mt < 2; mt++)
#pragma unroll
        for (int nt = 0; nt < 8; nt++)
#pragma unroll
            for (int c = 0; c < 4; c++) acc[mt][nt][c] = 0.f;

    float4 ra0 = *(const float4*)(Aptr);
    float4 ra1 = *(const float4*)(Aptr + 4);
    float4 rb0 = *(const float4*)(Bptr);
    float4 rb1 = *(const float4*)(Bptr + 4);

    const int NST = K / BKC;
    for (int s = 0; s < NST; s++) {
        float* base = sm + (s & 1) * STG;
        float* sAh = base;
        float* sAl = base + 128 * PADW;
        float* sBh = base + 2 * 128 * PADW;
        float* sBl = base + 3 * 128 * PADW;

        // split + store current chunk
        {
            float4 h, l;
            float* pa = sAh + srow * PADW + scol;
            float* qa = sAl + srow * PADW + scol;
            tf32_split(ra0.x, h.x, l.x); tf32_split(ra0.y, h.y, l.y);
            tf32_split(ra0.z, h.z, l.z); tf32_split(ra0.w, h.w, l.w);
            *(float4*)pa = h; *(float4*)qa = l;
            tf32_split(ra1.x, h.x, l.x); tf32_split(ra1.y, h.y, l.y);
            tf32_split(ra1.z, h.z, l.z); tf32_split(ra1.w, h.w, l.w);
            *(float4*)(pa + 4) = h; *(float4*)(qa + 4) = l;
            float* pb = sBh + srow * PADW + scol;
            float* qb = sBl + srow * PADW + scol;
            tf32_split(rb0.x, h.x, l.x); tf32_split(rb0.y, h.y, l.y);
            tf32_split(rb0.z, h.z, l.z); tf32_split(rb0.w, h.w, l.w);
            *(float4*)pb = h; *(float4*)qb = l;
            tf32_split(rb1.x, h.x, l.x); tf32_split(rb1.y, h.y, l.y);
            tf32_split(rb1.z, h.z, l.z); tf32_split(rb1.w, h.w, l.w);
            *(float4*)(pb + 4) = h; *(float4*)(qb + 4) = l;
        }
        __syncthreads();

        // prefetch next chunk
        if (s + 1 < NST) {
            Aptr += BKC; Bptr += BKC;
            ra0 = *(const float4*)(Aptr);
            ra1 = *(const float4*)(Aptr + 4);
            rb0 = *(const float4*)(Bptr);
            rb1 = *(const float4*)(Bptr + 4);
        }

        // mma over two k8 steps
#pragma unroll
        for (int ks = 0; ks < 2; ks++) {
            int k0 = ks * 8;
            float ah[2][4], al[2][4], bh[8][2], bl[8][2];
#pragma unroll
            for (int mt = 0; mt < 2; mt++) {
                int r0 = wM * 32 + mt * 16 + gid;
                ah[mt][0] = sAh[r0 * PADW + k0 + tig];
                ah[mt][1] = sAh[(r0 + 8) * PADW + k0 + tig];
                ah[mt][2] = sAh[r0 * PADW + k0 + tig + 4];
                ah[mt][3] = sAh[(r0 + 8) * PADW + k0 + tig + 4];
                al[mt][0] = sAl[r0 * PADW + k0 + tig];
                al[mt][1] = sAl[(r0 + 8) * PADW + k0 + tig];
                al[mt][2] = sAl[r0 * PADW + k0 + tig + 4];
                al[mt][3] = sAl[(r0 + 8) * PADW + k0 + tig + 4];
            }
#pragma unroll
            for (int nt = 0; nt < 8; nt++) {
                int n0 = wN * 64 + nt * 8 + gid;
                bh[nt][0] = sBh[n0 * PADW + k0 + tig];
                bh[nt][1] = sBh[n0 * PADW + k0 + tig + 4];
                bl[nt][0] = sBl[n0 * PADW + k0 + tig];
                bl[nt][1] = sBl[n0 * PADW + k0 + tig + 4];
            }
#pragma unroll
            for (int mt = 0; mt < 2; mt++)
#pragma unroll
                for (int nt = 0; nt < 8; nt++) {
                    mma_tf32(acc[mt][nt], ah[mt][0], ah[mt][1], ah[mt][2], ah[mt][3],
                             bh[nt][0], bh[nt][1]);
                    mma_tf32(acc[mt][nt], ah[mt][0], ah[mt][1], ah[mt][2], ah[mt][3],
                             bl[nt][0], bl[nt][1]);
                    mma_tf32(acc[mt][nt], al[mt][0], al[mt][1], al[mt][2], al[mt][3],
                             bh[nt][0], bh[nt][1]);
                }
        }
        __syncthreads();
    }

    // writeout
#pragma unroll
    for (int mt = 0; mt < 2; mt++) {
        int r0 = rowBase + wM * 32 + mt * 16 + gid;
#pragma unroll
        for (int nt = 0; nt < 8; nt++) {
            int c0 = colBase + wN * 64 + nt * 8 + 2 * tig;
            *(float2*)(C + (size_t)r0 * N + c0) = make_float2(acc[mt][nt][0], acc[mt][nt][1]);
            *(float2*)(C + (size_t)(r0 + 8) * N + c0) = make_float2(acc[mt][nt][2], acc[mt][nt][3]);
        }
    }
}

__global__ __launch_bounds__(256, 1)
void gemm_mma(const float* __restrict__ A, const float* __restrict__ B,
              float* __restrict__ C, int N, int K) {
    extern __shared__ float smg[];
    gemm_body(A, B, C, N, K, blockIdx.y * 128, blockIdx.x * 128, smg);
}

// fused K+V projection: z=0 -> (Wk -> K), z=1 -> (Wv -> V)
__global__ __launch_bounds__(256, 1)
void gemm_mma_kv(const float* __restrict__ A,
                 const float* __restrict__ Wk, const float* __restrict__ Wv,
                 float* __restrict__ Ko, float* __restrict__ Vo, int N, int K) {
    extern __shared__ float smg[];
    const float* B = blockIdx.z ? Wv : Wk;
    float* C = blockIdx.z ? Vo : Ko;
    gemm_body(A, B, C, N, K, blockIdx.y * 128, blockIdx.x * 128, smg);
}

// ---------------- gate: LN + dot(wg) + sigmoid(clamp) -----------------------
__global__ void gate_kernel(const float* __restrict__ x,
                            const float* __restrict__ wg,
                            const float* __restrict__ bg,
                            const float* __restrict__ gamma,
                            const float* __restrict__ beta,
                            float* __restrict__ gates) {
    int token = blockIdx.x;
    const float* row = x + (size_t)token * HH;
    __shared__ float red[256];
    int tid = threadIdx.x;

    float xr[4];
#pragma unroll
    for (int i = 0; i < 4; i++) xr[i] = row[tid + i * 256];

    float s = xr[0] + xr[1] + xr[2] + xr[3];
    red[tid] = s; __syncthreads();
    for (int o = 128; o > 0; o >>= 1) { if (tid < o) red[tid] += red[tid + o]; __syncthreads(); }
    float mu = red[0] * (1.0f / HH);
    __syncthreads();

    float v = 0.f;
#pragma unroll
    for (int i = 0; i < 4; i++) { float d = xr[i] - mu; v = fmaf(d, d, v); }
    red[tid] = v; __syncthreads();
    for (int o = 128; o > 0; o >>= 1) { if (tid < o) red[tid] += red[tid + o]; __syncthreads(); }
    float rstd = rsqrtf(red[0] * (1.0f / HH) + 1e-5f);
    __syncthreads();

    float dot = 0.f;
#pragma unroll
    for (int i = 0; i < 4; i++) {
        int h = tid + i * 256;
        float y = fmaf((xr[i] - mu) * rstd, gamma[h], beta[h]);
        dot = fmaf(y, wg[h], dot);
    }
    red[tid] = dot; __syncthreads();
    for (int o = 128; o > 0; o >>= 1) { if (tid < o) red[tid] += red[tid + o]; __syncthreads(); }
    if (tid == 0) {
        float z = red[0] + bg[0];
        z = fminf(10.f, fmaxf(-10.f, z));
        gates[token] = 1.f / (1.f + expf(-z));
    }
}

// ---------------- flash attention, fp32, 4x4 micro-tiles ---------------------
// 256 threads: ty=tid/16 (q rows 4ty..4ty+3), tx=tid%16.
// Score cols: tx+16j (conflict-free sK reads). Output dims: 4tx+j (float4 V).
#define AT_SMEM ((64*64 + 64*65 + 64*64 + 64*68) * 4)
__global__ __launch_bounds__(256)
void attn_kernel(const float* __restrict__ q, const float* __restrict__ k,
                 const float* __restrict__ v, const float* __restrict__ gates,
                 float* __restrict__ attn) {
    extern __shared__ float smf[];
    float* sQ = smf;               // [64][64]
    float* sK = sQ + 64 * 64;      // [64][65]
    float* sV = sK + 64 * 65;      // [64][64]
    float* sP = sV + 64 * 64;      // [64][68]

    int qb = blockIdx.x, h = blockIdx.y, b = blockIdx.z;
    int q0 = qb * 64;
    int tid = threadIdx.x;
    int ty = tid >> 4, tx = tid & 15;
    int kvh = h & 3;

    for (int e = tid; e < 64 * 16; e += 256) {
        int row = e >> 4, c4 = e & 15;
        float4 vq = *(const float4*)(q + ((size_t)(b * SS + q0 + row)) * HH + h * HDD + c4 * 4);
        *(float4*)(sQ + row * 64 + c4 * 4) = vq;
    }

    bool isl[4]; float m[4], l[4], o[4][4];
#pragma unroll
    for (int i = 0; i < 4; i++) {
        isl[i] = gates[b * SS + q0 + ty * 4 + i] <= 0.5f;
        m[i] = -INFINITY; l[i] = 0.f;
#pragma unroll
        for (int j = 0; j < 4; j++) o[i][j] = 0.f;
    }

    int kbEnd = min(qb + 2, SS / 64);
    for (int kb = 0; kb < kbEnd; kb++) {
        __syncthreads();   // prior PV done with sK/sV/sP
        for (int e = tid; e < 64 * 16; e += 256) {
            int row = e >> 4, c4 = e & 15;
            size_t base = ((size_t)(b * SS + kb * 64 + row)) * (RHH * HDD) + kvh * HDD + c4 * 4;
            float4 k4 = *(const float4*)(k + base);
            float4 v4 = *(const float4*)(v + base);
            sK[row * 65 + c4 * 4 + 0] = k4.x;
            sK[row * 65 + c4 * 4 + 1] = k4.y;
            sK[row * 65 + c4 * 4 + 2] = k4.z;
            sK[row * 65 + c4 * 4 + 3] = k4.w;
            *(float4*)(sV + row * 64 + c4 * 4) = v4;
        }
        __syncthreads();

        float s[4][4];
#pragma unroll
        for (int i = 0; i < 4; i++)
#pragma unroll
            for (int j = 0; j < 4; j++) s[i][j] = 0.f;

#pragma unroll 4
        for (int d = 0; d < 64; d++) {
            float qa[4], kk[4];
#pragma unroll
            for (int i = 0; i < 4; i++) qa[i] = sQ[(ty * 4 + i) * 64 + d];
#pragma unroll
            for (int j = 0; j < 4; j++) kk[j] = sK[(tx + 16 * j) * 65 + d];
#pragma unroll
            for (int i = 0; i < 4; i++)
#pragma unroll
                for (int j = 0; j < 4; j++)
                    s[i][j] = fmaf(qa[i], kk[j], s[i][j]);
        }

#pragma unroll
        for (int i = 0; i < 4; i++) {
            int irow = q0 + ty * 4 + i;
            float rmax = -INFINITY;
#pragma unroll
            for (int j = 0; j < 4; j++) {
                int jg = kb * 64 + tx + 16 * j;
                bool valid = isl[i] ? (abs(irow - jg) <= 64) : (jg <= irow);
                s[i][j] = valid ? s[i][j] * 0.125f : -INFINITY;
                rmax = fmaxf(rmax, s[i][j]);
            }
            rmax = fmaxf(rmax, __shfl_xor_sync(0xffffffffu, rmax, 1));
            rmax = fmaxf(rmax, __shfl_xor_sync(0xffffffffu, rmax, 2));
            rmax = fmaxf(rmax, __shfl_xor_sync(0xffffffffu, rmax, 4));
            rmax = fmaxf(rmax, __shfl_xor_sync(0xffffffffu, rmax, 8));
            float mnew = fmaxf(m[i], rmax);
            float alpha = __expf(fmaxf(m[i] - mnew, -80.f));
            float rsum = 0.f;
#pragma unroll
            for (int j = 0; j < 4; j++) {
                float p = __expf(fmaxf(s[i][j] - mnew, -80.f));
                rsum += p;
                sP[(ty * 4 + i) * 68 + tx + 16 * j] = p;
            }
            rsum += __shfl_xor_sync(0xffffffffu, rsum, 1);
            rsum += __shfl_xor_sync(0xffffffffu, rsum, 2);
            rsum += __shfl_xor_sync(0xffffffffu, rsum, 4);
            rsum += __shfl_xor_sync(0xffffffffu, rsum, 8);
            m[i] = mnew;
            l[i] = l[i] * alpha + rsum;
#pragma unroll
            for (int j = 0; j < 4; j++) o[i][j] *= alpha;
        }
        __syncthreads();   // sP visible

#pragma unroll 2
        for (int j64 = 0; j64 < 64; j64++) {
            float pa[4];
#pragma unroll
            for (int i = 0; i < 4; i++) pa[i] = sP[(ty * 4 + i) * 68 + j64];
            float4 vb4 = *(const float4*)(sV + j64 * 64 + tx * 4);
#pragma unroll
            for (int i = 0; i < 4; i++) {
                o[i][0] = fmaf(pa[i], vb4.x, o[i][0]);
                o[i][1] = fmaf(pa[i], vb4.y, o[i][1]);
                o[i][2] = fmaf(pa[i], vb4.z, o[i][2]);
                o[i][3] = fmaf(pa[i], vb4.w, o[i][3]);
            }
        }
    }

#pragma unroll
    for (int i = 0; i < 4; i++) {
        float inv = (l[i] > 0.f) ? 1.f / l[i] : 0.f;
        float4 ov = make_float4(o[i][0] * inv, o[i][1] * inv, o[i][2] * inv, o[i][3] * inv);
        *(float4*)(attn + ((size_t)(b * SS + q0 + ty * 4 + i)) * HH + h * HDD + tx * 4) = ov;
    }
}

// ---------------- gate regularization loss (deterministic reduction) ---------
__global__ void regloss_kernel(const float* __restrict__ gates, float* __restrict__ out,
                               int writeIdx) {
    __shared__ float red[256];
    int tid = threadIdx.x;
    float acc = 0.f;
    for (int t = tid; t < MM; t += 256) {
        float g = gates[t];
        float gs = fminf(fmaxf(g, 1e-5f), 1.f - 1e-5f);
        float binary = g * (1.f - g);
        float ent = g * logf(gs) + (1.f - g) * logf(1.f - gs);
        acc += 0.1f * binary - 0.01f * ent + 0.1f * g;
    }
    red[tid] = acc; __syncthreads();
    for (int o = 128; o > 0; o >>= 1) { if (tid < o) red[tid] += red[tid + o]; __syncthreads(); }
    if (tid == 0) out[writeIdx] = red[0] * (1.0f / MM);
}

// ---------------- launch ------------------------------------------------------
extern "C" void kernel_launch(void* const* d_in, const int* in_sizes, int n_in,
                              void* d_out, int out_size) {
    const float* x     = (const float*)d_in[0];
    const float* Wq    = (const float*)d_in[1];
    const float* Wk    = (const float*)d_in[2];
    const float* Wv    = (const float*)d_in[3];
    const float* Wo    = (const float*)d_in[4];
    const float* Wg    = (const float*)d_in[5];
    const float* bg    = (const float*)d_in[6];
    const float* gamma = (const float*)d_in[7];
    const float* beta  = (const float*)d_in[8];
    float* out = (float*)d_out;

    float *pGates, *pQ, *pK, *pV, *pAttn;
    cudaGetSymbolAddress((void**)&pGates, g_gates);
    cudaGetSymbolAddress((void**)&pQ,     g_q);
    cudaGetSymbolAddress((void**)&pK,     g_k);
    cudaGetSymbolAddress((void**)&pV,     g_v);
    cudaGetSymbolAddress((void**)&pAttn,  g_attn);

    cudaFuncSetAttribute(gemm_mma, cudaFuncAttributeMaxDynamicSharedMemorySize, GM_SMEM);
    cudaFuncSetAttribute(gemm_mma_kv, cudaFuncAttributeMaxDynamicSharedMemorySize, GM_SMEM);
    cudaFuncSetAttribute(attn_kernel, cudaFuncAttributeMaxDynamicSharedMemorySize, AT_SMEM);

    gate_kernel<<<MM, 256>>>(x, Wg, bg, gamma, beta, pGates);

    gemm_mma<<<dim3(HH / 128, MM / 128), 256, GM_SMEM>>>(x, Wq, pQ, HH, HH);
    gemm_mma_kv<<<dim3((RHH * HDD) / 128, MM / 128, 2), 256, GM_SMEM>>>(
        x, Wk, Wv, pK, pV, RHH * HDD, HH);

    attn_kernel<<<dim3(SS / 64, NHD, BB), 256, AT_SMEM>>>(pQ, pK, pV, pGates, pAttn);

    gemm_mma<<<dim3(HH / 128, MM / 128), 256, GM_SMEM>>>(pAttn, Wo, out, HH, HH);

    if (out_size > MM * HH)
        regloss_kernel<<<1, 256>>>(pGates, out, MM * HH);
}

// round 4
// speedup vs baseline: 2.9646x; 1.6838x over previous
#include <cuda_runtime.h>
#include <cuda_bf16.h>
#include <math.h>
#include <stdint.h>

// Problem constants
#define BB  2
#define SS  2048
#define HH  1024
#define NHD 16      // num heads
#define HDD 64      // head dim
#define RHH 4       // kv heads
#define MM  (BB*SS) // 4096 token rows

// ---------------- scratch (static device memory; no allocs allowed) ----------
__device__ float g_gates[MM];
__device__ float g_q[(size_t)MM * HH];
__device__ float g_k[(size_t)MM * (RHH*HDD)];
__device__ float g_v[(size_t)MM * (RHH*HDD)];
__device__ float g_attn[(size_t)MM * HH];

// ---------------- bf16 helpers ----------------------------------------------
// pack two floats into bf16x2: low half = lowElem, high half = highElem
__device__ __forceinline__ uint32_t pack_bf16(float lowElem, float highElem) {
    uint32_t r;
    asm("cvt.rn.bf16x2.f32 %0, %1, %2;" : "=r"(r) : "f"(highElem), "f"(lowElem));
    return r;
}
__device__ __forceinline__ float bf16_round(float x) {
    return __bfloat162float(__float2bfloat16(x));
}
// split pair (a,b) into hi word and residual-lo word
__device__ __forceinline__ void bf16_split2(float a, float b, uint32_t& hi, uint32_t& lo) {
    hi = pack_bf16(a, b);
    lo = pack_bf16(a - bf16_round(a), b - bf16_round(b));
}
__device__ __forceinline__ void mma_bf16(float* c, uint32_t a0, uint32_t a1, uint32_t a2,
                                         uint32_t a3, uint32_t b0, uint32_t b1) {
    asm volatile(
        "mma.sync.aligned.m16n8k16.row.col.f32.bf16.bf16.f32 "
        "{%0,%1,%2,%3}, {%4,%5,%6,%7}, {%8,%9}, {%0,%1,%2,%3};"
        : "+f"(c[0]), "+f"(c[1]), "+f"(c[2]), "+f"(c[3])
        : "r"(a0), "r"(a1), "r"(a2), "r"(a3), "r"(b0), "r"(b1));
}

// ==================== tensor-core bf16x3 GEMM ================================
// C[M,N] = A[M,K] @ B[N,K]^T. CTA tile 128x128, BK=32 (2 k16 steps), dbl-buffered.
// 256 thr = 8 warps in 4(M) x 2(N); warp tile 32x64 = 2 x 8 m16n8 tiles.
// SMEM rows: 32 bf16 = 16 words, padded to PWG=20 words (conflict-free frags).
#define PWG 20
#define STGW (4 * 128 * PWG)          // words per stage (Ahi,Alo,Bhi,Blo)
#define GM_SMEM (2 * STGW * 4)        // bytes

__device__ __forceinline__ void gemm_body(const float* __restrict__ A,
                                          const float* __restrict__ B,
                                          float* __restrict__ C,
                                          int N, int K,
                                          int rowBase, int colBase, uint32_t* sm) {
    int tid = threadIdx.x, lane = tid & 31, wid = tid >> 5;
    int gid = lane >> 2, tig = lane & 3;
    int wM = wid >> 1, wN = wid & 1;

    const float* Aptr = A + (size_t)(rowBase + (tid >> 1)) * K + (tid & 1) * 16;
    const float* Bptr = B + (size_t)(colBase + (tid >> 1)) * K + (tid & 1) * 16;
    int srow = tid >> 1, sw0 = (tid & 1) * 8;

    float acc[2][8][4];
#pragma unroll
    for (int mt = 0; mt < 2; mt++)
#pragma unroll
        for (int nt = 0; nt < 8; nt++)
#pragma unroll
            for (int c = 0; c < 4; c++) acc[mt][nt][c] = 0.f;

    float4 ra[4], rb[4];
#pragma unroll
    for (int i = 0; i < 4; i++) {
        ra[i] = *(const float4*)(Aptr + i * 4);
        rb[i] = *(const float4*)(Bptr + i * 4);
    }

    const int NST = K / 32;
    for (int s = 0; s < NST; s++) {
        uint32_t* base = sm + (s & 1) * STGW;
        uint32_t* sAh = base;
        uint32_t* sAl = base + 128 * PWG;
        uint32_t* sBh = base + 2 * 128 * PWG;
        uint32_t* sBl = base + 3 * 128 * PWG;

#pragma unroll
        for (int i = 0; i < 4; i++) {
            uint32_t h0, l0, h1, l1;
            bf16_split2(ra[i].x, ra[i].y, h0, l0);
            bf16_split2(ra[i].z, ra[i].w, h1, l1);
            sAh[srow * PWG + sw0 + i * 2]     = h0;
            sAh[srow * PWG + sw0 + i * 2 + 1] = h1;
            sAl[srow * PWG + sw0 + i * 2]     = l0;
            sAl[srow * PWG + sw0 + i * 2 + 1] = l1;
            bf16_split2(rb[i].x, rb[i].y, h0, l0);
            bf16_split2(rb[i].z, rb[i].w, h1, l1);
            sBh[srow * PWG + sw0 + i * 2]     = h0;
            sBh[srow * PWG + sw0 + i * 2 + 1] = h1;
            sBl[srow * PWG + sw0 + i * 2]     = l0;
            sBl[srow * PWG + sw0 + i * 2 + 1] = l1;
        }
        __syncthreads();

        if (s + 1 < NST) {
            Aptr += 32; Bptr += 32;
#pragma unroll
            for (int i = 0; i < 4; i++) {
                ra[i] = *(const float4*)(Aptr + i * 4);
                rb[i] = *(const float4*)(Bptr + i * 4);
            }
        }

#pragma unroll
        for (int ks = 0; ks < 2; ks++) {
            uint32_t ah[2][4], al[2][4];
#pragma unroll
            for (int mt = 0; mt < 2; mt++) {
                int r0 = (wM * 32 + mt * 16 + gid) * PWG + ks * 8 + tig;
                ah[mt][0] = sAh[r0];
                ah[mt][1] = sAh[r0 + 8 * PWG];
                ah[mt][2] = sAh[r0 + 4];
                ah[mt][3] = sAh[r0 + 8 * PWG + 4];
                al[mt][0] = sAl[r0];
                al[mt][1] = sAl[r0 + 8 * PWG];
                al[mt][2] = sAl[r0 + 4];
                al[mt][3] = sAl[r0 + 8 * PWG + 4];
            }
#pragma unroll
            for (int nt = 0; nt < 8; nt++) {
                int n0 = (wN * 64 + nt * 8 + gid) * PWG + ks * 8 + tig;
                uint32_t bh0 = sBh[n0], bh1 = sBh[n0 + 4];
                uint32_t bl0 = sBl[n0], bl1 = sBl[n0 + 4];
#pragma unroll
                for (int mt = 0; mt < 2; mt++) {
                    mma_bf16(acc[mt][nt], ah[mt][0], ah[mt][1], ah[mt][2], ah[mt][3], bh0, bh1);
                    mma_bf16(acc[mt][nt], ah[mt][0], ah[mt][1], ah[mt][2], ah[mt][3], bl0, bl1);
                    mma_bf16(acc[mt][nt], al[mt][0], al[mt][1], al[mt][2], al[mt][3], bh0, bh1);
                }
            }
        }
        __syncthreads();
    }

#pragma unroll
    for (int mt = 0; mt < 2; mt++) {
        int r0 = rowBase + wM * 32 + mt * 16 + gid;
#pragma unroll
        for (int nt = 0; nt < 8; nt++) {
            int c0 = colBase + wN * 64 + nt * 8 + 2 * tig;
            *(float2*)(C + (size_t)r0 * N + c0) = make_float2(acc[mt][nt][0], acc[mt][nt][1]);
            *(float2*)(C + (size_t)(r0 + 8) * N + c0) = make_float2(acc[mt][nt][2], acc[mt][nt][3]);
        }
    }
}

__global__ __launch_bounds__(256, 1)
void gemm_mma(const float* __restrict__ A, const float* __restrict__ B,
              float* __restrict__ C, int N, int K) {
    extern __shared__ uint32_t smg[];
    gemm_body(A, B, C, N, K, blockIdx.y * 128, blockIdx.x * 128, smg);
}

__global__ __launch_bounds__(256, 1)
void gemm_mma_kv(const float* __restrict__ A,
                 const float* __restrict__ Wk, const float* __restrict__ Wv,
                 float* __restrict__ Ko, float* __restrict__ Vo, int N, int K) {
    extern __shared__ uint32_t smg[];
    const float* B = blockIdx.z ? Wv : Wk;
    float* C = blockIdx.z ? Vo : Ko;
    gemm_body(A, B, C, N, K, blockIdx.y * 128, blockIdx.x * 128, smg);
}

// ==================== mma flash attention ====================================
// CTA: 128 thr = 4 warps, Q-tile 64 rows (warp w owns rows w*16..w*16+15),
// K-block 64, HD=64. bf16 hi/lo split, 3-mma products.
// SMEM word layout, pitch PW=36 words per 64-elem row:
//   sQh[64][PW] sQl sKh sKl sVh(transposed [d][j/2]) sVl
#define PW 36
#define AT_SMEM (6 * 64 * PW * 4)

__global__ __launch_bounds__(128)
void attn_mma(const float* __restrict__ q, const float* __restrict__ k,
              const float* __restrict__ v, const float* __restrict__ gates,
              float* __restrict__ attn) {
    extern __shared__ uint32_t sw[];
    uint32_t* sQh = sw;
    uint32_t* sQl = sw + 64 * PW;
    uint32_t* sKh = sw + 2 * 64 * PW;
    uint32_t* sKl = sw + 3 * 64 * PW;
    uint32_t* sVh = sw + 4 * 64 * PW;   // transposed: row=d, word=j/2
    uint32_t* sVl = sw + 5 * 64 * PW;

    int qb = blockIdx.x, h = blockIdx.y, b = blockIdx.z;
    int q0 = qb * 64;
    int tid = threadIdx.x, lane = tid & 31, w = tid >> 5;
    int gid = lane >> 2, tig = lane & 3;
    int kvh = h & 3;

    // ---- load Q tile (scaled by 1/8), split hi/lo ----
    {
        int row = tid >> 1, dh = (tid & 1) * 32;
        const float* qp = q + ((size_t)(b * SS + q0 + row)) * HH + h * HDD + dh;
#pragma unroll
        for (int i = 0; i < 8; i++) {
            float4 vq = *(const float4*)(qp + i * 4);
            vq.x *= 0.125f; vq.y *= 0.125f; vq.z *= 0.125f; vq.w *= 0.125f;
            uint32_t h0, l0, h1, l1;
            bf16_split2(vq.x, vq.y, h0, l0);
            bf16_split2(vq.z, vq.w, h1, l1);
            int wd = row * PW + dh / 2 + i * 2;
            sQh[wd] = h0; sQh[wd + 1] = h1;
            sQl[wd] = l0; sQl[wd + 1] = l1;
        }
    }

    int i0 = q0 + w * 16 + gid, i1 = i0 + 8;
    bool isl0 = gates[b * SS + i0] <= 0.5f;
    bool isl1 = gates[b * SS + i1] <= 0.5f;

    float m0 = -1e30f, m1 = -1e30f, l0s = 0.f, l1s = 0.f;
    float o[8][4];
#pragma unroll
    for (int nt = 0; nt < 8; nt++)
#pragma unroll
        for (int c = 0; c < 4; c++) o[nt][c] = 0.f;

    int kbEnd = min(qb + 2, SS / 64);
    for (int kb = 0; kb < kbEnd; kb++) {
        __syncthreads();   // previous iter done reading sK/sV (and Q store on iter 0)

        // ---- load K tile [j][d], split ----
        {
            int row = tid >> 1, dh = (tid & 1) * 32;
            const float* kp = k + ((size_t)(b * SS + kb * 64 + row)) * (RHH * HDD) + kvh * HDD + dh;
#pragma unroll
            for (int i = 0; i < 8; i++) {
                float4 vk = *(const float4*)(kp + i * 4);
                uint32_t h0, l0, h1, l1;
                bf16_split2(vk.x, vk.y, h0, l0);
                bf16_split2(vk.z, vk.w, h1, l1);
                int wd = row * PW + dh / 2 + i * 2;
                sKh[wd] = h0; sKh[wd + 1] = h1;
                sKl[wd] = l0; sKl[wd + 1] = l1;
            }
        }
        // ---- load V transposed [d][j/2]: thread handles j-pair, 16 d's ----
        {
            int jj = (tid & 31) * 2, dblk = tid >> 5;
            const float* vp0 = v + ((size_t)(b * SS + kb * 64 + jj)) * (RHH * HDD) + kvh * HDD + dblk * 16;
            const float* vp1 = vp0 + (RHH * HDD);
            float4 r0[4], r1[4];
#pragma unroll
            for (int i = 0; i < 4; i++) {
                r0[i] = *(const float4*)(vp0 + i * 4);
                r1[i] = *(const float4*)(vp1 + i * 4);
            }
            const float* f0 = (const float*)r0;
            const float* f1 = (const float*)r1;
#pragma unroll
            for (int i = 0; i < 16; i++) {
                int d = dblk * 16 + i;
                uint32_t hi, lo;
                bf16_split2(f0[i], f1[i], hi, lo);   // low half = j even
                sVh[d * PW + (tid & 31)] = hi;
                sVl[d * PW + (tid & 31)] = lo;
            }
        }
        __syncthreads();

        // ---- QK^T: s[nt][4] over 4 k16 steps ----
        float s[8][4];
#pragma unroll
        for (int nt = 0; nt < 8; nt++)
#pragma unroll
            for (int c = 0; c < 4; c++) s[nt][c] = 0.f;

#pragma unroll
        for (int ks = 0; ks < 4; ks++) {
            int rq = (w * 16 + gid) * PW + ks * 8 + tig;
            uint32_t ah0 = sQh[rq],          ah1 = sQh[rq + 8 * PW];
            uint32_t ah2 = sQh[rq + 4],      ah3 = sQh[rq + 8 * PW + 4];
            uint32_t al0 = sQl[rq],          al1 = sQl[rq + 8 * PW];
            uint32_t al2 = sQl[rq + 4],      al3 = sQl[rq + 8 * PW + 4];
#pragma unroll
            for (int nt = 0; nt < 8; nt++) {
                int rk = (nt * 8 + gid) * PW + ks * 8 + tig;
                uint32_t bh0 = sKh[rk], bh1 = sKh[rk + 4];
                uint32_t bl0 = sKl[rk], bl1 = sKl[rk + 4];
                mma_bf16(s[nt], ah0, ah1, ah2, ah3, bh0, bh1);
                mma_bf16(s[nt], ah0, ah1, ah2, ah3, bl0, bl1);
                mma_bf16(s[nt], al0, al1, al2, al3, bh0, bh1);
            }
        }

        // ---- mask + online softmax (rows live in-warp: lanes tig 0..3) ----
        float rm0 = -1e30f, rm1 = -1e30f;
#pragma unroll
        for (int nt = 0; nt < 8; nt++) {
            int jb = kb * 64 + nt * 8 + 2 * tig;
#pragma unroll
            for (int c = 0; c < 2; c++) {
                int j = jb + c;
                bool v0 = isl0 ? (abs(i0 - j) <= 64) : (j <= i0);
                s[nt][c] = v0 ? s[nt][c] : -1e30f;
                rm0 = fmaxf(rm0, s[nt][c]);
                bool v1 = isl1 ? (abs(i1 - j) <= 64) : (j <= i1);
                s[nt][2 + c] = v1 ? s[nt][2 + c] : -1e30f;
                rm1 = fmaxf(rm1, s[nt][2 + c]);
            }
        }
        rm0 = fmaxf(rm0, __shfl_xor_sync(0xffffffffu, rm0, 1));
        rm0 = fmaxf(rm0, __shfl_xor_sync(0xffffffffu, rm0, 2));
        rm1 = fmaxf(rm1, __shfl_xor_sync(0xffffffffu, rm1, 1));
        rm1 = fmaxf(rm1, __shfl_xor_sync(0xffffffffu, rm1, 2));

        float mn0 = fmaxf(m0, rm0), mn1 = fmaxf(m1, rm1);
        float al0f = __expf(fmaxf(m0 - mn0, -80.f));
        float al1f = __expf(fmaxf(m1 - mn1, -80.f));
        float rs0 = 0.f, rs1 = 0.f;
#pragma unroll
        for (int nt = 0; nt < 8; nt++) {
#pragma unroll
            for (int c = 0; c < 2; c++) {
                float p0 = __expf(fmaxf(s[nt][c] - mn0, -80.f));
                s[nt][c] = p0; rs0 += p0;
                float p1 = __expf(fmaxf(s[nt][2 + c] - mn1, -80.f));
                s[nt][2 + c] = p1; rs1 += p1;
            }
        }
        rs0 += __shfl_xor_sync(0xffffffffu, rs0, 1);
        rs0 += __shfl_xor_sync(0xffffffffu, rs0, 2);
        rs1 += __shfl_xor_sync(0xffffffffu, rs1, 1);
        rs1 += __shfl_xor_sync(0xffffffffu, rs1, 2);
        m0 = mn0; m1 = mn1;
        l0s = l0s * al0f + rs0;
        l1s = l1s * al1f + rs1;
#pragma unroll
        for (int nt = 0; nt < 8; nt++) {
            o[nt][0] *= al0f; o[nt][1] *= al0f;
            o[nt][2] *= al1f; o[nt][3] *= al1f;
        }

        // ---- PV: P comes straight from registers as A-frags ----
#pragma unroll
        for (int ks = 0; ks < 4; ks++) {
            // A frag: k16 step ks covers score tiles 2ks (k 0-7) and 2ks+1 (k 8-15)
            float p00 = s[2 * ks][0],     p01 = s[2 * ks][1];
            float p10 = s[2 * ks][2],     p11 = s[2 * ks][3];
            float p20 = s[2 * ks + 1][0], p21 = s[2 * ks + 1][1];
            float p30 = s[2 * ks + 1][2], p31 = s[2 * ks + 1][3];
            uint32_t ah0, al0, ah1, al1, ah2, al2, ah3, al3;
            bf16_split2(p00, p01, ah0, al0);
            bf16_split2(p10, p11, ah1, al1);
            bf16_split2(p20, p21, ah2, al2);
            bf16_split2(p30, p31, ah3, al3);
#pragma unroll
            for (int nt = 0; nt < 8; nt++) {
                int rv = (nt * 8 + gid) * PW + ks * 8 + tig;
                uint32_t bh0 = sVh[rv], bh1 = sVh[rv + 4];
                uint32_t bl0 = sVl[rv], bl1 = sVl[rv + 4];
                mma_bf16(o[nt], ah0, ah1, ah2, ah3, bh0, bh1);
                mma_bf16(o[nt], ah0, ah1, ah2, ah3, bl0, bl1);
                mma_bf16(o[nt], al0, al1, al2, al3, bh0, bh1);
            }
        }
    }

    // ---- epilogue ----
    float inv0 = (l0s > 0.f) ? 1.f / l0s : 0.f;
    float inv1 = (l1s > 0.f) ? 1.f / l1s : 0.f;
    float* out0 = attn + ((size_t)(b * SS + i0)) * HH + h * HDD + 2 * tig;
    float* out1 = attn + ((size_t)(b * SS + i1)) * HH + h * HDD + 2 * tig;
#pragma unroll
    for (int nt = 0; nt < 8; nt++) {
        *(float2*)(out0 + nt * 8) = make_float2(o[nt][0] * inv0, o[nt][1] * inv0);
        *(float2*)(out1 + nt * 8) = make_float2(o[nt][2] * inv1, o[nt][3] * inv1);
    }
}

// ---------------- gate: LN + dot(wg) + sigmoid(clamp) -----------------------
__global__ void gate_kernel(const float* __restrict__ x,
                            const float* __restrict__ wg,
                            const float* __restrict__ bg,
                            const float* __restrict__ gamma,
                            const float* __restrict__ beta,
                            float* __restrict__ gates) {
    int token = blockIdx.x;
    const float* row = x + (size_t)token * HH;
    __shared__ float red[256];
    int tid = threadIdx.x;

    float xr[4];
#pragma unroll
    for (int i = 0; i < 4; i++) xr[i] = row[tid + i * 256];

    float s = xr[0] + xr[1] + xr[2] + xr[3];
    red[tid] = s; __syncthreads();
    for (int o = 128; o > 0; o >>= 1) { if (tid < o) red[tid] += red[tid + o]; __syncthreads(); }
    float mu = red[0] * (1.0f / HH);
    __syncthreads();

    float v = 0.f;
#pragma unroll
    for (int i = 0; i < 4; i++) { float d = xr[i] - mu; v = fmaf(d, d, v); }
    red[tid] = v; __syncthreads();
    for (int o = 128; o > 0; o >>= 1) { if (tid < o) red[tid] += red[tid + o]; __syncthreads(); }
    float rstd = rsqrtf(red[0] * (1.0f / HH) + 1e-5f);
    __syncthreads();

    float dot = 0.f;
#pragma unroll
    for (int i = 0; i < 4; i++) {
        int hh = tid + i * 256;
        float y = fmaf((xr[i] - mu) * rstd, gamma[hh], beta[hh]);
        dot = fmaf(y, wg[hh], dot);
    }
    red[tid] = dot; __syncthreads();
    for (int o = 128; o > 0; o >>= 1) { if (tid < o) red[tid] += red[tid + o]; __syncthreads(); }
    if (tid == 0) {
        float z = red[0] + bg[0];
        z = fminf(10.f, fmaxf(-10.f, z));
        gates[token] = 1.f / (1.f + expf(-z));
    }
}

// ---------------- gate regularization loss (deterministic reduction) ---------
__global__ void regloss_kernel(const float* __restrict__ gates, float* __restrict__ out,
                               int writeIdx) {
    __shared__ float red[256];
    int tid = threadIdx.x;
    float acc = 0.f;
    for (int t = tid; t < MM; t += 256) {
        float g = gates[t];
        float gs = fminf(fmaxf(g, 1e-5f), 1.f - 1e-5f);
        float binary = g * (1.f - g);
        float ent = g * logf(gs) + (1.f - g) * logf(1.f - gs);
        acc += 0.1f * binary - 0.01f * ent + 0.1f * g;
    }
    red[tid] = acc; __syncthreads();
    for (int o = 128; o > 0; o >>= 1) { if (tid < o) red[tid] += red[tid + o]; __syncthreads(); }
    if (tid == 0) out[writeIdx] = red[0] * (1.0f / MM);
}

// ---------------- launch ------------------------------------------------------
extern "C" void kernel_launch(void* const* d_in, const int* in_sizes, int n_in,
                              void* d_out, int out_size) {
    const float* x     = (const float*)d_in[0];
    const float* Wq    = (const float*)d_in[1];
    const float* Wk    = (const float*)d_in[2];
    const float* Wv    = (const float*)d_in[3];
    const float* Wo    = (const float*)d_in[4];
    const float* Wg    = (const float*)d_in[5];
    const float* bg    = (const float*)d_in[6];
    const float* gamma = (const float*)d_in[7];
    const float* beta  = (const float*)d_in[8];
    float* out = (float*)d_out;

    float *pGates, *pQ, *pK, *pV, *pAttn;
    cudaGetSymbolAddress((void**)&pGates, g_gates);
    cudaGetSymbolAddress((void**)&pQ,     g_q);
    cudaGetSymbolAddress((void**)&pK,     g_k);
    cudaGetSymbolAddress((void**)&pV,     g_v);
    cudaGetSymbolAddress((void**)&pAttn,  g_attn);

    cudaFuncSetAttribute(gemm_mma, cudaFuncAttributeMaxDynamicSharedMemorySize, GM_SMEM);
    cudaFuncSetAttribute(gemm_mma_kv, cudaFuncAttributeMaxDynamicSharedMemorySize, GM_SMEM);
    cudaFuncSetAttribute(attn_mma, cudaFuncAttributeMaxDynamicSharedMemorySize, AT_SMEM);

    gate_kernel<<<MM, 256>>>(x, Wg, bg, gamma, beta, pGates);

    gemm_mma<<<dim3(HH / 128, MM / 128), 256, GM_SMEM>>>(x, Wq, pQ, HH, HH);
    gemm_mma_kv<<<dim3((RHH * HDD) / 128, MM / 128, 2), 256, GM_SMEM>>>(
        x, Wk, Wv, pK, pV, RHH * HDD, HH);

    attn_mma<<<dim3(SS / 64, NHD, BB), 128, AT_SMEM>>>(pQ, pK, pV, pGates, pAttn);

    gemm_mma<<<dim3(HH / 128, MM / 128), 256, GM_SMEM>>>(pAttn, Wo, out, HH, HH);

    if (out_size > MM * HH)
        regloss_kernel<<<1, 256>>>(pGates, out, MM * HH);
}

// round 7
// speedup vs baseline: 3.0908x; 1.0426x over previous
#include <cuda_runtime.h>
#include <cuda_bf16.h>
#include <math.h>
#include <stdint.h>

// Problem constants
#define BB  2
#define SS  2048
#define HH  1024
#define NHD 16      // num heads
#define HDD 64      // head dim
#define RHH 4       // kv heads
#define MM  (BB*SS) // 4096 token rows

// ---------------- scratch (static device memory; no allocs allowed) ----------
__device__ float    g_gates[MM];
__device__ uint32_t g_qph[(size_t)MM * 512];          // Q frag-packed bf16 hi
__device__ uint32_t g_qpl[(size_t)MM * 512];          // Q frag-packed bf16 lo
__device__ uint32_t g_kp [(size_t)RHH * MM * 64];     // K frag-packed (hi+lo interleaved u4)
__device__ float    g_v  [(size_t)MM * (RHH*HDD)];    // V fp32 (gemm out)
__device__ uint4    g_vp [(size_t)BB * RHH * HDD * 512]; // V transposed frag-packed
__device__ float    g_attn[(size_t)MM * HH];

// ---------------- bf16 helpers ----------------------------------------------
__device__ __forceinline__ uint32_t pack_bf16(float lowElem, float highElem) {
    uint32_t r;
    asm("cvt.rn.bf16x2.f32 %0, %1, %2;" : "=r"(r) : "f"(highElem), "f"(lowElem));
    return r;
}
__device__ __forceinline__ float bf16_round(float x) {
    return __bfloat162float(__float2bfloat16(x));
}
__device__ __forceinline__ void bf16_split2(float a, float b, uint32_t& hi, uint32_t& lo) {
    hi = pack_bf16(a, b);
    lo = pack_bf16(a - bf16_round(a), b - bf16_round(b));
}
__device__ __forceinline__ void mma_bf16(float* c, uint32_t a0, uint32_t a1, uint32_t a2,
                                         uint32_t a3, uint32_t b0, uint32_t b1) {
    asm volatile(
        "mma.sync.aligned.m16n8k16.row.col.f32.bf16.bf16.f32 "
        "{%0,%1,%2,%3}, {%4,%5,%6,%7}, {%8,%9}, {%0,%1,%2,%3};"
        : "+f"(c[0]), "+f"(c[1]), "+f"(c[2]), "+f"(c[3])
        : "r"(a0), "r"(a1), "r"(a2), "r"(a3), "r"(b0), "r"(b1));
}
__device__ __forceinline__ uint32_t smem_u32(const void* p) {
    uint32_t a;
    asm("{ .reg .u64 t; cvta.to.shared.u64 t, %1; cvt.u32.u64 %0, t; }" : "=r"(a) : "l"(p));
    return a;
}
__device__ __forceinline__ void cpa16(uint32_t dst, const void* src) {
    asm volatile("cp.async.ca.shared.global [%0], [%1], 16;" :: "r"(dst), "l"(src));
}
#define CPA_COMMIT() asm volatile("cp.async.commit_group;" ::: "memory")
#define CPA_WAIT(n)  asm volatile("cp.async.wait_group %0;" :: "n"(n) : "memory")

// ==================== tensor-core bf16x3 GEMM ================================
// C[M,N] = A[M,K] @ B[N,K]^T. CTA tile 128x128, BK=32, dbl-buffered SMEM.
// 8 warps 4(M)x2(N); warp tile 32x64.
// mode 0: fp32 C.  mode 1: Q frag-packed bf16 hi/lo (scale 1/8) -> outh/outl.
// mode 2: K frag-packed interleaved u4 -> outh.
#define PWG 20
#define STGW (4 * 128 * PWG)
#define GM_SMEM (2 * STGW * 4)

__device__ __forceinline__ void gemm_body(const float* __restrict__ A,
                                          const float* __restrict__ B,
                                          float* __restrict__ C,
                                          uint32_t* __restrict__ outh,
                                          uint32_t* __restrict__ outl,
                                          int N, int K, int mode,
                                          int rowBase, int colBase, uint32_t* sm) {
    int tid = threadIdx.x, lane = tid & 31, wid = tid >> 5;
    int gid = lane >> 2, tig = lane & 3;
    int wM = wid >> 1, wN = wid & 1;

    const float* Aptr = A + (size_t)(rowBase + (tid >> 1)) * K + (tid & 1) * 16;
    const float* Bptr = B + (size_t)(colBase + (tid >> 1)) * K + (tid & 1) * 16;
    int srow = tid >> 1, sw0 = (tid & 1) * 8;

    float acc[2][8][4];
#pragma unroll
    for (int mt = 0; mt < 2; mt++)
#pragma unroll
        for (int nt = 0; nt < 8; nt++)
#pragma unroll
            for (int c = 0; c < 4; c++) acc[mt][nt][c] = 0.f;

    float4 ra[4], rb[4];
#pragma unroll
    for (int i = 0; i < 4; i++) {
        ra[i] = *(const float4*)(Aptr + i * 4);
        rb[i] = *(const float4*)(Bptr + i * 4);
    }

    const int NST = K / 32;
    for (int s = 0; s < NST; s++) {
        uint32_t* base = sm + (s & 1) * STGW;
        uint32_t* sAh = base;
        uint32_t* sAl = base + 128 * PWG;
        uint32_t* sBh = base + 2 * 128 * PWG;
        uint32_t* sBl = base + 3 * 128 * PWG;

#pragma unroll
        for (int i = 0; i < 4; i++) {
            uint32_t h0, l0, h1, l1;
            bf16_split2(ra[i].x, ra[i].y, h0, l0);
            bf16_split2(ra[i].z, ra[i].w, h1, l1);
            sAh[srow * PWG + sw0 + i * 2]     = h0;
            sAh[srow * PWG + sw0 + i * 2 + 1] = h1;
            sAl[srow * PWG + sw0 + i * 2]     = l0;
            sAl[srow * PWG + sw0 + i * 2 + 1] = l1;
            bf16_split2(rb[i].x, rb[i].y, h0, l0);
            bf16_split2(rb[i].z, rb[i].w, h1, l1);
            sBh[srow * PWG + sw0 + i * 2]     = h0;
            sBh[srow * PWG + sw0 + i * 2 + 1] = h1;
            sBl[srow * PWG + sw0 + i * 2]     = l0;
            sBl[srow * PWG + sw0 + i * 2 + 1] = l1;
        }
        __syncthreads();

        if (s + 1 < NST) {
            Aptr += 32; Bptr += 32;
#pragma unroll
            for (int i = 0; i < 4; i++) {
                ra[i] = *(const float4*)(Aptr + i * 4);
                rb[i] = *(const float4*)(Bptr + i * 4);
            }
        }

#pragma unroll
        for (int ks = 0; ks < 2; ks++) {
            uint32_t ah[2][4], al[2][4];
#pragma unroll
            for (int mt = 0; mt < 2; mt++) {
                int r0 = (wM * 32 + mt * 16 + gid) * PWG + ks * 8 + tig;
                ah[mt][0] = sAh[r0];
                ah[mt][1] = sAh[r0 + 8 * PWG];
                ah[mt][2] = sAh[r0 + 4];
                ah[mt][3] = sAh[r0 + 8 * PWG + 4];
                al[mt][0] = sAl[r0];
                al[mt][1] = sAl[r0 + 8 * PWG];
                al[mt][2] = sAl[r0 + 4];
                al[mt][3] = sAl[r0 + 8 * PWG + 4];
            }
#pragma unroll
            for (int nt = 0; nt < 8; nt++) {
                int n0 = (wN * 64 + nt * 8 + gid) * PWG + ks * 8 + tig;
                uint32_t bh0 = sBh[n0], bh1 = sBh[n0 + 4];
                uint32_t bl0 = sBl[n0], bl1 = sBl[n0 + 4];
#pragma unroll
                for (int mt = 0; mt < 2; mt++) {
                    mma_bf16(acc[mt][nt], ah[mt][0], ah[mt][1], ah[mt][2], ah[mt][3], bh0, bh1);
                    mma_bf16(acc[mt][nt], ah[mt][0], ah[mt][1], ah[mt][2], ah[mt][3], bl0, bl1);
                    mma_bf16(acc[mt][nt], al[mt][0], al[mt][1], al[mt][2], al[mt][3], bh0, bh1);
                }
            }
        }
        __syncthreads();
    }

    // ---------------- epilogue ----------------
    if (mode == 0) {
#pragma unroll
        for (int mt = 0; mt < 2; mt++) {
            int r0 = rowBase + wM * 32 + mt * 16 + gid;
#pragma unroll
            for (int nt = 0; nt < 8; nt++) {
                int c0 = colBase + wN * 64 + nt * 8 + 2 * tig;
                *(float2*)(C + (size_t)r0 * N + c0) = make_float2(acc[mt][nt][0], acc[mt][nt][1]);
                *(float2*)(C + (size_t)(r0 + 8) * N + c0) = make_float2(acc[mt][nt][2], acc[mt][nt][3]);
            }
        }
    } else if (mode == 1) {   // Q frag-packed, scaled 1/8
#pragma unroll
        for (int mt = 0; mt < 2; mt++) {
            int r0 = rowBase + wM * 32 + mt * 16 + gid;
            int rp = r0 >> 4;
#pragma unroll
            for (int nt = 0; nt < 8; nt++) {
                int c0 = colBase + wN * 64 + nt * 8 + 2 * tig;
                int h = c0 >> 6, wl = (c0 & 63) >> 1;
                int ks = wl >> 3, tigg = wl & 7;
                int tA = tigg & 3, comp = (tigg & 4) ? 2 : 0;
                size_t wi = (((((size_t)rp * 16 + h) * 8 + gid) * 4 + ks) * 4 + tA) * 4 + comp;
                uint32_t h0, l0, h1, l1;
                bf16_split2(acc[mt][nt][0] * 0.125f, acc[mt][nt][1] * 0.125f, h0, l0);
                bf16_split2(acc[mt][nt][2] * 0.125f, acc[mt][nt][3] * 0.125f, h1, l1);
                outh[wi] = h0; outh[wi + 1] = h1;
                outl[wi] = l0; outl[wi + 1] = l1;
            }
        }
    } else {                  // K frag-packed interleaved (h_t, h_t4, l_t, l_t4)
#pragma unroll
        for (int mt = 0; mt < 2; mt++) {
            int r0 = rowBase + wM * 32 + mt * 16 + gid;
#pragma unroll
            for (int nt = 0; nt < 8; nt++) {
                int c0 = colBase + wN * 64 + nt * 8 + 2 * tig;
                int kvh = c0 >> 6, wl = (c0 & 63) >> 1;
                int ks = wl >> 3, tigg = wl & 7;
                int tA = tigg & 3, comp = (tigg & 4) ? 1 : 0;
                size_t wi0 = (((size_t)kvh * MM + r0) * 16 + ks * 4 + tA) * 4;
                size_t wi1 = wi0 + 8 * 16 * 4;
                uint32_t h0, l0, h1, l1;
                bf16_split2(acc[mt][nt][0], acc[mt][nt][1], h0, l0);
                bf16_split2(acc[mt][nt][2], acc[mt][nt][3], h1, l1);
                outh[wi0 + comp] = h0; outh[wi0 + comp + 2] = l0;
                outh[wi1 + comp] = h1; outh[wi1 + comp + 2] = l1;
            }
        }
    }
}

__global__ __launch_bounds__(256, 1)
void gemm_mma(const float* __restrict__ A, const float* __restrict__ B,
              float* __restrict__ C, uint32_t* __restrict__ outh,
              uint32_t* __restrict__ outl, int N, int K, int mode) {
    extern __shared__ uint32_t smg[];
    gemm_body(A, B, C, outh, outl, N, K, mode, blockIdx.y * 128, blockIdx.x * 128, smg);
}

// fused K+V projection: z=0 -> K frag-packed, z=1 -> V fp32
__global__ __launch_bounds__(256, 1)
void gemm_mma_kv(const float* __restrict__ A,
                 const float* __restrict__ Wk, const float* __restrict__ Wv,
                 uint32_t* __restrict__ kp, float* __restrict__ Vo, int N, int K) {
    extern __shared__ uint32_t smg[];
    if (blockIdx.z)
        gemm_body(A, Wv, Vo, nullptr, nullptr, N, K, 0, blockIdx.y * 128, blockIdx.x * 128, smg);
    else
        gemm_body(A, Wk, nullptr, kp, nullptr, N, K, 2, blockIdx.y * 128, blockIdx.x * 128, smg);
}

// ---------------- V transpose + split + frag-pack ----------------------------
__global__ __launch_bounds__(128)
void v_pack(const float* __restrict__ v, uint4* __restrict__ vp) {
    __shared__ float sm[64 * 68];
    int kb = blockIdx.x, kvh = blockIdx.y, b = blockIdx.z;
    int tid = threadIdx.x;
    for (int e = tid; e < 64 * 16; e += 128) {
        int row = e >> 4, c4 = e & 15;
        float4 t4 = *(const float4*)(v + ((size_t)(b * SS + kb * 64 + row)) * (RHH * HDD)
                                       + kvh * HDD + c4 * 4);
        sm[row * 68 + c4 * 4 + 0] = t4.x;
        sm[row * 68 + c4 * 4 + 1] = t4.y;
        sm[row * 68 + c4 * 4 + 2] = t4.z;
        sm[row * 68 + c4 * 4 + 3] = t4.w;
    }
    __syncthreads();
    int d = tid & 63, kshalf = tid >> 6;
    size_t base = ((size_t)(b * RHH + kvh) * 64 + d) * 512 + kb * 16;
#pragma unroll
    for (int kk = 0; kk < 2; kk++) {
        int ks = kshalf * 2 + kk;
#pragma unroll
        for (int tg = 0; tg < 4; tg++) {
            int j0 = (ks * 8 + tg) * 2, j1 = (ks * 8 + tg + 4) * 2;
            float a  = sm[j0 * 68 + d],       b2 = sm[(j0 + 1) * 68 + d];
            float c  = sm[j1 * 68 + d],       d2 = sm[(j1 + 1) * 68 + d];
            uint32_t hx, lx, hy, ly;
            bf16_split2(a, b2, hx, lx);
            bf16_split2(c, d2, hy, ly);
            vp[base + ks * 4 + tg] = make_uint4(hx, hy, lx, ly);
        }
    }
}

// ==================== mma flash attention (frag-packed, cp.async) ============
// CTA: 256 thr = 8 warps, q-tile 128 rows (warp w: rows q0+w*16..+15), K-block 64.
// SMEM (uint4): sQh[0..1023] sQl[1024..2047] K buf{0,1}@2048+b*1280, V @4608+b*1280.
// K/V row pitch 20 u4 (conflict-free frag reads).
#define AT_SMEM (7168 * 16)

__global__ __launch_bounds__(256)
void attn_mma(const uint4* __restrict__ qph, const uint4* __restrict__ qpl,
              const uint4* __restrict__ kp,  const uint4* __restrict__ vp,
              const float* __restrict__ gates, float* __restrict__ attn) {
    extern __shared__ uint4 sm4[];
    uint32_t smb = smem_u32(sm4);

    int qb = (int)(gridDim.x - 1 - blockIdx.x);   // long CTAs first
    int h = blockIdx.y, b = blockIdx.z;
    int q0 = qb * 128;
    int tid = threadIdx.x, lane = tid & 31, w = tid >> 5;
    int gid = lane >> 2, tig = lane & 3;
    int kvh = h & 3;

    // ---- Q fill: straight u4 copy from frag-packed global ----
    {
        int rp0 = (b * SS + q0) >> 4;
#pragma unroll
        for (int it = 0; it < 4; it++) {
            int idx = tid + it * 256;                 // 0..1023
            int ww = idx >> 7, rem = idx & 127;
            size_t g = ((size_t)(rp0 + ww) * 16 + h) * 128 + rem;
            sm4[idx]        = qph[g];
            sm4[1024 + idx] = qpl[g];
        }
    }

    int i0 = q0 + w * 16 + gid, i1 = i0 + 8;
    bool isl0 = gates[b * SS + i0] <= 0.5f;
    bool isl1 = gates[b * SS + i1] <= 0.5f;

    float m0 = -1e30f, m1 = -1e30f, l0s = 0.f, l1s = 0.f;
    float o[8][4];
#pragma unroll
    for (int nt = 0; nt < 8; nt++)
#pragma unroll
        for (int c = 0; c < 4; c++) o[nt][c] = 0.f;

    int kbEnd = min(2 * qb + 3, SS / 64);

    const uint4* kbase = kp + ((size_t)kvh * MM + b * SS) * 16;
    const uint4* vbase = vp + (size_t)(b * RHH + kvh) * 64 * 512;
    int fj = tid >> 2, fq = (tid & 3) * 4;

    // prefetch kb=0
    {
        const uint4* gk = kbase + (size_t)fj * 16 + fq;
        const uint4* gv = vbase + (size_t)fj * 512 + fq;
        uint32_t dk = smb + (2048 + fj * 20 + fq) * 16;
        uint32_t dv = smb + (4608 + fj * 20 + fq) * 16;
#pragma unroll
        for (int c = 0; c < 4; c++) { cpa16(dk + c * 16, gk + c); cpa16(dv + c * 16, gv + c); }
        CPA_COMMIT();
    }

    for (int kb = 0; kb < kbEnd; kb++) {
        int buf = kb & 1;
        if (kb + 1 < kbEnd) {
            const uint4* gk = kbase + ((size_t)((kb + 1) * 64 + fj)) * 16 + fq;
            const uint4* gv = vbase + (size_t)fj * 512 + (kb + 1) * 16 + fq;
            uint32_t dk = smb + (2048 + (buf ^ 1) * 1280 + fj * 20 + fq) * 16;
            uint32_t dv = smb + (4608 + (buf ^ 1) * 1280 + fj * 20 + fq) * 16;
#pragma unroll
            for (int c = 0; c < 4; c++) { cpa16(dk + c * 16, gk + c); cpa16(dv + c * 16, gv + c); }
            CPA_COMMIT();
            CPA_WAIT(1);
        } else {
            CPA_WAIT(0);
        }
        __syncthreads();

        const uint4* sK = sm4 + 2048 + buf * 1280;
        const uint4* sV = sm4 + 4608 + buf * 1280;

        // ---- QK^T ----
        float s[8][4];
#pragma unroll
        for (int nt = 0; nt < 8; nt++)
#pragma unroll
            for (int c = 0; c < 4; c++) s[nt][c] = 0.f;

#pragma unroll
        for (int ks = 0; ks < 4; ks++) {
            uint4 qh = sm4[w * 128 + gid * 16 + ks * 4 + tig];
            uint4 ql = sm4[1024 + w * 128 + gid * 16 + ks * 4 + tig];
#pragma unroll
            for (int nt = 0; nt < 8; nt++) {
                uint4 kk = sK[(nt * 8 + gid) * 20 + ks * 4 + tig];
                mma_bf16(s[nt], qh.x, qh.y, qh.z, qh.w, kk.x, kk.y);
                mma_bf16(s[nt], qh.x, qh.y, qh.z, qh.w, kk.z, kk.w);
                mma_bf16(s[nt], ql.x, ql.y, ql.z, ql.w, kk.x, kk.y);
            }
        }

        // ---- mask + online softmax ----
        float rm0 = -1e30f, rm1 = -1e30f;
#pragma unroll
        for (int nt = 0; nt < 8; nt++) {
            int jb = kb * 64 + nt * 8 + 2 * tig;
#pragma unroll
            for (int c = 0; c < 2; c++) {
                int j = jb + c;
                bool v0 = isl0 ? (abs(i0 - j) <= 64) : (j <= i0);
                s[nt][c] = v0 ? s[nt][c] : -1e30f;
                rm0 = fmaxf(rm0, s[nt][c]);
                bool v1 = isl1 ? (abs(i1 - j) <= 64) : (j <= i1);
                s[nt][2 + c] = v1 ? s[nt][2 + c] : -1e30f;
                rm1 = fmaxf(rm1, s[nt][2 + c]);
            }
        }
        rm0 = fmaxf(rm0, __shfl_xor_sync(0xffffffffu, rm0, 1));
        rm0 = fmaxf(rm0, __shfl_xor_sync(0xffffffffu, rm0, 2));
        rm1 = fmaxf(rm1, __shfl_xor_sync(0xffffffffu, rm1, 1));
        rm1 = fmaxf(rm1, __shfl_xor_sync(0xffffffffu, rm1, 2));

        float mn0 = fmaxf(m0, rm0), mn1 = fmaxf(m1, rm1);
        float al0f = __expf(fmaxf(m0 - mn0, -80.f));
        float al1f = __expf(fmaxf(m1 - mn1, -80.f));
        float rs0 = 0.f, rs1 = 0.f;
#pragma unroll
        for (int nt = 0; nt < 8; nt++) {
#pragma unroll
            for (int c = 0; c < 2; c++) {
                float p0 = __expf(fmaxf(s[nt][c] - mn0, -80.f));
                s[nt][c] = p0; rs0 += p0;
                float p1 = __expf(fmaxf(s[nt][2 + c] - mn1, -80.f));
                s[nt][2 + c] = p1; rs1 += p1;
            }
        }
        rs0 += __shfl_xor_sync(0xffffffffu, rs0, 1);
        rs0 += __shfl_xor_sync(0xffffffffu, rs0, 2);
        rs1 += __shfl_xor_sync(0xffffffffu, rs1, 1);
        rs1 += __shfl_xor_sync(0xffffffffu, rs1, 2);
        m0 = mn0; m1 = mn1;
        l0s = l0s * al0f + rs0;
        l1s = l1s * al1f + rs1;
#pragma unroll
        for (int nt = 0; nt < 8; nt++) {
            o[nt][0] *= al0f; o[nt][1] *= al0f;
            o[nt][2] *= al1f; o[nt][3] *= al1f;
        }

        // ---- PV (P from registers) ----
#pragma unroll
        for (int ks = 0; ks < 4; ks++) {
            uint32_t ah0, al0, ah1, al1, ah2, al2, ah3, al3;
            bf16_split2(s[2 * ks][0],     s[2 * ks][1],     ah0, al0);
            bf16_split2(s[2 * ks][2],     s[2 * ks][3],     ah1, al1);
            bf16_split2(s[2 * ks + 1][0], s[2 * ks + 1][1], ah2, al2);
            bf16_split2(s[2 * ks + 1][2], s[2 * ks + 1][3], ah3, al3);
#pragma unroll
            for (int nt = 0; nt < 8; nt++) {
                uint4 vv = sV[(nt * 8 + gid) * 20 + ks * 4 + tig];
                mma_bf16(o[nt], ah0, ah1, ah2, ah3, vv.x, vv.y);
                mma_bf16(o[nt], ah0, ah1, ah2, ah3, vv.z, vv.w);
                mma_bf16(o[nt], al0, al1, al2, al3, vv.x, vv.y);
            }
        }
        __syncthreads();  // all warps done with buf before its refill
    }

    // ---- epilogue ----
    float inv0 = (l0s > 0.f) ? 1.f / l0s : 0.f;
    float inv1 = (l1s > 0.f) ? 1.f / l1s : 0.f;
    float* out0 = attn + ((size_t)(b * SS + i0)) * HH + h * HDD + 2 * tig;
    float* out1 = attn + ((size_t)(b * SS + i1)) * HH + h * HDD + 2 * tig;
#pragma unroll
    for (int nt = 0; nt < 8; nt++) {
        *(float2*)(out0 + nt * 8) = make_float2(o[nt][0] * inv0, o[nt][1] * inv0);
        *(float2*)(out1 + nt * 8) = make_float2(o[nt][2] * inv1, o[nt][3] * inv1);
    }
}

// ---------------- gate: LN + dot(wg) + sigmoid(clamp) -----------------------
__global__ void gate_kernel(const float* __restrict__ x,
                            const float* __restrict__ wg,
                            const float* __restrict__ bg,
                            const float* __restrict__ gamma,
                            const float* __restrict__ beta,
                            float* __restrict__ gates) {
    int token = blockIdx.x;
    const float* row = x + (size_t)token * HH;
    __shared__ float red[256];
    int tid = threadIdx.x;

    float xr[4];
#pragma unroll
    for (int i = 0; i < 4; i++) xr[i] = row[tid + i * 256];

    float s = xr[0] + xr[1] + xr[2] + xr[3];
    red[tid] = s; __syncthreads();
    for (int o = 128; o > 0; o >>= 1) { if (tid < o) red[tid] += red[tid + o]; __syncthreads(); }
    float mu = red[0] * (1.0f / HH);
    __syncthreads();

    float v = 0.f;
#pragma unroll
    for (int i = 0; i < 4; i++) { float d = xr[i] - mu; v = fmaf(d, d, v); }
    red[tid] = v; __syncthreads();
    for (int o = 128; o > 0; o >>= 1) { if (tid < o) red[tid] += red[tid + o]; __syncthreads(); }
    float rstd = rsqrtf(red[0] * (1.0f / HH) + 1e-5f);
    __syncthreads();

    float dot = 0.f;
#pragma unroll
    for (int i = 0; i < 4; i++) {
        int hh = tid + i * 256;
        float y = fmaf((xr[i] - mu) * rstd, gamma[hh], beta[hh]);
        dot = fmaf(y, wg[hh], dot);
    }
    red[tid] = dot; __syncthreads();
    for (int o = 128; o > 0; o >>= 1) { if (tid < o) red[tid] += red[tid + o]; __syncthreads(); }
    if (tid == 0) {
        float z = red[0] + bg[0];
        z = fminf(10.f, fmaxf(-10.f, z));
        gates[token] = 1.f / (1.f + expf(-z));
    }
}

// ---------------- gate regularization loss ------------------------------------
__global__ void regloss_kernel(const float* __restrict__ gates, float* __restrict__ out,
                               int writeIdx) {
    __shared__ float red[256];
    int tid = threadIdx.x;
    float acc = 0.f;
    for (int t = tid; t < MM; t += 256) {
        float g = gates[t];
        float gs = fminf(fmaxf(g, 1e-5f), 1.f - 1e-5f);
        float binary = g * (1.f - g);
        float ent = g * logf(gs) + (1.f - g) * logf(1.f - gs);
        acc += 0.1f * binary - 0.01f * ent + 0.1f * g;
    }
    red[tid] = acc; __syncthreads();
    for (int o = 128; o > 0; o >>= 1) { if (tid < o) red[tid] += red[tid + o]; __syncthreads(); }
    if (tid == 0) out[writeIdx] = red[0] * (1.0f / MM);
}

// ---------------- launch ------------------------------------------------------
extern "C" void kernel_launch(void* const* d_in, const int* in_sizes, int n_in,
                              void* d_out, int out_size) {
    const float* x     = (const float*)d_in[0];
    const float* Wq    = (const float*)d_in[1];
    const float* Wk    = (const float*)d_in[2];
    const float* Wv    = (const float*)d_in[3];
    const float* Wo    = (const float*)d_in[4];
    const float* Wg    = (const float*)d_in[5];
    const float* bg    = (const float*)d_in[6];
    const float* gamma = (const float*)d_in[7];
    const float* beta  = (const float*)d_in[8];
    float* out = (float*)d_out;

    float *pGates, *pV, *pAttn;
    uint32_t *pQh, *pQl, *pKp;
    uint4 *pVp;
    cudaGetSymbolAddress((void**)&pGates, g_gates);
    cudaGetSymbolAddress((void**)&pQh,    g_qph);
    cudaGetSymbolAddress((void**)&pQl,    g_qpl);
    cudaGetSymbolAddress((void**)&pKp,    g_kp);
    cudaGetSymbolAddress((void**)&pV,     g_v);
    cudaGetSymbolAddress((void**)&pVp,    g_vp);
    cudaGetSymbolAddress((void**)&pAttn,  g_attn);

    cudaFuncSetAttribute(gemm_mma, cudaFuncAttributeMaxDynamicSharedMemorySize, GM_SMEM);
    cudaFuncSetAttribute(gemm_mma_kv, cudaFuncAttributeMaxDynamicSharedMemorySize, GM_SMEM);
    cudaFuncSetAttribute(attn_mma, cudaFuncAttributeMaxDynamicSharedMemorySize, AT_SMEM);

    gate_kernel<<<MM, 256>>>(x, Wg, bg, gamma, beta, pGates);

    gemm_mma<<<dim3(HH / 128, MM / 128), 256, GM_SMEM>>>(x, Wq, nullptr, pQh, pQl, HH, HH, 1);
    gemm_mma_kv<<<dim3((RHH * HDD) / 128, MM / 128, 2), 256, GM_SMEM>>>(
        x, Wk, Wv, pKp, pV, RHH * HDD, HH);
    v_pack<<<dim3(SS / 64, RHH, BB), 128>>>(pV, pVp);

    attn_mma<<<dim3(SS / 128, NHD, BB), 256, AT_SMEM>>>(
        (const uint4*)pQh, (const uint4*)pQl, (const uint4*)pKp, pVp, pGates, pAttn);

    gemm_mma<<<dim3(HH / 128, MM / 128), 256, GM_SMEM>>>(pAttn, Wo, out, nullptr, nullptr, HH, HH, 0);

    if (out_size > MM * HH)
        regloss_kernel<<<1, 256>>>(pGates, out, MM * HH);
}

// round 8
// speedup vs baseline: 3.5272x; 1.1412x over previous
#include <cuda_runtime.h>
#include <cuda_bf16.h>
#include <math.h>
#include <stdint.h>

// Problem constants
#define BB  2
#define SS  2048
#define HH  1024
#define NHD 16      // num heads
#define HDD 64      // head dim
#define RHH 4       // kv heads
#define MM  (BB*SS) // 4096 token rows

// ---------------- scratch (static device memory; no allocs allowed) ----------
__device__ float    g_gates[MM];
__device__ int      g_order[MM];                      // compacted row order per batch
__device__ uint32_t g_qph[(size_t)MM * 512];          // Q row-packed bf16 hi: [tok][h][32w]
__device__ uint32_t g_qpl[(size_t)MM * 512];          // Q row-packed bf16 lo
__device__ uint32_t g_kp [(size_t)RHH * MM * 64];     // K frag-packed (hi+lo interleaved u4)
__device__ float    g_v  [(size_t)MM * (RHH*HDD)];    // V fp32 (gemm out)
__device__ uint4    g_vp [(size_t)BB * RHH * HDD * 512]; // V transposed frag-packed
__device__ float    g_attn[(size_t)MM * HH];

// ---------------- bf16 helpers ----------------------------------------------
__device__ __forceinline__ uint32_t pack_bf16(float lowElem, float highElem) {
    uint32_t r;
    asm("cvt.rn.bf16x2.f32 %0, %1, %2;" : "=r"(r) : "f"(highElem), "f"(lowElem));
    return r;
}
__device__ __forceinline__ float bf16_round(float x) {
    return __bfloat162float(__float2bfloat16(x));
}
__device__ __forceinline__ void bf16_split2(float a, float b, uint32_t& hi, uint32_t& lo) {
    hi = pack_bf16(a, b);
    lo = pack_bf16(a - bf16_round(a), b - bf16_round(b));
}
__device__ __forceinline__ void mma_bf16(float* c, uint32_t a0, uint32_t a1, uint32_t a2,
                                         uint32_t a3, uint32_t b0, uint32_t b1) {
    asm volatile(
        "mma.sync.aligned.m16n8k16.row.col.f32.bf16.bf16.f32 "
        "{%0,%1,%2,%3}, {%4,%5,%6,%7}, {%8,%9}, {%0,%1,%2,%3};"
        : "+f"(c[0]), "+f"(c[1]), "+f"(c[2]), "+f"(c[3])
        : "r"(a0), "r"(a1), "r"(a2), "r"(a3), "r"(b0), "r"(b1));
}
__device__ __forceinline__ uint32_t smem_u32(const void* p) {
    uint32_t a;
    asm("{ .reg .u64 t; cvta.to.shared.u64 t, %1; cvt.u32.u64 %0, t; }" : "=r"(a) : "l"(p));
    return a;
}
__device__ __forceinline__ void cpa16(uint32_t dst, const void* src) {
    asm volatile("cp.async.ca.shared.global [%0], [%1], 16;" :: "r"(dst), "l"(src));
}
#define CPA_COMMIT() asm volatile("cp.async.commit_group;" ::: "memory")
#define CPA_WAIT(n)  asm volatile("cp.async.wait_group %0;" :: "n"(n) : "memory")

// ==================== tensor-core bf16x3 GEMM ================================
// C[M,N] = A[M,K] @ B[N,K]^T. CTA tile 128x128, BK=32, dbl-buffered SMEM.
// 8 warps 4(M)x2(N); warp tile 32x64.
// mode 0: fp32 C.  mode 1: Q row-packed bf16 hi/lo (scale 1/8) -> outh/outl.
// mode 2: K frag-packed interleaved u4 -> outh.
#define PWG 20
#define STGW (4 * 128 * PWG)
#define GM_SMEM (2 * STGW * 4)

__device__ __forceinline__ void gemm_body(const float* __restrict__ A,
                                          const float* __restrict__ B,
                                          float* __restrict__ C,
                                          uint32_t* __restrict__ outh,
                                          uint32_t* __restrict__ outl,
                                          int N, int K, int mode,
                                          int rowBase, int colBase, uint32_t* sm) {
    int tid = threadIdx.x, lane = tid & 31, wid = tid >> 5;
    int gid = lane >> 2, tig = lane & 3;
    int wM = wid >> 1, wN = wid & 1;

    const float* Aptr = A + (size_t)(rowBase + (tid >> 1)) * K + (tid & 1) * 16;
    const float* Bptr = B + (size_t)(colBase + (tid >> 1)) * K + (tid & 1) * 16;
    int srow = tid >> 1, sw0 = (tid & 1) * 8;

    float acc[2][8][4];
#pragma unroll
    for (int mt = 0; mt < 2; mt++)
#pragma unroll
        for (int nt = 0; nt < 8; nt++)
#pragma unroll
            for (int c = 0; c < 4; c++) acc[mt][nt][c] = 0.f;

    float4 ra[4], rb[4];
#pragma unroll
    for (int i = 0; i < 4; i++) {
        ra[i] = *(const float4*)(Aptr + i * 4);
        rb[i] = *(const float4*)(Bptr + i * 4);
    }

    const int NST = K / 32;
    for (int s = 0; s < NST; s++) {
        uint32_t* base = sm + (s & 1) * STGW;
        uint32_t* sAh = base;
        uint32_t* sAl = base + 128 * PWG;
        uint32_t* sBh = base + 2 * 128 * PWG;
        uint32_t* sBl = base + 3 * 128 * PWG;

#pragma unroll
        for (int i = 0; i < 4; i++) {
            uint32_t h0, l0, h1, l1;
            bf16_split2(ra[i].x, ra[i].y, h0, l0);
            bf16_split2(ra[i].z, ra[i].w, h1, l1);
            sAh[srow * PWG + sw0 + i * 2]     = h0;
            sAh[srow * PWG + sw0 + i * 2 + 1] = h1;
            sAl[srow * PWG + sw0 + i * 2]     = l0;
            sAl[srow * PWG + sw0 + i * 2 + 1] = l1;
            bf16_split2(rb[i].x, rb[i].y, h0, l0);
            bf16_split2(rb[i].z, rb[i].w, h1, l1);
            sBh[srow * PWG + sw0 + i * 2]     = h0;
            sBh[srow * PWG + sw0 + i * 2 + 1] = h1;
            sBl[srow * PWG + sw0 + i * 2]     = l0;
            sBl[srow * PWG + sw0 + i * 2 + 1] = l1;
        }
        __syncthreads();

        if (s + 1 < NST) {
            Aptr += 32; Bptr += 32;
#pragma unroll
            for (int i = 0; i < 4; i++) {
                ra[i] = *(const float4*)(Aptr + i * 4);
                rb[i] = *(const float4*)(Bptr + i * 4);
            }
        }

#pragma unroll
        for (int ks = 0; ks < 2; ks++) {
            uint32_t ah[2][4], al[2][4];
#pragma unroll
            for (int mt = 0; mt < 2; mt++) {
                int r0 = (wM * 32 + mt * 16 + gid) * PWG + ks * 8 + tig;
                ah[mt][0] = sAh[r0];
                ah[mt][1] = sAh[r0 + 8 * PWG];
                ah[mt][2] = sAh[r0 + 4];
                ah[mt][3] = sAh[r0 + 8 * PWG + 4];
                al[mt][0] = sAl[r0];
                al[mt][1] = sAl[r0 + 8 * PWG];
                al[mt][2] = sAl[r0 + 4];
                al[mt][3] = sAl[r0 + 8 * PWG + 4];
            }
#pragma unroll
            for (int nt = 0; nt < 8; nt++) {
                int n0 = (wN * 64 + nt * 8 + gid) * PWG + ks * 8 + tig;
                uint32_t bh0 = sBh[n0], bh1 = sBh[n0 + 4];
                uint32_t bl0 = sBl[n0], bl1 = sBl[n0 + 4];
#pragma unroll
                for (int mt = 0; mt < 2; mt++) {
                    mma_bf16(acc[mt][nt], ah[mt][0], ah[mt][1], ah[mt][2], ah[mt][3], bh0, bh1);
                    mma_bf16(acc[mt][nt], ah[mt][0], ah[mt][1], ah[mt][2], ah[mt][3], bl0, bl1);
                    mma_bf16(acc[mt][nt], al[mt][0], al[mt][1], al[mt][2], al[mt][3], bh0, bh1);
                }
            }
        }
        __syncthreads();
    }

    // ---------------- epilogue ----------------
    if (mode == 0) {
#pragma unroll
        for (int mt = 0; mt < 2; mt++) {
            int r0 = rowBase + wM * 32 + mt * 16 + gid;
#pragma unroll
            for (int nt = 0; nt < 8; nt++) {
                int c0 = colBase + wN * 64 + nt * 8 + 2 * tig;
                *(float2*)(C + (size_t)r0 * N + c0) = make_float2(acc[mt][nt][0], acc[mt][nt][1]);
                *(float2*)(C + (size_t)(r0 + 8) * N + c0) = make_float2(acc[mt][nt][2], acc[mt][nt][3]);
            }
        }
    } else if (mode == 1) {   // Q row-packed, scaled 1/8: [tok][h][32 words]
#pragma unroll
        for (int mt = 0; mt < 2; mt++) {
            int r0 = rowBase + wM * 32 + mt * 16 + gid;
#pragma unroll
            for (int nt = 0; nt < 8; nt++) {
                int c0 = colBase + wN * 64 + nt * 8 + 2 * tig;
                int hh = c0 >> 6, w32 = (c0 & 63) >> 1;
                uint32_t h0, l0, h1, l1;
                bf16_split2(acc[mt][nt][0] * 0.125f, acc[mt][nt][1] * 0.125f, h0, l0);
                bf16_split2(acc[mt][nt][2] * 0.125f, acc[mt][nt][3] * 0.125f, h1, l1);
                size_t i0 = ((size_t)r0 * 16 + hh) * 32 + w32;
                size_t i1 = ((size_t)(r0 + 8) * 16 + hh) * 32 + w32;
                outh[i0] = h0; outl[i0] = l0;
                outh[i1] = h1; outl[i1] = l1;
            }
        }
    } else {                  // K frag-packed interleaved (h_t, h_t4, l_t, l_t4)
#pragma unroll
        for (int mt = 0; mt < 2; mt++) {
            int r0 = rowBase + wM * 32 + mt * 16 + gid;
#pragma unroll
            for (int nt = 0; nt < 8; nt++) {
                int c0 = colBase + wN * 64 + nt * 8 + 2 * tig;
                int kvh = c0 >> 6, wl = (c0 & 63) >> 1;
                int ks = wl >> 3, tigg = wl & 7;
                int tA = tigg & 3, comp = (tigg & 4) ? 1 : 0;
                size_t wi0 = (((size_t)kvh * MM + r0) * 16 + ks * 4 + tA) * 4;
                size_t wi1 = wi0 + 8 * 16 * 4;
                uint32_t h0, l0, h1, l1;
                bf16_split2(acc[mt][nt][0], acc[mt][nt][1], h0, l0);
                bf16_split2(acc[mt][nt][2], acc[mt][nt][3], h1, l1);
                outh[wi0 + comp] = h0; outh[wi0 + comp + 2] = l0;
                outh[wi1 + comp] = h1; outh[wi1 + comp + 2] = l1;
            }
        }
    }
}

__global__ __launch_bounds__(256, 1)
void gemm_mma(const float* __restrict__ A, const float* __restrict__ B,
              float* __restrict__ C, uint32_t* __restrict__ outh,
              uint32_t* __restrict__ outl, int N, int K, int mode) {
    extern __shared__ uint32_t smg[];
    gemm_body(A, B, C, outh, outl, N, K, mode, blockIdx.y * 128, blockIdx.x * 128, smg);
}

// fused K+V projection: z=0 -> K frag-packed, z=1 -> V fp32
__global__ __launch_bounds__(256, 1)
void gemm_mma_kv(const float* __restrict__ A,
                 const float* __restrict__ Wk, const float* __restrict__ Wv,
                 uint32_t* __restrict__ kp, float* __restrict__ Vo, int N, int K) {
    extern __shared__ uint32_t smg[];
    if (blockIdx.z)
        gemm_body(A, Wv, Vo, nullptr, nullptr, N, K, 0, blockIdx.y * 128, blockIdx.x * 128, smg);
    else
        gemm_body(A, Wk, nullptr, kp, nullptr, N, K, 2, blockIdx.y * 128, blockIdx.x * 128, smg);
}

// ---------------- V transpose + split + frag-pack ----------------------------
__global__ __launch_bounds__(128)
void v_pack(const float* __restrict__ v, uint4* __restrict__ vp) {
    __shared__ float sm[64 * 68];
    int kb = blockIdx.x, kvh = blockIdx.y, b = blockIdx.z;
    int tid = threadIdx.x;
    for (int e = tid; e < 64 * 16; e += 128) {
        int row = e >> 4, c4 = e & 15;
        float4 t4 = *(const float4*)(v + ((size_t)(b * SS + kb * 64 + row)) * (RHH * HDD)
                                       + kvh * HDD + c4 * 4);
        sm[row * 68 + c4 * 4 + 0] = t4.x;
        sm[row * 68 + c4 * 4 + 1] = t4.y;
        sm[row * 68 + c4 * 4 + 2] = t4.z;
        sm[row * 68 + c4 * 4 + 3] = t4.w;
    }
    __syncthreads();
    int d = tid & 63, kshalf = tid >> 6;
    size_t base = ((size_t)(b * RHH + kvh) * 64 + d) * 512 + kb * 16;
#pragma unroll
    for (int kk = 0; kk < 2; kk++) {
        int ks = kshalf * 2 + kk;
#pragma unroll
        for (int tg = 0; tg < 4; tg++) {
            int j0 = (ks * 8 + tg) * 2, j1 = (ks * 8 + tg + 4) * 2;
            float a  = sm[j0 * 68 + d],       b2 = sm[(j0 + 1) * 68 + d];
            float c  = sm[j1 * 68 + d],       d2 = sm[(j1 + 1) * 68 + d];
            uint32_t hx, lx, hy, ly;
            bf16_split2(a, b2, hx, lx);
            bf16_split2(c, d2, hy, ly);
            vp[base + ks * 4 + tg] = make_uint4(hx, hy, lx, ly);
        }
    }
}

// ---------------- build compacted row order: [causal asc | local asc] --------
__global__ __launch_bounds__(256)
void build_order(const float* __restrict__ gates, int* __restrict__ order) {
    int b = blockIdx.x, tid = threadIdx.x;
    __shared__ int cnt[256];
    bool loc[8];
    int c = 0;
#pragma unroll
    for (int i = 0; i < 8; i++) {
        loc[i] = gates[b * SS + tid * 8 + i] <= 0.5f;
        if (!loc[i]) c++;
    }
    cnt[tid] = c;
    __syncthreads();
    for (int off = 1; off < 256; off <<= 1) {
        int add = (tid >= off) ? cnt[tid - off] : 0;
        __syncthreads();
        cnt[tid] += add;
        __syncthreads();
    }
    int nC = cnt[255];
    int cb = cnt[tid] - c;                 // causal slot base (exclusive prefix)
    int lb = nC + (tid * 8 - cb);          // local slot base
#pragma unroll
    for (int i = 0; i < 8; i++) {
        if (loc[i]) order[b * SS + lb++] = tid * 8 + i;
        else        order[b * SS + cb++] = tid * 8 + i;
    }
}

// ==================== mma flash attention (compacted rows) ===================
// CTA: 256 thr = 8 warps, 128 compacted q-rows. K dbl-buffered, V single.
// SMEM (uint4): Q hi [0,1024) lo [1024,2048); K buf{0,1} @2048+buf*1280; V @4608.
#define AT_SMEM (5888 * 16)

__global__ __launch_bounds__(256, 2)
void attn_mma(const uint32_t* __restrict__ qph, const uint32_t* __restrict__ qpl,
              const uint4* __restrict__ kp,  const uint4* __restrict__ vp,
              const float* __restrict__ gates, const int* __restrict__ order,
              float* __restrict__ attn) {
    extern __shared__ uint4 sm4[];
    __shared__ int srows[128];
    __shared__ int sminlo, smaxhi;
    uint32_t smb = smem_u32(sm4);
    uint32_t* sQw = (uint32_t*)sm4;

    int t = blockIdx.x, h = blockIdx.y, b = blockIdx.z;
    int tid = threadIdx.x, lane = tid & 31, w = tid >> 5;
    int gid = lane >> 2, tig = lane & 3;
    int kvh = h & 3;

    if (tid == 0) { sminlo = SS; smaxhi = 0; }
    if (tid < 128) srows[tid] = order[b * SS + t * 128 + tid];
    __syncthreads();
    if (tid < 128) {
        int myi = srows[tid];
        bool isl = gates[b * SS + myi] <= 0.5f;
        int lo = isl ? max(0, myi - 64) : 0;
        int hi = isl ? min(SS - 1, myi + 64) : myi;
        atomicMin(&sminlo, lo);
        atomicMax(&smaxhi, hi);
    }

    // ---- Q gather: row-major packed -> frag layout (thread = row*2+half) ----
    {
        int r = tid >> 1, half = tid & 1;
        int ri = srows[r];   // srows written pre-sync by same... (guarded below)
        // NOTE: srows[r] read is safe: the __syncthreads above ordered it.
        const uint32_t* src = (half ? qpl : qph) + ((size_t)(b * SS + ri) * 16 + h) * 32;
        uint32_t* dst = sQw + half * 4096;
        int wd = r >> 4, g2 = r & 15;
        int gidq = g2 & 7, hiRow = g2 >> 3;
#pragma unroll
        for (int w32 = 0; w32 < 32; w32++) {
            int ks = w32 >> 3, rem = w32 & 7;
            int tg2 = rem & 3, comp = ((rem >> 2) << 1) | hiRow;
            dst[(((wd * 8 + gidq) * 4 + ks) * 4 + tg2) * 4 + comp] = src[w32];
        }
    }
    __syncthreads();

    int kbStart = sminlo >> 6;
    int kbEnd = (smaxhi >> 6) + 1;

    int i0 = srows[w * 16 + gid], i1 = srows[w * 16 + gid + 8];
    bool isl0 = gates[b * SS + i0] <= 0.5f;
    bool isl1 = gates[b * SS + i1] <= 0.5f;

    float m0 = -1e30f, m1 = -1e30f, l0s = 0.f, l1s = 0.f;
    float o[8][4];
#pragma unroll
    for (int nt = 0; nt < 8; nt++)
#pragma unroll
        for (int c = 0; c < 4; c++) o[nt][c] = 0.f;

    const uint4* kbase = kp + ((size_t)kvh * MM + b * SS) * 16;
    const uint4* vbase = vp + (size_t)(b * RHH + kvh) * 64 * 512;
    int fj = tid >> 2, fq = (tid & 3) * 4;

    // prefetch K[kbStart] + V[kbStart]
    {
        const uint4* gk = kbase + ((size_t)(kbStart * 64 + fj)) * 16 + fq;
        const uint4* gv = vbase + (size_t)fj * 512 + kbStart * 16 + fq;
        uint32_t dk = smb + (2048 + fj * 20 + fq) * 16;
        uint32_t dv = smb + (4608 + fj * 20 + fq) * 16;
#pragma unroll
        for (int c = 0; c < 4; c++) { cpa16(dk + c * 16, gk + c); cpa16(dv + c * 16, gv + c); }
        CPA_COMMIT();
    }

    for (int kb = kbStart; kb < kbEnd; kb++) {
        int buf = (kb - kbStart) & 1;
        CPA_WAIT(0);
        __syncthreads();

        // prefetch next K into other buffer (overlaps QK+softmax+PV)
        if (kb + 1 < kbEnd) {
            const uint4* gk = kbase + ((size_t)((kb + 1) * 64 + fj)) * 16 + fq;
            uint32_t dk = smb + (2048 + (buf ^ 1) * 1280 + fj * 20 + fq) * 16;
#pragma unroll
            for (int c = 0; c < 4; c++) cpa16(dk + c * 16, gk + c);
            CPA_COMMIT();
        }

        const uint4* sK = sm4 + 2048 + buf * 1280;
        const uint4* sV = sm4 + 4608;

        // ---- QK^T ----
        float s[8][4];
#pragma unroll
        for (int nt = 0; nt < 8; nt++)
#pragma unroll
            for (int c = 0; c < 4; c++) s[nt][c] = 0.f;

#pragma unroll
        for (int ks = 0; ks < 4; ks++) {
            uint4 qh = sm4[w * 128 + gid * 16 + ks * 4 + tig];
            uint4 ql = sm4[1024 + w * 128 + gid * 16 + ks * 4 + tig];
#pragma unroll
            for (int nt = 0; nt < 8; nt++) {
                uint4 kk = sK[(nt * 8 + gid) * 20 + ks * 4 + tig];
                mma_bf16(s[nt], qh.x, qh.y, qh.z, qh.w, kk.x, kk.y);
                mma_bf16(s[nt], qh.x, qh.y, qh.z, qh.w, kk.z, kk.w);
                mma_bf16(s[nt], ql.x, ql.y, ql.z, ql.w, kk.x, kk.y);
            }
        }

        // ---- mask + online softmax ----
        float rm0 = -1e30f, rm1 = -1e30f;
#pragma unroll
        for (int nt = 0; nt < 8; nt++) {
            int jb = kb * 64 + nt * 8 + 2 * tig;
#pragma unroll
            for (int c = 0; c < 2; c++) {
                int j = jb + c;
                bool v0 = isl0 ? (abs(i0 - j) <= 64) : (j <= i0);
                s[nt][c] = v0 ? s[nt][c] : -1e30f;
                rm0 = fmaxf(rm0, s[nt][c]);
                bool v1 = isl1 ? (abs(i1 - j) <= 64) : (j <= i1);
                s[nt][2 + c] = v1 ? s[nt][2 + c] : -1e30f;
                rm1 = fmaxf(rm1, s[nt][2 + c]);
            }
        }
        rm0 = fmaxf(rm0, __shfl_xor_sync(0xffffffffu, rm0, 1));
        rm0 = fmaxf(rm0, __shfl_xor_sync(0xffffffffu, rm0, 2));
        rm1 = fmaxf(rm1, __shfl_xor_sync(0xffffffffu, rm1, 1));
        rm1 = fmaxf(rm1, __shfl_xor_sync(0xffffffffu, rm1, 2));

        float mn0 = fmaxf(m0, rm0), mn1 = fmaxf(m1, rm1);
        float al0f = __expf(fmaxf(m0 - mn0, -80.f));
        float al1f = __expf(fmaxf(m1 - mn1, -80.f));
        float rs0 = 0.f, rs1 = 0.f;
#pragma unroll
        for (int nt = 0; nt < 8; nt++) {
#pragma unroll
            for (int c = 0; c < 2; c++) {
                float p0 = __expf(fmaxf(s[nt][c] - mn0, -80.f));
                s[nt][c] = p0; rs0 += p0;
                float p1 = __expf(fmaxf(s[nt][2 + c] - mn1, -80.f));
                s[nt][2 + c] = p1; rs1 += p1;
            }
        }
        rs0 += __shfl_xor_sync(0xffffffffu, rs0, 1);
        rs0 += __shfl_xor_sync(0xffffffffu, rs0, 2);
        rs1 += __shfl_xor_sync(0xffffffffu, rs1, 1);
        rs1 += __shfl_xor_sync(0xffffffffu, rs1, 2);
        m0 = mn0; m1 = mn1;
        l0s = l0s * al0f + rs0;
        l1s = l1s * al1f + rs1;
#pragma unroll
        for (int nt = 0; nt < 8; nt++) {
            o[nt][0] *= al0f; o[nt][1] *= al0f;
            o[nt][2] *= al1f; o[nt][3] *= al1f;
        }

        // ---- PV (P from registers, single V buffer) ----
#pragma unroll
        for (int ks = 0; ks < 4; ks++) {
            uint32_t ah0, al0, ah1, al1, ah2, al2, ah3, al3;
            bf16_split2(s[2 * ks][0],     s[2 * ks][1],     ah0, al0);
            bf16_split2(s[2 * ks][2],     s[2 * ks][3],     ah1, al1);
            bf16_split2(s[2 * ks + 1][0], s[2 * ks + 1][1], ah2, al2);
            bf16_split2(s[2 * ks + 1][2], s[2 * ks + 1][3], ah3, al3);
#pragma unroll
            for (int nt = 0; nt < 8; nt++) {
                uint4 vv = sV[(nt * 8 + gid) * 20 + ks * 4 + tig];
                mma_bf16(o[nt], ah0, ah1, ah2, ah3, vv.x, vv.y);
                mma_bf16(o[nt], ah0, ah1, ah2, ah3, vv.z, vv.w);
                mma_bf16(o[nt], al0, al1, al2, al3, vv.x, vv.y);
            }
        }
        __syncthreads();   // all warps done with V before refill

        if (kb + 1 < kbEnd) {
            const uint4* gv = vbase + (size_t)fj * 512 + (kb + 1) * 16 + fq;
            uint32_t dv = smb + (4608 + fj * 20 + fq) * 16;
#pragma unroll
            for (int c = 0; c < 4; c++) cpa16(dv + c * 16, gv + c);
            CPA_COMMIT();
        }
    }

    // ---- epilogue (scatter to true rows) ----
    float inv0 = (l0s > 0.f) ? 1.f / l0s : 0.f;
    float inv1 = (l1s > 0.f) ? 1.f / l1s : 0.f;
    float* out0 = attn + ((size_t)(b * SS + i0)) * HH + h * HDD + 2 * tig;
    float* out1 = attn + ((size_t)(b * SS + i1)) * HH + h * HDD + 2 * tig;
#pragma unroll
    for (int nt = 0; nt < 8; nt++) {
        *(float2*)(out0 + nt * 8) = make_float2(o[nt][0] * inv0, o[nt][1] * inv0);
        *(float2*)(out1 + nt * 8) = make_float2(o[nt][2] * inv1, o[nt][3] * inv1);
    }
}

// ---------------- gate: LN + dot(wg) + sigmoid(clamp) -----------------------
__global__ void gate_kernel(const float* __restrict__ x,
                            const float* __restrict__ wg,
                            const float* __restrict__ bg,
                            const float* __restrict__ gamma,
                            const float* __restrict__ beta,
                            float* __restrict__ gates) {
    int token = blockIdx.x;
    const float* row = x + (size_t)token * HH;
    __shared__ float red[256];
    int tid = threadIdx.x;

    float xr[4];
#pragma unroll
    for (int i = 0; i < 4; i++) xr[i] = row[tid + i * 256];

    float s = xr[0] + xr[1] + xr[2] + xr[3];
    red[tid] = s; __syncthreads();
    for (int o = 128; o > 0; o >>= 1) { if (tid < o) red[tid] += red[tid + o]; __syncthreads(); }
    float mu = red[0] * (1.0f / HH);
    __syncthreads();

    float v = 0.f;
#pragma unroll
    for (int i = 0; i < 4; i++) { float d = xr[i] - mu; v = fmaf(d, d, v); }
    red[tid] = v; __syncthreads();
    for (int o = 128; o > 0; o >>= 1) { if (tid < o) red[tid] += red[tid + o]; __syncthreads(); }
    float rstd = rsqrtf(red[0] * (1.0f / HH) + 1e-5f);
    __syncthreads();

    float dot = 0.f;
#pragma unroll
    for (int i = 0; i < 4; i++) {
        int hh = tid + i * 256;
        float y = fmaf((xr[i] - mu) * rstd, gamma[hh], beta[hh]);
        dot = fmaf(y, wg[hh], dot);
    }
    red[tid] = dot; __syncthreads();
    for (int o = 128; o > 0; o >>= 1) { if (tid < o) red[tid] += red[tid + o]; __syncthreads(); }
    if (tid == 0) {
        float z = red[0] + bg[0];
        z = fminf(10.f, fmaxf(-10.f, z));
        gates[token] = 1.f / (1.f + expf(-z));
    }
}

// ---------------- gate regularization loss ------------------------------------
__global__ void regloss_kernel(const float* __restrict__ gates, float* __restrict__ out,
                               int writeIdx) {
    __shared__ float red[256];
    int tid = threadIdx.x;
    float acc = 0.f;
    for (int t = tid; t < MM; t += 256) {
        float g = gates[t];
        float gs = fminf(fmaxf(g, 1e-5f), 1.f - 1e-5f);
        float binary = g * (1.f - g);
        float ent = g * logf(gs) + (1.f - g) * logf(1.f - gs);
        acc += 0.1f * binary - 0.01f * ent + 0.1f * g;
    }
    red[tid] = acc; __syncthreads();
    for (int o = 128; o > 0; o >>= 1) { if (tid < o) red[tid] += red[tid + o]; __syncthreads(); }
    if (tid == 0) out[writeIdx] = red[0] * (1.0f / MM);
}

// ---------------- launch ------------------------------------------------------
extern "C" void kernel_launch(void* const* d_in, const int* in_sizes, int n_in,
                              void* d_out, int out_size) {
    const float* x     = (const float*)d_in[0];
    const float* Wq    = (const float*)d_in[1];
    const float* Wk    = (const float*)d_in[2];
    const float* Wv    = (const float*)d_in[3];
    const float* Wo    = (const float*)d_in[4];
    const float* Wg    = (const float*)d_in[5];
    const float* bg    = (const float*)d_in[6];
    const float* gamma = (const float*)d_in[7];
    const float* beta  = (const float*)d_in[8];
    float* out = (float*)d_out;

    float *pGates, *pV, *pAttn;
    uint32_t *pQh, *pQl, *pKp;
    uint4 *pVp;
    int *pOrder;
    cudaGetSymbolAddress((void**)&pGates, g_gates);
    cudaGetSymbolAddress((void**)&pOrder, g_order);
    cudaGetSymbolAddress((void**)&pQh,    g_qph);
    cudaGetSymbolAddress((void**)&pQl,    g_qpl);
    cudaGetSymbolAddress((void**)&pKp,    g_kp);
    cudaGetSymbolAddress((void**)&pV,     g_v);
    cudaGetSymbolAddress((void**)&pVp,    g_vp);
    cudaGetSymbolAddress((void**)&pAttn,  g_attn);

    cudaFuncSetAttribute(gemm_mma, cudaFuncAttributeMaxDynamicSharedMemorySize, GM_SMEM);
    cudaFuncSetAttribute(gemm_mma_kv, cudaFuncAttributeMaxDynamicSharedMemorySize, GM_SMEM);
    cudaFuncSetAttribute(attn_mma, cudaFuncAttributeMaxDynamicSharedMemorySize, AT_SMEM);

    gate_kernel<<<MM, 256>>>(x, Wg, bg, gamma, beta, pGates);
    build_order<<<BB, 256>>>(pGates, pOrder);

    gemm_mma<<<dim3(HH / 128, MM / 128), 256, GM_SMEM>>>(x, Wq, nullptr, pQh, pQl, HH, HH, 1);
    gemm_mma_kv<<<dim3((RHH * HDD) / 128, MM / 128, 2), 256, GM_SMEM>>>(
        x, Wk, Wv, pKp, pV, RHH * HDD, HH);
    v_pack<<<dim3(SS / 64, RHH, BB), 128>>>(pV, pVp);

    attn_mma<<<dim3(SS / 128, NHD, BB), 256, AT_SMEM>>>(
        pQh, pQl, (const uint4*)pKp, pVp, pGates, pOrder, pAttn);

    gemm_mma<<<dim3(HH / 128, MM / 128), 256, GM_SMEM>>>(pAttn, Wo, out, nullptr, nullptr, HH, HH, 0);

    if (out_size > MM * HH)
        regloss_kernel<<<1, 256>>>(pGates, out, MM * HH);
}

// round 11
// speedup vs baseline: 3.6546x; 1.0361x over previous
#include <cuda_runtime.h>
#include <cuda_bf16.h>
#include <math.h>
#include <stdint.h>

// Problem constants
#define BB  2
#define SS  2048
#define HH  1024
#define NHD 16      // num heads
#define HDD 64      // head dim
#define RHH 4       // kv heads
#define MM  (BB*SS) // 4096 token rows
#define KW  (HH/2)  // 512 words per row (bf16x2)

// ---------------- scratch (static device memory; no allocs allowed) ----------
__device__ float    g_gates[MM];
__device__ int      g_order[MM];
__device__ uint32_t g_xh [(size_t)MM * KW];           // x split hi (bf16x2 words)
__device__ uint32_t g_xl [(size_t)MM * KW];
__device__ uint32_t g_wqh[(size_t)HH * KW];           // Wq split
__device__ uint32_t g_wql[(size_t)HH * KW];
__device__ uint32_t g_wkh[(size_t)(RHH*HDD) * KW];    // Wk split
__device__ uint32_t g_wkl[(size_t)(RHH*HDD) * KW];
__device__ uint32_t g_wvh[(size_t)(RHH*HDD) * KW];    // Wv split
__device__ uint32_t g_wvl[(size_t)(RHH*HDD) * KW];
__device__ uint32_t g_woh[(size_t)HH * KW];           // Wo split
__device__ uint32_t g_wol[(size_t)HH * KW];
__device__ uint32_t g_qph[(size_t)MM * 512];          // Q row-packed bf16 hi [tok][h][32w]
__device__ uint32_t g_qpl[(size_t)MM * 512];
__device__ uint32_t g_kp [(size_t)RHH * MM * 64];     // K frag-packed (hi+lo interleaved u4)
__device__ float    g_v  [(size_t)MM * (RHH*HDD)];    // V fp32 (gemm out)
__device__ uint4    g_vp [(size_t)BB * RHH * HDD * 512]; // V transposed frag-packed
__device__ uint32_t g_oh [(size_t)MM * 512];          // attn out split hi
__device__ uint32_t g_ol [(size_t)MM * 512];

// ---------------- bf16 helpers ----------------------------------------------
__device__ __forceinline__ uint32_t pack_bf16(float lowElem, float highElem) {
    uint32_t r;
    asm("cvt.rn.bf16x2.f32 %0, %1, %2;" : "=r"(r) : "f"(highElem), "f"(lowElem));
    return r;
}
__device__ __forceinline__ float bf16_round(float x) {
    return __bfloat162float(__float2bfloat16(x));
}
__device__ __forceinline__ void bf16_split2(float a, float b, uint32_t& hi, uint32_t& lo) {
    hi = pack_bf16(a, b);
    lo = pack_bf16(a - bf16_round(a), b - bf16_round(b));
}
__device__ __forceinline__ void mma_bf16(float* c, uint32_t a0, uint32_t a1, uint32_t a2,
                                         uint32_t a3, uint32_t b0, uint32_t b1) {
    asm volatile(
        "mma.sync.aligned.m16n8k16.row.col.f32.bf16.bf16.f32 "
        "{%0,%1,%2,%3}, {%4,%5,%6,%7}, {%8,%9}, {%0,%1,%2,%3};"
        : "+f"(c[0]), "+f"(c[1]), "+f"(c[2]), "+f"(c[3])
        : "r"(a0), "r"(a1), "r"(a2), "r"(a3), "r"(b0), "r"(b1));
}
__device__ __forceinline__ uint32_t smem_u32(const void* p) {
    uint32_t a;
    asm("{ .reg .u64 t; cvta.to.shared.u64 t, %1; cvt.u32.u64 %0, t; }" : "=r"(a) : "l"(p));
    return a;
}
__device__ __forceinline__ void cpa16(uint32_t dst, const void* src) {
    asm volatile("cp.async.ca.shared.global [%0], [%1], 16;" :: "r"(dst), "l"(src));
}
#define CPA_COMMIT() asm volatile("cp.async.commit_group;" ::: "memory")
#define CPA_WAIT(n)  asm volatile("cp.async.wait_group %0;" :: "n"(n) : "memory")

// ---------------- fp32 -> bf16 hi/lo split (whole tensor) --------------------
__global__ __launch_bounds__(256)
void split_fp32(const float* __restrict__ src, uint32_t* __restrict__ hi,
                uint32_t* __restrict__ lo, int nwords) {
    for (int i = blockIdx.x * 256 + threadIdx.x; i < nwords; i += gridDim.x * 256) {
        float2 v = *(const float2*)(src + 2 * (size_t)i);
        uint32_t h, l;
        bf16_split2(v.x, v.y, h, l);
        hi[i] = h; lo[i] = l;
    }
}

// ==================== tensor-core bf16x3 GEMM (pre-split operands) ===========
// C[M,N] = A[M,K] @ B[N,K]^T with A/B given as bf16x2 hi/lo word arrays.
// CTA tile 128x128, BK=32 elems (16 words), dbl-buffered cp.async SMEM.
// 8 warps 4(M)x2(N); warp tile 32x64. PWG=20-word row pitch (conflict-free).
// mode 0: fp32 C.  mode 1: Q row-packed (scale 1/8) -> outh/outl.
// mode 2: K frag-packed interleaved u4 -> outh.
#define PWG 20
#define STGW (4 * 128 * PWG)
#define GM_SMEM (2 * STGW * 4)

__device__ __forceinline__ void gemm_body(const uint32_t* __restrict__ Ah,
                                          const uint32_t* __restrict__ Al,
                                          const uint32_t* __restrict__ Bh,
                                          const uint32_t* __restrict__ Bl,
                                          float* __restrict__ C,
                                          uint32_t* __restrict__ outh,
                                          uint32_t* __restrict__ outl,
                                          int N, int Kw, int mode,
                                          int rowBase, int colBase, uint32_t* sm) {
    int tid = threadIdx.x, lane = tid & 31, wid = tid >> 5;
    int gid = lane >> 2, tig = lane & 3;
    int wM = wid >> 1, wN = wid & 1;
    uint32_t smb = smem_u32(sm);

    int lrow = tid >> 1, lh8 = (tid & 1) * 8;   // load assignment
    const uint32_t* pAh = Ah + (size_t)(rowBase + lrow) * Kw + lh8;
    const uint32_t* pAl = Al + (size_t)(rowBase + lrow) * Kw + lh8;
    const uint32_t* pBh = Bh + (size_t)(colBase + lrow) * Kw + lh8;
    const uint32_t* pBl = Bl + (size_t)(colBase + lrow) * Kw + lh8;
    uint32_t dstOff = (lrow * PWG + lh8) * 4;   // bytes within array

    float acc[2][8][4];
#pragma unroll
    for (int mt = 0; mt < 2; mt++)
#pragma unroll
        for (int nt = 0; nt < 8; nt++)
#pragma unroll
            for (int c = 0; c < 4; c++) acc[mt][nt][c] = 0.f;

    const int NST = Kw / 16;

    // prefetch stage 0 into buf 0
    {
        uint32_t d0 = smb + dstOff;
        cpa16(d0,                        pAh);     cpa16(d0 + 16,                        pAh + 4);
        cpa16(d0 + 128 * PWG * 4,        pAl);     cpa16(d0 + 128 * PWG * 4 + 16,        pAl + 4);
        cpa16(d0 + 2 * 128 * PWG * 4,    pBh);     cpa16(d0 + 2 * 128 * PWG * 4 + 16,    pBh + 4);
        cpa16(d0 + 3 * 128 * PWG * 4,    pBl);     cpa16(d0 + 3 * 128 * PWG * 4 + 16,    pBl + 4);
        CPA_COMMIT();
    }

    for (int s = 0; s < NST; s++) {
        int buf = s & 1;
        if (s + 1 < NST) {
            int off = (s + 1) * 16;
            uint32_t d0 = smb + (buf ^ 1) * STGW * 4 + dstOff;
            cpa16(d0,                     pAh + off); cpa16(d0 + 16,                     pAh + off + 4);
            cpa16(d0 + 128 * PWG * 4,     pAl + off); cpa16(d0 + 128 * PWG * 4 + 16,     pAl + off + 4);
            cpa16(d0 + 2 * 128 * PWG * 4, pBh + off); cpa16(d0 + 2 * 128 * PWG * 4 + 16, pBh + off + 4);
            cpa16(d0 + 3 * 128 * PWG * 4, pBl + off); cpa16(d0 + 3 * 128 * PWG * 4 + 16, pBl + off + 4);
            CPA_COMMIT();
            CPA_WAIT(1);
        } else {
            CPA_WAIT(0);
        }
        __syncthreads();

        uint32_t* base = sm + buf * STGW;
        uint32_t* sAh = base;
        uint32_t* sAl = base + 128 * PWG;
        uint32_t* sBh = base + 2 * 128 * PWG;
        uint32_t* sBl = base + 3 * 128 * PWG;

#pragma unroll
        for (int ks = 0; ks < 2; ks++) {
            uint32_t ah[2][4], al[2][4];
#pragma unroll
            for (int mt = 0; mt < 2; mt++) {
                int r0 = (wM * 32 + mt * 16 + gid) * PWG + ks * 8 + tig;
                ah[mt][0] = sAh[r0];
                ah[mt][1] = sAh[r0 + 8 * PWG];
                ah[mt][2] = sAh[r0 + 4];
                ah[mt][3] = sAh[r0 + 8 * PWG + 4];
                al[mt][0] = sAl[r0];
                al[mt][1] = sAl[r0 + 8 * PWG];
                al[mt][2] = sAl[r0 + 4];
                al[mt][3] = sAl[r0 + 8 * PWG + 4];
            }
#pragma unroll
            for (int nt = 0; nt < 8; nt++) {
                int n0 = (wN * 64 + nt * 8 + gid) * PWG + ks * 8 + tig;
                uint32_t bh0 = sBh[n0], bh1 = sBh[n0 + 4];
                uint32_t bl0 = sBl[n0], bl1 = sBl[n0 + 4];
#pragma unroll
                for (int mt = 0; mt < 2; mt++) {
                    mma_bf16(acc[mt][nt], ah[mt][0], ah[mt][1], ah[mt][2], ah[mt][3], bh0, bh1);
                    mma_bf16(acc[mt][nt], ah[mt][0], ah[mt][1], ah[mt][2], ah[mt][3], bl0, bl1);
                    mma_bf16(acc[mt][nt], al[mt][0], al[mt][1], al[mt][2], al[mt][3], bh0, bh1);
                }
            }
        }
        __syncthreads();
    }

    // ---------------- epilogue ----------------
    if (mode == 0) {
#pragma unroll
        for (int mt = 0; mt < 2; mt++) {
            int r0 = rowBase + wM * 32 + mt * 16 + gid;
#pragma unroll
            for (int nt = 0; nt < 8; nt++) {
                int c0 = colBase + wN * 64 + nt * 8 + 2 * tig;
                *(float2*)(C + (size_t)r0 * N + c0) = make_float2(acc[mt][nt][0], acc[mt][nt][1]);
                *(float2*)(C + (size_t)(r0 + 8) * N + c0) = make_float2(acc[mt][nt][2], acc[mt][nt][3]);
            }
        }
    } else if (mode == 1) {   // Q row-packed, scaled 1/8: [tok][h][32 words]
#pragma unroll
        for (int mt = 0; mt < 2; mt++) {
            int r0 = rowBase + wM * 32 + mt * 16 + gid;
#pragma unroll
            for (int nt = 0; nt < 8; nt++) {
                int c0 = colBase + wN * 64 + nt * 8 + 2 * tig;
                int hh = c0 >> 6, w32 = (c0 & 63) >> 1;
                uint32_t h0, l0, h1, l1;
                bf16_split2(acc[mt][nt][0] * 0.125f, acc[mt][nt][1] * 0.125f, h0, l0);
                bf16_split2(acc[mt][nt][2] * 0.125f, acc[mt][nt][3] * 0.125f, h1, l1);
                size_t i0 = ((size_t)r0 * 16 + hh) * 32 + w32;
                size_t i1 = ((size_t)(r0 + 8) * 16 + hh) * 32 + w32;
                outh[i0] = h0; outl[i0] = l0;
                outh[i1] = h1; outl[i1] = l1;
            }
        }
    } else {                  // K frag-packed interleaved (h_t, h_t4, l_t, l_t4)
#pragma unroll
        for (int mt = 0; mt < 2; mt++) {
            int r0 = rowBase + wM * 32 + mt * 16 + gid;
#pragma unroll
            for (int nt = 0; nt < 8; nt++) {
                int c0 = colBase + wN * 64 + nt * 8 + 2 * tig;
                int kvh = c0 >> 6, wl = (c0 & 63) >> 1;
                int ks = wl >> 3, tigg = wl & 7;
                int tA = tigg & 3, comp = (tigg & 4) ? 1 : 0;
                size_t wi0 = (((size_t)kvh * MM + r0) * 16 + ks * 4 + tA) * 4;
                size_t wi1 = wi0 + 8 * 16 * 4;
                uint32_t h0, l0, h1, l1;
                bf16_split2(acc[mt][nt][0], acc[mt][nt][1], h0, l0);
                bf16_split2(acc[mt][nt][2], acc[mt][nt][3], h1, l1);
                outh[wi0 + comp] = h0; outh[wi0 + comp + 2] = l0;
                outh[wi1 + comp] = h1; outh[wi1 + comp + 2] = l1;
            }
        }
    }
}

__global__ __launch_bounds__(256, 2)
void gemm_mma(const uint32_t* __restrict__ Ah, const uint32_t* __restrict__ Al,
              const uint32_t* __restrict__ Bh, const uint32_t* __restrict__ Bl,
              float* __restrict__ C, uint32_t* __restrict__ outh,
              uint32_t* __restrict__ outl, int N, int Kw, int mode) {
    extern __shared__ uint32_t smg[];
    gemm_body(Ah, Al, Bh, Bl, C, outh, outl, N, Kw, mode,
              blockIdx.y * 128, blockIdx.x * 128, smg);
}

// fused K+V projection: z=0 -> K frag-packed, z=1 -> V fp32
__global__ __launch_bounds__(256, 2)
void gemm_mma_kv(const uint32_t* __restrict__ xh, const uint32_t* __restrict__ xl,
                 const uint32_t* __restrict__ wkh, const uint32_t* __restrict__ wkl,
                 const uint32_t* __restrict__ wvh, const uint32_t* __restrict__ wvl,
                 uint32_t* __restrict__ kp, float* __restrict__ Vo, int N, int Kw) {
    extern __shared__ uint32_t smg[];
    if (blockIdx.z)
        gemm_body(xh, xl, wvh, wvl, Vo, nullptr, nullptr, N, Kw, 0,
                  blockIdx.y * 128, blockIdx.x * 128, smg);
    else
        gemm_body(xh, xl, wkh, wkl, nullptr, kp, nullptr, N, Kw, 2,
                  blockIdx.y * 128, blockIdx.x * 128, smg);
}

// ---------------- V transpose + split + frag-pack ----------------------------
__global__ __launch_bounds__(128)
void v_pack(const float* __restrict__ v, uint4* __restrict__ vp) {
    __shared__ float sm[64 * 68];
    int kb = blockIdx.x, kvh = blockIdx.y, b = blockIdx.z;
    int tid = threadIdx.x;
    for (int e = tid; e < 64 * 16; e += 128) {
        int row = e >> 4, c4 = e & 15;
        float4 t4 = *(const float4*)(v + ((size_t)(b * SS + kb * 64 + row)) * (RHH * HDD)
                                       + kvh * HDD + c4 * 4);
        sm[row * 68 + c4 * 4 + 0] = t4.x;
        sm[row * 68 + c4 * 4 + 1] = t4.y;
        sm[row * 68 + c4 * 4 + 2] = t4.z;
        sm[row * 68 + c4 * 4 + 3] = t4.w;
    }
    __syncthreads();
    int d = tid & 63, kshalf = tid >> 6;
    size_t base = ((size_t)(b * RHH + kvh) * 64 + d) * 512 + kb * 16;
#pragma unroll
    for (int kk = 0; kk < 2; kk++) {
        int ks = kshalf * 2 + kk;
#pragma unroll
        for (int tg = 0; tg < 4; tg++) {
            int j0 = (ks * 8 + tg) * 2, j1 = (ks * 8 + tg + 4) * 2;
            float a  = sm[j0 * 68 + d],       b2 = sm[(j0 + 1) * 68 + d];
            float c  = sm[j1 * 68 + d],       d2 = sm[(j1 + 1) * 68 + d];
            uint32_t hx, lx, hy, ly;
            bf16_split2(a, b2, hx, lx);
            bf16_split2(c, d2, hy, ly);
            vp[base + ks * 4 + tg] = make_uint4(hx, hy, lx, ly);
        }
    }
}

// ---------------- build compacted row order: [causal asc | local asc] --------
__global__ __launch_bounds__(256)
void build_order(const float* __restrict__ gates, int* __restrict__ order) {
    int b = blockIdx.x, tid = threadIdx.x;
    __shared__ int cnt[256];
    bool loc[8];
    int c = 0;
#pragma unroll
    for (int i = 0; i < 8; i++) {
        loc[i] = gates[b * SS + tid * 8 + i] <= 0.5f;
        if (!loc[i]) c++;
    }
    cnt[tid] = c;
    __syncthreads();
    for (int off = 1; off < 256; off <<= 1) {
        int add = (tid >= off) ? cnt[tid - off] : 0;
        __syncthreads();
        cnt[tid] += add;
        __syncthreads();
    }
    int nC = cnt[255];
    int cb = cnt[tid] - c;
    int lb = nC + (tid * 8 - cb);
#pragma unroll
    for (int i = 0; i < 8; i++) {
        if (loc[i]) order[b * SS + lb++] = tid * 8 + i;
        else        order[b * SS + cb++] = tid * 8 + i;
    }
}

// ==================== mma flash attention (compacted rows) ===================
// CTA: 256 thr = 8 warps, 128 compacted q-rows. K dbl-buffered, V single.
// SMEM (uint4): Q hi [0,1024) lo [1024,2048); K buf{0,1} @2048+buf*1280; V @4608.
#define AT_SMEM (5888 * 16)

__global__ __launch_bounds__(256, 2)
void attn_mma(const uint32_t* __restrict__ qph, const uint32_t* __restrict__ qpl,
              const uint4* __restrict__ kp,  const uint4* __restrict__ vp,
              const float* __restrict__ gates, const int* __restrict__ order,
              uint32_t* __restrict__ oh, uint32_t* __restrict__ ol) {
    extern __shared__ uint4 sm4[];
    __shared__ int srows[128];
    __shared__ int sminlo, smaxhi;
    uint32_t smb = smem_u32(sm4);
    uint32_t* sQw = (uint32_t*)sm4;

    int t = blockIdx.x, h = blockIdx.y, b = blockIdx.z;
    int tid = threadIdx.x, lane = tid & 31, w = tid >> 5;
    int gid = lane >> 2, tig = lane & 3;
    int kvh = h & 3;

    if (tid == 0) { sminlo = SS; smaxhi = 0; }
    if (tid < 128) srows[tid] = order[b * SS + t * 128 + tid];
    __syncthreads();
    if (tid < 128) {
        int myi = srows[tid];
        bool isl = gates[b * SS + myi] <= 0.5f;
        int lo = isl ? max(0, myi - 64) : 0;
        int hi = isl ? min(SS - 1, myi + 64) : myi;
        atomicMin(&sminlo, lo);
        atomicMax(&smaxhi, hi);
    }

    // ---- Q gather: row-major packed -> frag layout (thread = row*2+half) ----
    {
        int r = tid >> 1, half = tid & 1;
        int ri = srows[r];
        const uint32_t* src = (half ? qpl : qph) + ((size_t)(b * SS + ri) * 16 + h) * 32;
        uint32_t* dst = sQw + half * 4096;
        int wd = r >> 4, g2 = r & 15;
        int gidq = g2 & 7, hiRow = g2 >> 3;
#pragma unroll
        for (int w32 = 0; w32 < 32; w32++) {
            int ks = w32 >> 3, rem = w32 & 7;
            int tg2 = rem & 3, comp = ((rem >> 2) << 1) | hiRow;
            dst[(((wd * 8 + gidq) * 4 + ks) * 4 + tg2) * 4 + comp] = src[w32];
        }
    }
    __syncthreads();

    int kbStart = sminlo >> 6;
    int kbEnd = (smaxhi >> 6) + 1;

    int i0 = srows[w * 16 + gid], i1 = srows[w * 16 + gid + 8];
    bool isl0 = gates[b * SS + i0] <= 0.5f;
    bool isl1 = gates[b * SS + i1] <= 0.5f;

    float m0 = -1e30f, m1 = -1e30f, l0s = 0.f, l1s = 0.f;
    float o[8][4];
#pragma unroll
    for (int nt = 0; nt < 8; nt++)
#pragma unroll
        for (int c = 0; c < 4; c++) o[nt][c] = 0.f;

    const uint4* kbase = kp + ((size_t)kvh * MM + b * SS) * 16;
    const uint4* vbase = vp + (size_t)(b * RHH + kvh) * 64 * 512;
    int fj = tid >> 2, fq = (tid & 3) * 4;

    // prefetch K[kbStart] + V[kbStart]
    {
        const uint4* gk = kbase + ((size_t)(kbStart * 64 + fj)) * 16 + fq;
        const uint4* gv = vbase + (size_t)fj * 512 + kbStart * 16 + fq;
        uint32_t dk = smb + (2048 + fj * 20 + fq) * 16;
        uint32_t dv = smb + (4608 + fj * 20 + fq) * 16;
#pragma unroll
        for (int c = 0; c < 4; c++) { cpa16(dk + c * 16, gk + c); cpa16(dv + c * 16, gv + c); }
        CPA_COMMIT();
    }

    for (int kb = kbStart; kb < kbEnd; kb++) {
        int buf = (kb - kbStart) & 1;
        CPA_WAIT(0);
        __syncthreads();

        if (kb + 1 < kbEnd) {
            const uint4* gk = kbase + ((size_t)((kb + 1) * 64 + fj)) * 16 + fq;
            uint32_t dk = smb + (2048 + (buf ^ 1) * 1280 + fj * 20 + fq) * 16;
#pragma unroll
            for (int c = 0; c < 4; c++) cpa16(dk + c * 16, gk + c);
            CPA_COMMIT();
        }

        const uint4* sK = sm4 + 2048 + buf * 1280;
        const uint4* sV = sm4 + 4608;

        // ---- QK^T ----
        float s[8][4];
#pragma unroll
        for (int nt = 0; nt < 8; nt++)
#pragma unroll
            for (int c = 0; c < 4; c++) s[nt][c] = 0.f;

#pragma unroll
        for (int ks = 0; ks < 4; ks++) {
            uint4 qh = sm4[w * 128 + gid * 16 + ks * 4 + tig];
            uint4 ql = sm4[1024 + w * 128 + gid * 16 + ks * 4 + tig];
#pragma unroll
            for (int nt = 0; nt < 8; nt++) {
                uint4 kk = sK[(nt * 8 + gid) * 20 + ks * 4 + tig];
                mma_bf16(s[nt], qh.x, qh.y, qh.z, qh.w, kk.x, kk.y);
                mma_bf16(s[nt], qh.x, qh.y, qh.z, qh.w, kk.z, kk.w);
                mma_bf16(s[nt], ql.x, ql.y, ql.z, ql.w, kk.x, kk.y);
            }
        }

        // ---- mask + online softmax ----
        float rm0 = -1e30f, rm1 = -1e30f;
#pragma unroll
        for (int nt = 0; nt < 8; nt++) {
            int jb = kb * 64 + nt * 8 + 2 * tig;
#pragma unroll
            for (int c = 0; c < 2; c++) {
                int j = jb + c;
                bool v0 = isl0 ? (abs(i0 - j) <= 64) : (j <= i0);
                s[nt][c] = v0 ? s[nt][c] : -1e30f;
                rm0 = fmaxf(rm0, s[nt][c]);
                bool v1 = isl1 ? (abs(i1 - j) <= 64) : (j <= i1);
                s[nt][2 + c] = v1 ? s[nt][2 + c] : -1e30f;
                rm1 = fmaxf(rm1, s[nt][2 + c]);
            }
        }
        rm0 = fmaxf(rm0, __shfl_xor_sync(0xffffffffu, rm0, 1));
        rm0 = fmaxf(rm0, __shfl_xor_sync(0xffffffffu, rm0, 2));
        rm1 = fmaxf(rm1, __shfl_xor_sync(0xffffffffu, rm1, 1));
        rm1 = fmaxf(rm1, __shfl_xor_sync(0xffffffffu, rm1, 2));

        float mn0 = fmaxf(m0, rm0), mn1 = fmaxf(m1, rm1);
        float al0f = __expf(fmaxf(m0 - mn0, -80.f));
        float al1f = __expf(fmaxf(m1 - mn1, -80.f));
        float rs0 = 0.f, rs1 = 0.f;
#pragma unroll
        for (int nt = 0; nt < 8; nt++) {
#pragma unroll
            for (int c = 0; c < 2; c++) {
                float p0 = __expf(fmaxf(s[nt][c] - mn0, -80.f));
                s[nt][c] = p0; rs0 += p0;
                float p1 = __expf(fmaxf(s[nt][2 + c] - mn1, -80.f));
                s[nt][2 + c] = p1; rs1 += p1;
            }
        }
        rs0 += __shfl_xor_sync(0xffffffffu, rs0, 1);
        rs0 += __shfl_xor_sync(0xffffffffu, rs0, 2);
        rs1 += __shfl_xor_sync(0xffffffffu, rs1, 1);
        rs1 += __shfl_xor_sync(0xffffffffu, rs1, 2);
        m0 = mn0; m1 = mn1;
        l0s = l0s * al0f + rs0;
        l1s = l1s * al1f + rs1;
#pragma unroll
        for (int nt = 0; nt < 8; nt++) {
            o[nt][0] *= al0f; o[nt][1] *= al0f;
            o[nt][2] *= al1f; o[nt][3] *= al1f;
        }

        // ---- PV (P from registers, single V buffer) ----
#pragma unroll
        for (int ks = 0; ks < 4; ks++) {
            uint32_t ah0, al0, ah1, al1, ah2, al2, ah3, al3;
            bf16_split2(s[2 * ks][0],     s[2 * ks][1],     ah0, al0);
            bf16_split2(s[2 * ks][2],     s[2 * ks][3],     ah1, al1);
            bf16_split2(s[2 * ks + 1][0], s[2 * ks + 1][1], ah2, al2);
            bf16_split2(s[2 * ks + 1][2], s[2 * ks + 1][3], ah3, al3);
#pragma unroll
            for (int nt = 0; nt < 8; nt++) {
                uint4 vv = sV[(nt * 8 + gid) * 20 + ks * 4 + tig];
                mma_bf16(o[nt], ah0, ah1, ah2, ah3, vv.x, vv.y);
                mma_bf16(o[nt], ah0, ah1, ah2, ah3, vv.z, vv.w);
                mma_bf16(o[nt], al0, al1, al2, al3, vv.x, vv.y);
            }
        }
        __syncthreads();

        if (kb + 1 < kbEnd) {
            const uint4* gv = vbase + (size_t)fj * 512 + (kb + 1) * 16 + fq;
            uint32_t dv = smb + (4608 + fj * 20 + fq) * 16;
#pragma unroll
            for (int c = 0; c < 4; c++) cpa16(dv + c * 16, gv + c);
            CPA_COMMIT();
        }
    }

    // ---- epilogue: write row-packed bf16 hi/lo words (scatter to true rows) --
    float inv0 = (l0s > 0.f) ? 1.f / l0s : 0.f;
    float inv1 = (l1s > 0.f) ? 1.f / l1s : 0.f;
    size_t base0 = ((size_t)(b * SS + i0) * 16 + h) * 32 + tig;
    size_t base1 = ((size_t)(b * SS + i1) * 16 + h) * 32 + tig;
#pragma unroll
    for (int nt = 0; nt < 8; nt++) {
        uint32_t h0, l0, h1, l1;
        bf16_split2(o[nt][0] * inv0, o[nt][1] * inv0, h0, l0);
        bf16_split2(o[nt][2] * inv1, o[nt][3] * inv1, h1, l1);
        oh[base0 + nt * 4] = h0; ol[base0 + nt * 4] = l0;
        oh[base1 + nt * 4] = h1; ol[base1 + nt * 4] = l1;
    }
}

// ---------------- gate: LN + dot(wg) + sigmoid(clamp) -----------------------
__global__ void gate_kernel(const float* __restrict__ x,
                            const float* __restrict__ wg,
                            const float* __restrict__ bg,
                            const float* __restrict__ gamma,
                            const float* __restrict__ beta,
                            float* __restrict__ gates) {
    int token = blockIdx.x;
    const float* row = x + (size_t)token * HH;
    __shared__ float red[256];
    int tid = threadIdx.x;

    float xr[4];
#pragma unroll
    for (int i = 0; i < 4; i++) xr[i] = row[tid + i * 256];

    float s = xr[0] + xr[1] + xr[2] + xr[3];
    red[tid] = s; __syncthreads();
    for (int o = 128; o > 0; o >>= 1) { if (tid < o) red[tid] += red[tid + o]; __syncthreads(); }
    float mu = red[0] * (1.0f / HH);
    __syncthreads();

    float v = 0.f;
#pragma unroll
    for (int i = 0; i < 4; i++) { float d = xr[i] - mu; v = fmaf(d, d, v); }
    red[tid] = v; __syncthreads();
    for (int o = 128; o > 0; o >>= 1) { if (tid < o) red[tid] += red[tid + o]; __syncthreads(); }
    float rstd = rsqrtf(red[0] * (1.0f / HH) + 1e-5f);
    __syncthreads();

    float dot = 0.f;
#pragma unroll
    for (int i = 0; i < 4; i++) {
        int hh = tid + i * 256;
        float y = fmaf((xr[i] - mu) * rstd, gamma[hh], beta[hh]);
        dot = fmaf(y, wg[hh], dot);
    }
    red[tid] = dot; __syncthreads();
    for (int o = 128; o > 0; o >>= 1) { if (tid < o) red[tid] += red[tid + o]; __syncthreads(); }
    if (tid == 0) {
        float z = red[0] + bg[0];
        z = fminf(10.f, fmaxf(-10.f, z));
        gates[token] = 1.f / (1.f + expf(-z));
    }
}

// ---------------- gate regularization loss ------------------------------------
__global__ void regloss_kernel(const float* __restrict__ gates, float* __restrict__ out,
                               int writeIdx) {
    __shared__ float red[256];
    int tid = threadIdx.x;
    float acc = 0.f;
    for (int t = tid; t < MM; t += 256) {
        float g = gates[t];
        float gs = fminf(fmaxf(g, 1e-5f), 1.f - 1e-5f);
        float binary = g * (1.f - g);
        float ent = g * logf(gs) + (1.f - g) * logf(1.f - gs);
        acc += 0.1f * binary - 0.01f * ent + 0.1f * g;
    }
    red[tid] = acc; __syncthreads();
    for (int o = 128; o > 0; o >>= 1) { if (tid < o) red[tid] += red[tid + o]; __syncthreads(); }
    if (tid == 0) out[writeIdx] = red[0] * (1.0f / MM);
}

// ---------------- launch ------------------------------------------------------
extern "C" void kernel_launch(void* const* d_in, const int* in_sizes, int n_in,
                              void* d_out, int out_size) {
    const float* x     = (const float*)d_in[0];
    const float* Wq    = (const float*)d_in[1];
    const float* Wk    = (const float*)d_in[2];
    const float* Wv    = (const float*)d_in[3];
    const float* Wo    = (const float*)d_in[4];
    const float* Wg    = (const float*)d_in[5];
    const float* bg    = (const float*)d_in[6];
    const float* gamma = (const float*)d_in[7];
    const float* beta  = (const float*)d_in[8];
    float* out = (float*)d_out;

    float *pGates, *pV;
    uint32_t *pXh, *pXl, *pWqh, *pWql, *pWkh, *pWkl, *pWvh, *pWvl, *pWoh, *pWol;
    uint32_t *pQh, *pQl, *pKp, *pOh, *pOl;
    uint4 *pVp;
    int *pOrder;
    cudaGetSymbolAddress((void**)&pGates, g_gates);
    cudaGetSymbolAddress((void**)&pOrder, g_order);
    cudaGetSymbolAddress((void**)&pXh,    g_xh);
    cudaGetSymbolAddress((void**)&pXl,    g_xl);
    cudaGetSymbolAddress((void**)&pWqh,   g_wqh);
    cudaGetSymbolAddress((void**)&pWql,   g_wql);
    cudaGetSymbolAddress((void**)&pWkh,   g_wkh);
    cudaGetSymbolAddress((void**)&pWkl,   g_wkl);
    cudaGetSymbolAddress((void**)&pWvh,   g_wvh);
    cudaGetSymbolAddress((void**)&pWvl,   g_wvl);
    cudaGetSymbolAddress((void**)&pWoh,   g_woh);
    cudaGetSymbolAddress((void**)&pWol,   g_wol);
    cudaGetSymbolAddress((void**)&pQh,    g_qph);
    cudaGetSymbolAddress((void**)&pQl,    g_qpl);
    cudaGetSymbolAddress((void**)&pKp,    g_kp);
    cudaGetSymbolAddress((void**)&pV,     g_v);
    cudaGetSymbolAddress((void**)&pVp,    g_vp);
    cudaGetSymbolAddress((void**)&pOh,    g_oh);
    cudaGetSymbolAddress((void**)&pOl,    g_ol);

    cudaFuncSetAttribute(gemm_mma, cudaFuncAttributeMaxDynamicSharedMemorySize, GM_SMEM);
    cudaFuncSetAttribute(gemm_mma_kv, cudaFuncAttributeMaxDynamicSharedMemorySize, GM_SMEM);
    cudaFuncSetAttribute(attn_mma, cudaFuncAttributeMaxDynamicSharedMemorySize, AT_SMEM);

    gate_kernel<<<MM, 256>>>(x, Wg, bg, gamma, beta, pGates);
    build_order<<<BB, 256>>>(pGates, pOrder);

    split_fp32<<<1024, 256>>>(x,  pXh,  pXl,  MM * KW);
    split_fp32<<<512,  256>>>(Wq, pWqh, pWql, HH * KW);
    split_fp32<<<256,  256>>>(Wk, pWkh, pWkl, (RHH * HDD) * KW);
    split_fp32<<<256,  256>>>(Wv, pWvh, pWvl, (RHH * HDD) * KW);
    split_fp32<<<512,  256>>>(Wo, pWoh, pWol, HH * KW);

    gemm_mma<<<dim3(HH / 128, MM / 128), 256, GM_SMEM>>>(
        pXh, pXl, pWqh, pWql, nullptr, pQh, pQl, HH, KW, 1);
    gemm_mma_kv<<<dim3((RHH * HDD) / 128, MM / 128, 2), 256, GM_SMEM>>>(
        pXh, pXl, pWkh, pWkl, pWvh, pWvl, pKp, pV, RHH * HDD, KW);
    v_pack<<<dim3(SS / 64, RHH, BB), 128>>>(pV, pVp);

    attn_mma<<<dim3(SS / 128, NHD, BB), 256, AT_SMEM>>>(
        pQh, pQl, (const uint4*)pKp, pVp, pGates, pOrder, pOh, pOl);

    gemm_mma<<<dim3(HH / 128, MM / 128), 256, GM_SMEM>>>(
        pOh, pOl, pWoh, pWol, out, nullptr, nullptr, HH, KW, 0);

    if (out_size > MM * HH)
        regloss_kernel<<<1, 256>>>(pGates, out, MM * HH);
}

// round 12
// speedup vs baseline: 3.7250x; 1.0193x over previous
#include <cuda_runtime.h>
#include <cuda_bf16.h>
#include <math.h>
#include <stdint.h>

// Problem constants
#define BB  2
#define SS  2048
#define HH  1024
#define NHD 16      // num heads
#define HDD 64      // head dim
#define RHH 4       // kv heads
#define MM  (BB*SS) // 4096 token rows
#define KW  (HH/2)  // 512 words per row (bf16x2)

// word counts per tensor (for merged split kernel)
#define XW  (MM*KW)          // 2097152
#define WQW (HH*KW)          // 524288
#define WKW ((RHH*HDD)*KW)   // 131072
#define TOTW (XW + WQW + 2*WKW + WQW)

// ---------------- scratch (static device memory; no allocs allowed) ----------
__device__ float    g_gates[MM];
__device__ int      g_order[MM];
__device__ uint32_t g_xh [(size_t)MM * KW];           // x split hi (permuted word order)
__device__ uint32_t g_xl [(size_t)MM * KW];
__device__ uint32_t g_wqh[(size_t)HH * KW];
__device__ uint32_t g_wql[(size_t)HH * KW];
__device__ uint32_t g_wkh[(size_t)(RHH*HDD) * KW];
__device__ uint32_t g_wkl[(size_t)(RHH*HDD) * KW];
__device__ uint32_t g_wvh[(size_t)(RHH*HDD) * KW];
__device__ uint32_t g_wvl[(size_t)(RHH*HDD) * KW];
__device__ uint32_t g_woh[(size_t)HH * KW];
__device__ uint32_t g_wol[(size_t)HH * KW];
__device__ uint32_t g_qph[(size_t)MM * 512];          // Q row-packed bf16 hi [tok][h][32w] (raw order)
__device__ uint32_t g_qpl[(size_t)MM * 512];
__device__ uint32_t g_kp [(size_t)RHH * MM * 64];     // K frag-packed (hi+lo interleaved u4)
__device__ uint4    g_vp [(size_t)BB * RHH * HDD * 512]; // V transposed frag-packed
__device__ uint32_t g_oh [(size_t)MM * 512];          // attn out split hi (permuted word order)
__device__ uint32_t g_ol [(size_t)MM * 512];

// ---------------- bf16 helpers ----------------------------------------------
__device__ __forceinline__ uint32_t pack_bf16(float lowElem, float highElem) {
    uint32_t r;
    asm("cvt.rn.bf16x2.f32 %0, %1, %2;" : "=r"(r) : "f"(highElem), "f"(lowElem));
    return r;
}
__device__ __forceinline__ float bf16_round(float x) {
    return __bfloat162float(__float2bfloat16(x));
}
__device__ __forceinline__ void bf16_split2(float a, float b, uint32_t& hi, uint32_t& lo) {
    hi = pack_bf16(a, b);
    lo = pack_bf16(a - bf16_round(a), b - bf16_round(b));
}
__device__ __forceinline__ void mma_bf16(float* c, uint32_t a0, uint32_t a1, uint32_t a2,
                                         uint32_t a3, uint32_t b0, uint32_t b1) {
    asm volatile(
        "mma.sync.aligned.m16n8k16.row.col.f32.bf16.bf16.f32 "
        "{%0,%1,%2,%3}, {%4,%5,%6,%7}, {%8,%9}, {%0,%1,%2,%3};"
        : "+f"(c[0]), "+f"(c[1]), "+f"(c[2]), "+f"(c[3])
        : "r"(a0), "r"(a1), "r"(a2), "r"(a3), "r"(b0), "r"(b1));
}
__device__ __forceinline__ uint32_t smem_u32(const void* p) {
    uint32_t a;
    asm("{ .reg .u64 t; cvta.to.shared.u64 t, %1; cvt.u32.u64 %0, t; }" : "=r"(a) : "l"(p));
    return a;
}
__device__ __forceinline__ void cpa16(uint32_t dst, const void* src) {
    asm volatile("cp.async.ca.shared.global [%0], [%1], 16;" :: "r"(dst), "l"(src));
}
#define CPA_COMMIT() asm volatile("cp.async.commit_group;" ::: "memory")
#define CPA_WAIT(n)  asm volatile("cp.async.wait_group %0;" :: "n"(n) : "memory")

// ---------------- merged fp32 -> bf16 hi/lo split, permuted word order -------
// Within each 8-word group, original word w (t=w&7) is stored at position
// (t&3)*2 + (t>>2). Pair reads at (g*8 + tig*2, +1) then yield (w=tig, w=tig+4).
__global__ __launch_bounds__(256)
void split_all(const float* __restrict__ x,  const float* __restrict__ Wq,
               const float* __restrict__ Wk, const float* __restrict__ Wv,
               const float* __restrict__ Wo,
               uint32_t* __restrict__ xh,  uint32_t* __restrict__ xl,
               uint32_t* __restrict__ wqh, uint32_t* __restrict__ wql,
               uint32_t* __restrict__ wkh, uint32_t* __restrict__ wkl,
               uint32_t* __restrict__ wvh, uint32_t* __restrict__ wvl,
               uint32_t* __restrict__ woh, uint32_t* __restrict__ wol) {
    for (int i = blockIdx.x * 256 + threadIdx.x; i < TOTW; i += gridDim.x * 256) {
        const float* src; uint32_t *ph, *pl; int local;
        if (i < XW)                      { src = x;  ph = xh;  pl = xl;  local = i; }
        else if (i < XW + WQW)           { src = Wq; ph = wqh; pl = wql; local = i - XW; }
        else if (i < XW + WQW + WKW)     { src = Wk; ph = wkh; pl = wkl; local = i - XW - WQW; }
        else if (i < XW + WQW + 2*WKW)   { src = Wv; ph = wvh; pl = wvl; local = i - XW - WQW - WKW; }
        else                             { src = Wo; ph = woh; pl = wol; local = i - XW - WQW - 2*WKW; }
        float2 v = *(const float2*)(src + 2 * (size_t)local);
        uint32_t h, l;
        bf16_split2(v.x, v.y, h, l);
        int t = local & 7;
        int pos = (local & ~7) | ((t & 3) << 1) | (t >> 2);
        ph[pos] = h; pl[pos] = l;
    }
}

// ==================== tensor-core bf16x3 GEMM (pre-split, permuted) ==========
// C[M,N] = A[M,K] @ B[N,K]^T, A/B as permuted bf16x2 hi/lo word arrays.
// CTA tile 128x128, BK=32 elems (16 words), dbl-buffered cp.async SMEM.
// 8 warps 4(M)x2(N); warp tile 32x64. PWG=24-word pitch (LDS.64 conflict-free).
// mode 0: fp32 C. mode 1: Q row-packed raw order (scale 1/8) -> outh/outl.
// mode 2: K frag-packed u4 -> outh. mode 3: V transposed frag-packed -> vpout.
#define PWG 24
#define STGW (4 * 128 * PWG)
#define GM_SMEM (2 * STGW * 4)

__device__ __forceinline__ void gemm_body(const uint32_t* __restrict__ Ah,
                                          const uint32_t* __restrict__ Al,
                                          const uint32_t* __restrict__ Bh,
                                          const uint32_t* __restrict__ Bl,
                                          float* __restrict__ C,
                                          uint32_t* __restrict__ outh,
                                          uint32_t* __restrict__ outl,
                                          uint4* __restrict__ vpout,
                                          int N, int Kw, int mode,
                                          int rowBase, int colBase, uint32_t* sm) {
    int tid = threadIdx.x, lane = tid & 31, wid = tid >> 5;
    int gid = lane >> 2, tig = lane & 3;
    int wM = wid >> 1, wN = wid & 1;
    uint32_t smb = smem_u32(sm);

    int lrow = tid >> 1, lh8 = (tid & 1) * 8;
    const uint32_t* pAh = Ah + (size_t)(rowBase + lrow) * Kw + lh8;
    const uint32_t* pAl = Al + (size_t)(rowBase + lrow) * Kw + lh8;
    const uint32_t* pBh = Bh + (size_t)(colBase + lrow) * Kw + lh8;
    const uint32_t* pBl = Bl + (size_t)(colBase + lrow) * Kw + lh8;
    uint32_t dstOff = (lrow * PWG + lh8) * 4;

    float acc[2][8][4];
#pragma unroll
    for (int mt = 0; mt < 2; mt++)
#pragma unroll
        for (int nt = 0; nt < 8; nt++)
#pragma unroll
            for (int c = 0; c < 4; c++) acc[mt][nt][c] = 0.f;

    const int NST = Kw / 16;

    {
        uint32_t d0 = smb + dstOff;
        cpa16(d0,                        pAh);  cpa16(d0 + 16,                        pAh + 4);
        cpa16(d0 + 128 * PWG * 4,        pAl);  cpa16(d0 + 128 * PWG * 4 + 16,        pAl + 4);
        cpa16(d0 + 2 * 128 * PWG * 4,    pBh);  cpa16(d0 + 2 * 128 * PWG * 4 + 16,    pBh + 4);
        cpa16(d0 + 3 * 128 * PWG * 4,    pBl);  cpa16(d0 + 3 * 128 * PWG * 4 + 16,    pBl + 4);
        CPA_COMMIT();
    }

    for (int s = 0; s < NST; s++) {
        int buf = s & 1;
        if (s + 1 < NST) {
            int off = (s + 1) * 16;
            uint32_t d0 = smb + (buf ^ 1) * STGW * 4 + dstOff;
            cpa16(d0,                     pAh + off); cpa16(d0 + 16,                     pAh + off + 4);
            cpa16(d0 + 128 * PWG * 4,     pAl + off); cpa16(d0 + 128 * PWG * 4 + 16,     pAl + off + 4);
            cpa16(d0 + 2 * 128 * PWG * 4, pBh + off); cpa16(d0 + 2 * 128 * PWG * 4 + 16, pBh + off + 4);
            cpa16(d0 + 3 * 128 * PWG * 4, pBl + off); cpa16(d0 + 3 * 128 * PWG * 4 + 16, pBl + off + 4);
            CPA_COMMIT();
            CPA_WAIT(1);
        } else {
            CPA_WAIT(0);
        }
        __syncthreads();

        uint32_t* base = sm + buf * STGW;
        uint32_t* sAh = base;
        uint32_t* sAl = base + 128 * PWG;
        uint32_t* sBh = base + 2 * 128 * PWG;
        uint32_t* sBl = base + 3 * 128 * PWG;

#pragma unroll
        for (int ks = 0; ks < 2; ks++) {
            uint32_t ah[2][4], al[2][4];
#pragma unroll
            for (int mt = 0; mt < 2; mt++) {
                int r0 = (wM * 32 + mt * 16 + gid) * PWG + ks * 8 + tig * 2;
                uint2 eh = *(const uint2*)(sAh + r0);
                uint2 oh2 = *(const uint2*)(sAh + r0 + 8 * PWG);
                ah[mt][0] = eh.x; ah[mt][1] = oh2.x; ah[mt][2] = eh.y; ah[mt][3] = oh2.y;
                uint2 el = *(const uint2*)(sAl + r0);
                uint2 ol2 = *(const uint2*)(sAl + r0 + 8 * PWG);
                al[mt][0] = el.x; al[mt][1] = ol2.x; al[mt][2] = el.y; al[mt][3] = ol2.y;
            }
#pragma unroll
            for (int nt = 0; nt < 8; nt++) {
                int n0 = (wN * 64 + nt * 8 + gid) * PWG + ks * 8 + tig * 2;
                uint2 bh = *(const uint2*)(sBh + n0);
                uint2 bl = *(const uint2*)(sBl + n0);
#pragma unroll
                for (int mt = 0; mt < 2; mt++) {
                    mma_bf16(acc[mt][nt], ah[mt][0], ah[mt][1], ah[mt][2], ah[mt][3], bh.x, bh.y);
                    mma_bf16(acc[mt][nt], ah[mt][0], ah[mt][1], ah[mt][2], ah[mt][3], bl.x, bl.y);
                    mma_bf16(acc[mt][nt], al[mt][0], al[mt][1], al[mt][2], al[mt][3], bh.x, bh.y);
                }
            }
        }
        __syncthreads();
    }

    // ---------------- epilogue ----------------
    if (mode == 0) {
#pragma unroll
        for (int mt = 0; mt < 2; mt++) {
            int r0 = rowBase + wM * 32 + mt * 16 + gid;
#pragma unroll
            for (int nt = 0; nt < 8; nt++) {
                int c0 = colBase + wN * 64 + nt * 8 + 2 * tig;
                *(float2*)(C + (size_t)r0 * N + c0) = make_float2(acc[mt][nt][0], acc[mt][nt][1]);
                *(float2*)(C + (size_t)(r0 + 8) * N + c0) = make_float2(acc[mt][nt][2], acc[mt][nt][3]);
            }
        }
    } else if (mode == 1) {   // Q row-packed raw order, scaled 1/8
#pragma unroll
        for (int mt = 0; mt < 2; mt++) {
            int r0 = rowBase + wM * 32 + mt * 16 + gid;
#pragma unroll
            for (int nt = 0; nt < 8; nt++) {
                int c0 = colBase + wN * 64 + nt * 8 + 2 * tig;
                int hh = c0 >> 6, w32 = (c0 & 63) >> 1;
                uint32_t h0, l0, h1, l1;
                bf16_split2(acc[mt][nt][0] * 0.125f, acc[mt][nt][1] * 0.125f, h0, l0);
                bf16_split2(acc[mt][nt][2] * 0.125f, acc[mt][nt][3] * 0.125f, h1, l1);
                size_t i0 = ((size_t)r0 * 16 + hh) * 32 + w32;
                size_t i1 = ((size_t)(r0 + 8) * 16 + hh) * 32 + w32;
                outh[i0] = h0; outl[i0] = l0;
                outh[i1] = h1; outl[i1] = l1;
            }
        }
    } else if (mode == 2) {   // K frag-packed interleaved
#pragma unroll
        for (int mt = 0; mt < 2; mt++) {
            int r0 = rowBase + wM * 32 + mt * 16 + gid;
#pragma unroll
            for (int nt = 0; nt < 8; nt++) {
                int c0 = colBase + wN * 64 + nt * 8 + 2 * tig;
                int kvh = c0 >> 6, wl = (c0 & 63) >> 1;
                int ks = wl >> 3, tigg = wl & 7;
                int tA = tigg & 3, comp = (tigg & 4) ? 1 : 0;
                size_t wi0 = (((size_t)kvh * MM + r0) * 16 + ks * 4 + tA) * 4;
                size_t wi1 = wi0 + 8 * 16 * 4;
                uint32_t h0, l0, h1, l1;
                bf16_split2(acc[mt][nt][0], acc[mt][nt][1], h0, l0);
                bf16_split2(acc[mt][nt][2], acc[mt][nt][3], h1, l1);
                outh[wi0 + comp] = h0; outh[wi0 + comp + 2] = l0;
                outh[wi1 + comp] = h1; outh[wi1 + comp + 2] = l1;
            }
        }
    } else {                  // mode 3: V transposed frag-packed (shfl pair exchange)
#pragma unroll
        for (int mt = 0; mt < 2; mt++) {
            int r = wM * 32 + mt * 16 + gid;
            int tok = rowBase + r;
            int b = tok / SS;
            int j64 = tok % SS;
            int kb = j64 >> 6;
            int j = j64 & 63;
            int ks = j >> 4, tg = (j >> 1) & 3;
            bool even = (gid & 1) == 0;
#pragma unroll
            for (int nt = 0; nt < 8; nt++) {
                int c0 = colBase + wN * 64 + nt * 8 + 2 * tig;
                float p0 = __shfl_xor_sync(0xffffffffu, acc[mt][nt][0], 4);
                float p1 = __shfl_xor_sync(0xffffffffu, acc[mt][nt][1], 4);
                float p2 = __shfl_xor_sync(0xffffffffu, acc[mt][nt][2], 4);
                float p3 = __shfl_xor_sync(0xffffffffu, acc[mt][nt][3], 4);
                float v0, v1, v2, v3; int d;
                if (even) { d = c0;     v0 = acc[mt][nt][0]; v1 = p0; v2 = acc[mt][nt][2]; v3 = p2; }
                else      { d = c0 + 1; v0 = p1; v1 = acc[mt][nt][1]; v2 = p3; v3 = acc[mt][nt][3]; }
                int kvh = d >> 6, dd = d & 63;
                uint32_t hx, lx, hy, ly;
                bf16_split2(v0, v1, hx, lx);
                bf16_split2(v2, v3, hy, ly);
                vpout[((size_t)(b * RHH + kvh) * 64 + dd) * 512 + kb * 16 + ks * 4 + tg] =
                    make_uint4(hx, hy, lx, ly);
            }
        }
    }
}

__global__ __launch_bounds__(256, 2)
void gemm_mma(const uint32_t* __restrict__ Ah, const uint32_t* __restrict__ Al,
              const uint32_t* __restrict__ Bh, const uint32_t* __restrict__ Bl,
              float* __restrict__ C, uint32_t* __restrict__ outh,
              uint32_t* __restrict__ outl, int N, int Kw, int mode) {
    extern __shared__ uint32_t smg[];
    gemm_body(Ah, Al, Bh, Bl, C, outh, outl, nullptr, N, Kw, mode,
              blockIdx.y * 128, blockIdx.x * 128, smg);
}

// fused K+V projection: z=0 -> K frag-packed, z=1 -> V frag-packed (vp)
__global__ __launch_bounds__(256, 2)
void gemm_mma_kv(const uint32_t* __restrict__ xh, const uint32_t* __restrict__ xl,
                 const uint32_t* __restrict__ wkh, const uint32_t* __restrict__ wkl,
                 const uint32_t* __restrict__ wvh, const uint32_t* __restrict__ wvl,
                 uint32_t* __restrict__ kp, uint4* __restrict__ vpout, int N, int Kw) {
    extern __shared__ uint32_t smg[];
    if (blockIdx.z)
        gemm_body(xh, xl, wvh, wvl, nullptr, nullptr, nullptr, vpout, N, Kw, 3,
                  blockIdx.y * 128, blockIdx.x * 128, smg);
    else
        gemm_body(xh, xl, wkh, wkl, nullptr, kp, nullptr, nullptr, N, Kw, 2,
                  blockIdx.y * 128, blockIdx.x * 128, smg);
}

// ---------------- build compacted row order: [causal asc | local asc] --------
__global__ __launch_bounds__(256)
void build_order(const float* __restrict__ gates, int* __restrict__ order) {
    int b = blockIdx.x, tid = threadIdx.x;
    __shared__ int cnt[256];
    bool loc[8];
    int c = 0;
#pragma unroll
    for (int i = 0; i < 8; i++) {
        loc[i] = gates[b * SS + tid * 8 + i] <= 0.5f;
        if (!loc[i]) c++;
    }
    cnt[tid] = c;
    __syncthreads();
    for (int off = 1; off < 256; off <<= 1) {
        int add = (tid >= off) ? cnt[tid - off] : 0;
        __syncthreads();
        cnt[tid] += add;
        __syncthreads();
    }
    int nC = cnt[255];
    int cb = cnt[tid] - c;
    int lb = nC + (tid * 8 - cb);
#pragma unroll
    for (int i = 0; i < 8; i++) {
        if (loc[i]) order[b * SS + lb++] = tid * 8 + i;
        else        order[b * SS + cb++] = tid * 8 + i;
    }
}

// ==================== mma flash attention (compacted rows) ===================
// CTA: 256 thr = 8 warps, 128 compacted q-rows. K dbl-buffered, V single.
// SMEM (uint4): Q hi [0,1024) lo [1024,2048); K buf{0,1} @2048+buf*1280; V @4608.
#define AT_SMEM (5888 * 16)

__global__ __launch_bounds__(256, 2)
void attn_mma(const uint32_t* __restrict__ qph, const uint32_t* __restrict__ qpl,
              const uint4* __restrict__ kp,  const uint4* __restrict__ vp,
              const float* __restrict__ gates, const int* __restrict__ order,
              uint32_t* __restrict__ oh, uint32_t* __restrict__ ol) {
    extern __shared__ uint4 sm4[];
    __shared__ int srows[128];
    __shared__ int sminlo, smaxhi;
    uint32_t smb = smem_u32(sm4);
    uint32_t* sQw = (uint32_t*)sm4;

    int t = blockIdx.x, h = blockIdx.y, b = blockIdx.z;
    int tid = threadIdx.x, lane = tid & 31, w = tid >> 5;
    int gid = lane >> 2, tig = lane & 3;
    int kvh = h & 3;

    if (tid == 0) { sminlo = SS; smaxhi = 0; }
    if (tid < 128) srows[tid] = order[b * SS + t * 128 + tid];
    __syncthreads();
    if (tid < 128) {
        int myi = srows[tid];
        bool isl = gates[b * SS + myi] <= 0.5f;
        int lo = isl ? max(0, myi - 64) : 0;
        int hi = isl ? min(SS - 1, myi + 64) : myi;
        atomicMin(&sminlo, lo);
        atomicMax(&smaxhi, hi);
    }

    // ---- Q gather: row-major packed (raw order) -> frag layout ----
    {
        int r = tid >> 1, half = tid & 1;
        int ri = srows[r];
        const uint32_t* src = (half ? qpl : qph) + ((size_t)(b * SS + ri) * 16 + h) * 32;
        uint32_t* dst = sQw + half * 4096;
        int wd = r >> 4, g2 = r & 15;
        int gidq = g2 & 7, hiRow = g2 >> 3;
#pragma unroll
        for (int w32 = 0; w32 < 32; w32++) {
            int ks = w32 >> 3, rem = w32 & 7;
            int tg2 = rem & 3, comp = ((rem >> 2) << 1) | hiRow;
            dst[(((wd * 8 + gidq) * 4 + ks) * 4 + tg2) * 4 + comp] = src[w32];
        }
    }
    __syncthreads();

    int kbStart = sminlo >> 6;
    int kbEnd = (smaxhi >> 6) + 1;

    int i0 = srows[w * 16 + gid], i1 = srows[w * 16 + gid + 8];
    bool isl0 = gates[b * SS + i0] <= 0.5f;
    bool isl1 = gates[b * SS + i1] <= 0.5f;

    float m0 = -1e30f, m1 = -1e30f, l0s = 0.f, l1s = 0.f;
    float o[8][4];
#pragma unroll
    for (int nt = 0; nt < 8; nt++)
#pragma unroll
        for (int c = 0; c < 4; c++) o[nt][c] = 0.f;

    const uint4* kbase = kp + ((size_t)kvh * MM + b * SS) * 16;
    const uint4* vbase = vp + (size_t)(b * RHH + kvh) * 64 * 512;
    int fj = tid >> 2, fq = (tid & 3) * 4;

    {
        const uint4* gk = kbase + ((size_t)(kbStart * 64 + fj)) * 16 + fq;
        const uint4* gv = vbase + (size_t)fj * 512 + kbStart * 16 + fq;
        uint32_t dk = smb + (2048 + fj * 20 + fq) * 16;
        uint32_t dv = smb + (4608 + fj * 20 + fq) * 16;
#pragma unroll
        for (int c = 0; c < 4; c++) { cpa16(dk + c * 16, gk + c); cpa16(dv + c * 16, gv + c); }
        CPA_COMMIT();
    }

    for (int kb = kbStart; kb < kbEnd; kb++) {
        int buf = (kb - kbStart) & 1;
        CPA_WAIT(0);
        __syncthreads();

        if (kb + 1 < kbEnd) {
            const uint4* gk = kbase + ((size_t)((kb + 1) * 64 + fj)) * 16 + fq;
            uint32_t dk = smb + (2048 + (buf ^ 1) * 1280 + fj * 20 + fq) * 16;
#pragma unroll
            for (int c = 0; c < 4; c++) cpa16(dk + c * 16, gk + c);
            CPA_COMMIT();
        }

        const uint4* sK = sm4 + 2048 + buf * 1280;
        const uint4* sV = sm4 + 4608;

        // ---- QK^T ----
        float s[8][4];
#pragma unroll
        for (int nt = 0; nt < 8; nt++)
#pragma unroll
            for (int c = 0; c < 4; c++) s[nt][c] = 0.f;

#pragma unroll
        for (int ks = 0; ks < 4; ks++) {
            uint4 qh = sm4[w * 128 + gid * 16 + ks * 4 + tig];
            uint4 ql = sm4[1024 + w * 128 + gid * 16 + ks * 4 + tig];
#pragma unroll
            for (int nt = 0; nt < 8; nt++) {
                uint4 kk = sK[(nt * 8 + gid) * 20 + ks * 4 + tig];
                mma_bf16(s[nt], qh.x, qh.y, qh.z, qh.w, kk.x, kk.y);
                mma_bf16(s[nt], qh.x, qh.y, qh.z, qh.w, kk.z, kk.w);
                mma_bf16(s[nt], ql.x, ql.y, ql.z, ql.w, kk.x, kk.y);
            }
        }

        // ---- mask + online softmax ----
        float rm0 = -1e30f, rm1 = -1e30f;
#pragma unroll
        for (int nt = 0; nt < 8; nt++) {
            int jb = kb * 64 + nt * 8 + 2 * tig;
#pragma unroll
            for (int c = 0; c < 2; c++) {
                int j = jb + c;
                bool v0 = isl0 ? (abs(i0 - j) <= 64) : (j <= i0);
                s[nt][c] = v0 ? s[nt][c] : -1e30f;
                rm0 = fmaxf(rm0, s[nt][c]);
                bool v1 = isl1 ? (abs(i1 - j) <= 64) : (j <= i1);
                s[nt][2 + c] = v1 ? s[nt][2 + c] : -1e30f;
                rm1 = fmaxf(rm1, s[nt][2 + c]);
            }
        }
        rm0 = fmaxf(rm0, __shfl_xor_sync(0xffffffffu, rm0, 1));
        rm0 = fmaxf(rm0, __shfl_xor_sync(0xffffffffu, rm0, 2));
        rm1 = fmaxf(rm1, __shfl_xor_sync(0xffffffffu, rm1, 1));
        rm1 = fmaxf(rm1, __shfl_xor_sync(0xffffffffu, rm1, 2));

        float mn0 = fmaxf(m0, rm0), mn1 = fmaxf(m1, rm1);
        float al0f = __expf(fmaxf(m0 - mn0, -80.f));
        float al1f = __expf(fmaxf(m1 - mn1, -80.f));
        float rs0 = 0.f, rs1 = 0.f;
#pragma unroll
        for (int nt = 0; nt < 8; nt++) {
#pragma unroll
            for (int c = 0; c < 2; c++) {
                float p0 = __expf(fmaxf(s[nt][c] - mn0, -80.f));
                s[nt][c] = p0; rs0 += p0;
                float p1 = __expf(fmaxf(s[nt][2 + c] - mn1, -80.f));
                s[nt][2 + c] = p1; rs1 += p1;
            }
        }
        rs0 += __shfl_xor_sync(0xffffffffu, rs0, 1);
        rs0 += __shfl_xor_sync(0xffffffffu, rs0, 2);
        rs1 += __shfl_xor_sync(0xffffffffu, rs1, 1);
        rs1 += __shfl_xor_sync(0xffffffffu, rs1, 2);
        m0 = mn0; m1 = mn1;
        l0s = l0s * al0f + rs0;
        l1s = l1s * al1f + rs1;
#pragma unroll
        for (int nt = 0; nt < 8; nt++) {
            o[nt][0] *= al0f; o[nt][1] *= al0f;
            o[nt][2] *= al1f; o[nt][3] *= al1f;
        }

        // ---- PV (P from registers, single V buffer) ----
#pragma unroll
        for (int ks = 0; ks < 4; ks++) {
            uint32_t ah0, al0, ah1, al1, ah2, al2, ah3, al3;
            bf16_split2(s[2 * ks][0],     s[2 * ks][1],     ah0, al0);
            bf16_split2(s[2 * ks][2],     s[2 * ks][3],     ah1, al1);
            bf16_split2(s[2 * ks + 1][0], s[2 * ks + 1][1], ah2, al2);
            bf16_split2(s[2 * ks + 1][2], s[2 * ks + 1][3], ah3, al3);
#pragma unroll
            for (int nt = 0; nt < 8; nt++) {
                uint4 vv = sV[(nt * 8 + gid) * 20 + ks * 4 + tig];
                mma_bf16(o[nt], ah0, ah1, ah2, ah3, vv.x, vv.y);
                mma_bf16(o[nt], ah0, ah1, ah2, ah3, vv.z, vv.w);
                mma_bf16(o[nt], al0, al1, al2, al3, vv.x, vv.y);
            }
        }
        __syncthreads();

        if (kb + 1 < kbEnd) {
            const uint4* gv = vbase + (size_t)fj * 512 + (kb + 1) * 16 + fq;
            uint32_t dv = smb + (4608 + fj * 20 + fq) * 16;
#pragma unroll
            for (int c = 0; c < 4; c++) cpa16(dv + c * 16, gv + c);
            CPA_COMMIT();
        }
    }

    // ---- epilogue: permuted word positions (for O-gemm LDS.64 pairs) --------
    float inv0 = (l0s > 0.f) ? 1.f / l0s : 0.f;
    float inv1 = (l1s > 0.f) ? 1.f / l1s : 0.f;
    size_t base0 = ((size_t)(b * SS + i0) * 16 + h) * 32 + tig * 2;
    size_t base1 = ((size_t)(b * SS + i1) * 16 + h) * 32 + tig * 2;
#pragma unroll
    for (int nt = 0; nt < 8; nt++) {
        int off = (nt >> 1) * 8 + (nt & 1);
        uint32_t h0, l0, h1, l1;
        bf16_split2(o[nt][0] * inv0, o[nt][1] * inv0, h0, l0);
        bf16_split2(o[nt][2] * inv1, o[nt][3] * inv1, h1, l1);
        oh[base0 + off] = h0; ol[base0 + off] = l0;
        oh[base1 + off] = h1; ol[base1 + off] = l1;
    }
}

// ---------------- gate: LN + dot(wg) + sigmoid(clamp) -----------------------
__global__ void gate_kernel(const float* __restrict__ x,
                            const float* __restrict__ wg,
                            const float* __restrict__ bg,
                            const float* __restrict__ gamma,
                            const float* __restrict__ beta,
                            float* __restrict__ gates) {
    int token = blockIdx.x;
    const float* row = x + (size_t)token * HH;
    __shared__ float red[256];
    int tid = threadIdx.x;

    float xr[4];
#pragma unroll
    for (int i = 0; i < 4; i++) xr[i] = row[tid + i * 256];

    float s = xr[0] + xr[1] + xr[2] + xr[3];
    red[tid] = s; __syncthreads();
    for (int o = 128; o > 0; o >>= 1) { if (tid < o) red[tid] += red[tid + o]; __syncthreads(); }
    float mu = red[0] * (1.0f / HH);
    __syncthreads();

    float v = 0.f;
#pragma unroll
    for (int i = 0; i < 4; i++) { float d = xr[i] - mu; v = fmaf(d, d, v); }
    red[tid] = v; __syncthreads();
    for (int o = 128; o > 0; o >>= 1) { if (tid < o) red[tid] += red[tid + o]; __syncthreads(); }
    float rstd = rsqrtf(red[0] * (1.0f / HH) + 1e-5f);
    __syncthreads();

    float dot = 0.f;
#pragma unroll
    for (int i = 0; i < 4; i++) {
        int hh = tid + i * 256;
        float y = fmaf((xr[i] - mu) * rstd, gamma[hh], beta[hh]);
        dot = fmaf(y, wg[hh], dot);
    }
    red[tid] = dot; __syncthreads();
    for (int o = 128; o > 0; o >>= 1) { if (tid < o) red[tid] += red[tid + o]; __syncthreads(); }
    if (tid == 0) {
        float z = red[0] + bg[0];
        z = fminf(10.f, fmaxf(-10.f, z));
        gates[token] = 1.f / (1.f + expf(-z));
    }
}

// ---------------- gate regularization loss ------------------------------------
__global__ void regloss_kernel(const float* __restrict__ gates, float* __restrict__ out,
                               int writeIdx) {
    __shared__ float red[256];
    int tid = threadIdx.x;
    float acc = 0.f;
    for (int t = tid; t < MM; t += 256) {
        float g = gates[t];
        float gs = fminf(fmaxf(g, 1e-5f), 1.f - 1e-5f);
        float binary = g * (1.f - g);
        float ent = g * logf(gs) + (1.f - g) * logf(1.f - gs);
        acc += 0.1f * binary - 0.01f * ent + 0.1f * g;
    }
    red[tid] = acc; __syncthreads();
    for (int o = 128; o > 0; o >>= 1) { if (tid < o) red[tid] += red[tid + o]; __syncthreads(); }
    if (tid == 0) out[writeIdx] = red[0] * (1.0f / MM);
}

// ---------------- launch ------------------------------------------------------
extern "C" void kernel_launch(void* const* d_in, const int* in_sizes, int n_in,
                              void* d_out, int out_size) {
    const float* x     = (const float*)d_in[0];
    const float* Wq    = (const float*)d_in[1];
    const float* Wk    = (const float*)d_in[2];
    const float* Wv    = (const float*)d_in[3];
    const float* Wo    = (const float*)d_in[4];
    const float* Wg    = (const float*)d_in[5];
    const float* bg    = (const float*)d_in[6];
    const float* gamma = (const float*)d_in[7];
    const float* beta  = (const float*)d_in[8];
    float* out = (float*)d_out;

    float *pGates;
    uint32_t *pXh, *pXl, *pWqh, *pWql, *pWkh, *pWkl, *pWvh, *pWvl, *pWoh, *pWol;
    uint32_t *pQh, *pQl, *pKp, *pOh, *pOl;
    uint4 *pVp;
    int *pOrder;
    cudaGetSymbolAddress((void**)&pGates, g_gates);
    cudaGetSymbolAddress((void**)&pOrder, g_order);
    cudaGetSymbolAddress((void**)&pXh,    g_xh);
    cudaGetSymbolAddress((void**)&pXl,    g_xl);
    cudaGetSymbolAddress((void**)&pWqh,   g_wqh);
    cudaGetSymbolAddress((void**)&pWql,   g_wql);
    cudaGetSymbolAddress((void**)&pWkh,   g_wkh);
    cudaGetSymbolAddress((void**)&pWkl,   g_wkl);
    cudaGetSymbolAddress((void**)&pWvh,   g_wvh);
    cudaGetSymbolAddress((void**)&pWvl,   g_wvl);
    cudaGetSymbolAddress((void**)&pWoh,   g_woh);
    cudaGetSymbolAddress((void**)&pWol,   g_wol);
    cudaGetSymbolAddress((void**)&pQh,    g_qph);
    cudaGetSymbolAddress((void**)&pQl,    g_qpl);
    cudaGetSymbolAddress((void**)&pKp,    g_kp);
    cudaGetSymbolAddress((void**)&pVp,    g_vp);
    cudaGetSymbolAddress((void**)&pOh,    g_oh);
    cudaGetSymbolAddress((void**)&pOl,    g_ol);

    cudaFuncSetAttribute(gemm_mma, cudaFuncAttributeMaxDynamicSharedMemorySize, GM_SMEM);
    cudaFuncSetAttribute(gemm_mma_kv, cudaFuncAttributeMaxDynamicSharedMemorySize, GM_SMEM);
    cudaFuncSetAttribute(attn_mma, cudaFuncAttributeMaxDynamicSharedMemorySize, AT_SMEM);

    gate_kernel<<<MM, 256>>>(x, Wg, bg, gamma, beta, pGates);
    build_order<<<BB, 256>>>(pGates, pOrder);

    split_all<<<1024, 256>>>(x, Wq, Wk, Wv, Wo,
                             pXh, pXl, pWqh, pWql, pWkh, pWkl, pWvh, pWvl, pWoh, pWol);

    gemm_mma<<<dim3(HH / 128, MM / 128), 256, GM_SMEM>>>(
        pXh, pXl, pWqh, pWql, nullptr, pQh, pQl, HH, KW, 1);
    gemm_mma_kv<<<dim3((RHH * HDD) / 128, MM / 128, 2), 256, GM_SMEM>>>(
        pXh, pXl, pWkh, pWkl, pWvh, pWvl, pKp, pVp, RHH * HDD, KW);

    attn_mma<<<dim3(SS / 128, NHD, BB), 256, AT_SMEM>>>(
        pQh, pQl, (const uint4*)pKp, pVp, pGates, pOrder, pOh, pOl);

    gemm_mma<<<dim3(HH / 128, MM / 128), 256, GM_SMEM>>>(
        pOh, pOl, pWoh, pWol, out, nullptr, nullptr, HH, KW, 0);

    if (out_size > MM * HH)
        regloss_kernel<<<1, 256>>>(pGates, out, MM * HH);
}

// round 14
// speedup vs baseline: 3.8231x; 1.0263x over previous
#include <cuda_runtime.h>
#include <cuda_bf16.h>
#include <math.h>
#include <stdint.h>

// Problem constants
#define BB  2
#define SS  2048
#define HH  1024
#define NHD 16      // num heads
#define HDD 64      // head dim
#define RHH 4       // kv heads
#define MM  (BB*SS) // 4096 token rows
#define KW  (HH/2)  // 512 hi-words per row (bf16x2); merged row = 2*KW words

// word counts per tensor (hi-words, for merged split kernel)
#define XW  (MM*KW)
#define WQW (HH*KW)
#define WKW ((RHH*HDD)*KW)
#define TOTW (XW + WQW + 2*WKW + WQW)

// ---------------- scratch (static device memory; no allocs allowed) ----------
__device__ float    g_gates[MM];
__device__ int      g_order[MM];
__device__ uint32_t g_x [(size_t)MM * 2 * KW];          // x merged hi/lo interleaved
__device__ uint32_t g_wq[(size_t)HH * 2 * KW];
__device__ uint32_t g_wk[(size_t)(RHH*HDD) * 2 * KW];
__device__ uint32_t g_wv[(size_t)(RHH*HDD) * 2 * KW];
__device__ uint32_t g_wo[(size_t)HH * 2 * KW];
__device__ uint32_t g_qph[(size_t)MM * 512];            // Q row-packed bf16 hi (raw order)
__device__ uint32_t g_qpl[(size_t)MM * 512];
__device__ uint32_t g_kp [(size_t)RHH * MM * 64];       // K frag-packed (hi+lo interleaved u4)
__device__ uint4    g_vp [(size_t)BB * RHH * HDD * 512];// V transposed frag-packed
__device__ uint32_t g_o  [(size_t)MM * 1024];           // attn out merged hi/lo interleaved

// ---------------- bf16 helpers ----------------------------------------------
__device__ __forceinline__ uint32_t pack_bf16(float lowElem, float highElem) {
    uint32_t r;
    asm("cvt.rn.bf16x2.f32 %0, %1, %2;" : "=r"(r) : "f"(highElem), "f"(lowElem));
    return r;
}
__device__ __forceinline__ float bf16_round(float x) {
    return __bfloat162float(__float2bfloat16(x));
}
__device__ __forceinline__ void bf16_split2(float a, float b, uint32_t& hi, uint32_t& lo) {
    hi = pack_bf16(a, b);
    lo = pack_bf16(a - bf16_round(a), b - bf16_round(b));
}
__device__ __forceinline__ void mma_bf16(float* c, uint32_t a0, uint32_t a1, uint32_t a2,
                                         uint32_t a3, uint32_t b0, uint32_t b1) {
    asm volatile(
        "mma.sync.aligned.m16n8k16.row.col.f32.bf16.bf16.f32 "
        "{%0,%1,%2,%3}, {%4,%5,%6,%7}, {%8,%9}, {%0,%1,%2,%3};"
        : "+f"(c[0]), "+f"(c[1]), "+f"(c[2]), "+f"(c[3])
        : "r"(a0), "r"(a1), "r"(a2), "r"(a3), "r"(b0), "r"(b1));
}
__device__ __forceinline__ uint32_t smem_u32(const void* p) {
    uint32_t a;
    asm("{ .reg .u64 t; cvta.to.shared.u64 t, %1; cvt.u32.u64 %0, t; }" : "=r"(a) : "l"(p));
    return a;
}
__device__ __forceinline__ void cpa16(uint32_t dst, const void* src) {
    asm volatile("cp.async.ca.shared.global [%0], [%1], 16;" :: "r"(dst), "l"(src));
}
#define CPA_COMMIT() asm volatile("cp.async.commit_group;" ::: "memory")
#define CPA_WAIT(n)  asm volatile("cp.async.wait_group %0;" :: "n"(n) : "memory")

// ---------------- merged fp32 -> interleaved hi/lo split ---------------------
// Per 8-hi-word group -> 16 merged words: for t = local&7 (tig=t&3, half=t>>2):
//   hi at group*16 + tig*4 + half,  lo at group*16 + tig*4 + 2 + half.
// So each 16B u4 [tig*4 .. tig*4+3] = (h(tig), h(tig+4), l(tig), l(tig+4)).
__global__ __launch_bounds__(256)
void split_all(const float* __restrict__ x,  const float* __restrict__ Wq,
               const float* __restrict__ Wk, const float* __restrict__ Wv,
               const float* __restrict__ Wo,
               uint32_t* __restrict__ xo,  uint32_t* __restrict__ wqo,
               uint32_t* __restrict__ wko, uint32_t* __restrict__ wvo,
               uint32_t* __restrict__ woo) {
    for (int i = blockIdx.x * 256 + threadIdx.x; i < TOTW; i += gridDim.x * 256) {
        const float* src; uint32_t* dst; int local;
        if (i < XW)                      { src = x;  dst = xo;  local = i; }
        else if (i < XW + WQW)           { src = Wq; dst = wqo; local = i - XW; }
        else if (i < XW + WQW + WKW)     { src = Wk; dst = wko; local = i - XW - WQW; }
        else if (i < XW + WQW + 2*WKW)   { src = Wv; dst = wvo; local = i - XW - WQW - WKW; }
        else                             { src = Wo; dst = woo; local = i - XW - WQW - 2*WKW; }
        float2 v = *(const float2*)(src + 2 * (size_t)local);
        uint32_t h, l;
        bf16_split2(v.x, v.y, h, l);
        int t = local & 7;
        size_t pos = ((size_t)(local >> 3)) * 16 + (t & 3) * 4 + (t >> 2);
        dst[pos] = h; dst[pos + 2] = l;
    }
}

// ==================== tensor-core bf16x3 GEMM (merged interleaved) ===========
// C[M,N] = A[M,K] @ B[N,K]^T, A/B as merged hi/lo interleaved word arrays.
// CTA tile 128x128, BK=32 elems (32 merged words), dbl-buffered cp.async SMEM.
// 8 warps 4(M)x2(N); warp tile 32x64. Pitch PWG=48 words (LDS.128 conflict-free).
// mode 0: fp32 C. mode 1: Q row-packed raw order (scale 1/8) -> outh/outl.
// mode 2: K frag-packed u4 -> outh. mode 3: V transposed frag-packed -> vpout.
#define PWG 48
#define STGW (2 * 128 * PWG)
#define GM_SMEM (2 * STGW * 4)

__device__ __forceinline__ void gemm_body(const uint32_t* __restrict__ A,
                                          const uint32_t* __restrict__ B,
                                          float* __restrict__ C,
                                          uint32_t* __restrict__ outh,
                                          uint32_t* __restrict__ outl,
                                          uint4* __restrict__ vpout,
                                          int N, int Kw, int mode,
                                          int rowBase, int colBase, uint32_t* sm) {
    int tid = threadIdx.x, lane = tid & 31, wid = tid >> 5;
    int gid = lane >> 2, tig = lane & 3;
    int wM = wid >> 1, wN = wid & 1;
    uint32_t smb = smem_u32(sm);

    int lrow = tid >> 1, lh16 = (tid & 1) * 16;
    const uint32_t* pA = A + (size_t)(rowBase + lrow) * (2 * Kw) + lh16;
    const uint32_t* pB = B + (size_t)(colBase + lrow) * (2 * Kw) + lh16;
    uint32_t dstOff = (lrow * PWG + lh16) * 4;  // bytes

    float acc[2][8][4];
#pragma unroll
    for (int mt = 0; mt < 2; mt++)
#pragma unroll
        for (int nt = 0; nt < 8; nt++)
#pragma unroll
            for (int c = 0; c < 4; c++) acc[mt][nt][c] = 0.f;

    const int NST = Kw / 16;   // 32 elems (32 merged words) per stage

    {
        uint32_t dA = smb + dstOff;
        uint32_t dB = dA + 128 * PWG * 4;
#pragma unroll
        for (int c = 0; c < 4; c++) { cpa16(dA + c * 16, pA + c * 4); cpa16(dB + c * 16, pB + c * 4); }
        CPA_COMMIT();
    }

    for (int s = 0; s < NST; s++) {
        int buf = s & 1;
        if (s + 1 < NST) {
            int off = (s + 1) * 32;
            uint32_t dA = smb + (buf ^ 1) * STGW * 4 + dstOff;
            uint32_t dB = dA + 128 * PWG * 4;
#pragma unroll
            for (int c = 0; c < 4; c++) {
                cpa16(dA + c * 16, pA + off + c * 4);
                cpa16(dB + c * 16, pB + off + c * 4);
            }
            CPA_COMMIT();
            CPA_WAIT(1);
        } else {
            CPA_WAIT(0);
        }
        __syncthreads();

        uint32_t* sA = sm + buf * STGW;
        uint32_t* sB = sA + 128 * PWG;

#pragma unroll
        for (int ks = 0; ks < 2; ks++) {
            uint32_t ah[2][4], al[2][4];
#pragma unroll
            for (int mt = 0; mt < 2; mt++) {
                int r0 = (wM * 32 + mt * 16 + gid) * PWG + ks * 16 + tig * 4;
                uint4 q1 = *(const uint4*)(sA + r0);
                uint4 q2 = *(const uint4*)(sA + r0 + 8 * PWG);
                ah[mt][0] = q1.x; ah[mt][1] = q2.x; ah[mt][2] = q1.y; ah[mt][3] = q2.y;
                al[mt][0] = q1.z; al[mt][1] = q2.z; al[mt][2] = q1.w; al[mt][3] = q2.w;
            }
#pragma unroll
            for (int nt = 0; nt < 8; nt++) {
                int n0 = (wN * 64 + nt * 8 + gid) * PWG + ks * 16 + tig * 4;
                uint4 qb = *(const uint4*)(sB + n0);
#pragma unroll
                for (int mt = 0; mt < 2; mt++) {
                    mma_bf16(acc[mt][nt], ah[mt][0], ah[mt][1], ah[mt][2], ah[mt][3], qb.x, qb.y);
                    mma_bf16(acc[mt][nt], ah[mt][0], ah[mt][1], ah[mt][2], ah[mt][3], qb.z, qb.w);
                    mma_bf16(acc[mt][nt], al[mt][0], al[mt][1], al[mt][2], al[mt][3], qb.x, qb.y);
                }
            }
        }
        __syncthreads();
    }

    // ---------------- epilogue ----------------
    if (mode == 0) {
#pragma unroll
        for (int mt = 0; mt < 2; mt++) {
            int r0 = rowBase + wM * 32 + mt * 16 + gid;
#pragma unroll
            for (int nt = 0; nt < 8; nt++) {
                int c0 = colBase + wN * 64 + nt * 8 + 2 * tig;
                *(float2*)(C + (size_t)r0 * N + c0) = make_float2(acc[mt][nt][0], acc[mt][nt][1]);
                *(float2*)(C + (size_t)(r0 + 8) * N + c0) = make_float2(acc[mt][nt][2], acc[mt][nt][3]);
            }
        }
    } else if (mode == 1) {   // Q row-packed raw order, scaled 1/8
#pragma unroll
        for (int mt = 0; mt < 2; mt++) {
            int r0 = rowBase + wM * 32 + mt * 16 + gid;
#pragma unroll
            for (int nt = 0; nt < 8; nt++) {
                int c0 = colBase + wN * 64 + nt * 8 + 2 * tig;
                int hh = c0 >> 6, w32 = (c0 & 63) >> 1;
                uint32_t h0, l0, h1, l1;
                bf16_split2(acc[mt][nt][0] * 0.125f, acc[mt][nt][1] * 0.125f, h0, l0);
                bf16_split2(acc[mt][nt][2] * 0.125f, acc[mt][nt][3] * 0.125f, h1, l1);
                size_t i0 = ((size_t)r0 * 16 + hh) * 32 + w32;
                size_t i1 = ((size_t)(r0 + 8) * 16 + hh) * 32 + w32;
                outh[i0] = h0; outl[i0] = l0;
                outh[i1] = h1; outl[i1] = l1;
            }
        }
    } else if (mode == 2) {   // K frag-packed interleaved
#pragma unroll
        for (int mt = 0; mt < 2; mt++) {
            int r0 = rowBase + wM * 32 + mt * 16 + gid;
#pragma unroll
            for (int nt = 0; nt < 8; nt++) {
                int c0 = colBase + wN * 64 + nt * 8 + 2 * tig;
                int kvh = c0 >> 6, wl = (c0 & 63) >> 1;
                int ks = wl >> 3, tigg = wl & 7;
                int tA = tigg & 3, comp = (tigg & 4) ? 1 : 0;
                size_t wi0 = (((size_t)kvh * MM + r0) * 16 + ks * 4 + tA) * 4;
                size_t wi1 = wi0 + 8 * 16 * 4;
                uint32_t h0, l0, h1, l1;
                bf16_split2(acc[mt][nt][0], acc[mt][nt][1], h0, l0);
                bf16_split2(acc[mt][nt][2], acc[mt][nt][3], h1, l1);
                outh[wi0 + comp] = h0; outh[wi0 + comp + 2] = l0;
                outh[wi1 + comp] = h1; outh[wi1 + comp + 2] = l1;
            }
        }
    } else {                  // mode 3: V transposed frag-packed (shfl pair exchange)
#pragma unroll
        for (int mt = 0; mt < 2; mt++) {
            int r = wM * 32 + mt * 16 + gid;
            int tok = rowBase + r;
            int b = tok / SS;
            int j64 = tok % SS;
            int kb = j64 >> 6;
            int j = j64 & 63;
            int ks = j >> 4, tg = (j >> 1) & 3;
            bool even = (gid & 1) == 0;
#pragma unroll
            for (int nt = 0; nt < 8; nt++) {
                int c0 = colBase + wN * 64 + nt * 8 + 2 * tig;
                float p0 = __shfl_xor_sync(0xffffffffu, acc[mt][nt][0], 4);
                float p1 = __shfl_xor_sync(0xffffffffu, acc[mt][nt][1], 4);
                float p2 = __shfl_xor_sync(0xffffffffu, acc[mt][nt][2], 4);
                float p3 = __shfl_xor_sync(0xffffffffu, acc[mt][nt][3], 4);
                float v0, v1, v2, v3; int d;
                if (even) { d = c0;     v0 = acc[mt][nt][0]; v1 = p0; v2 = acc[mt][nt][2]; v3 = p2; }
                else      { d = c0 + 1; v0 = p1; v1 = acc[mt][nt][1]; v2 = p3; v3 = acc[mt][nt][3]; }
                int kvh = d >> 6, dd = d & 63;
                uint32_t hx, lx, hy, ly;
                bf16_split2(v0, v1, hx, lx);
                bf16_split2(v2, v3, hy, ly);
                vpout[((size_t)(b * RHH + kvh) * 64 + dd) * 512 + kb * 16 + ks * 4 + tg] =
                    make_uint4(hx, hy, lx, ly);
            }
        }
    }
}

__global__ __launch_bounds__(256, 2)
void gemm_mma(const uint32_t* __restrict__ A, const uint32_t* __restrict__ B,
              float* __restrict__ C, uint32_t* __restrict__ outh,
              uint32_t* __restrict__ outl, int N, int Kw, int mode) {
    extern __shared__ uint32_t smg[];
    gemm_body(A, B, C, outh, outl, nullptr, N, Kw, mode,
              blockIdx.y * 128, blockIdx.x * 128, smg);
}

// fused K+V projection: z=0 -> K frag-packed, z=1 -> V frag-packed
__global__ __launch_bounds__(256, 2)
void gemm_mma_kv(const uint32_t* __restrict__ xm,
                 const uint32_t* __restrict__ wkm, const uint32_t* __restrict__ wvm,
                 uint32_t* __restrict__ kp, uint4* __restrict__ vpout, int N, int Kw) {
    extern __shared__ uint32_t smg[];
    if (blockIdx.z)
        gemm_body(xm, wvm, nullptr, nullptr, nullptr, vpout, N, Kw, 3,
                  blockIdx.y * 128, blockIdx.x * 128, smg);
    else
        gemm_body(xm, wkm, nullptr, kp, nullptr, nullptr, N, Kw, 2,
                  blockIdx.y * 128, blockIdx.x * 128, smg);
}

// ---------------- build compacted row order: [causal asc | local asc] --------
__global__ __launch_bounds__(256)
void build_order(const float* __restrict__ gates, int* __restrict__ order) {
    int b = blockIdx.x, tid = threadIdx.x;
    __shared__ int cnt[256];
    bool loc[8];
    int c = 0;
#pragma unroll
    for (int i = 0; i < 8; i++) {
        loc[i] = gates[b * SS + tid * 8 + i] <= 0.5f;
        if (!loc[i]) c++;
    }
    cnt[tid] = c;
    __syncthreads();
    for (int off = 1; off < 256; off <<= 1) {
        int add = (tid >= off) ? cnt[tid - off] : 0;
        __syncthreads();
        cnt[tid] += add;
        __syncthreads();
    }
    int nC = cnt[255];
    int cb = cnt[tid] - c;
    int lb = nC + (tid * 8 - cb);
#pragma unroll
    for (int i = 0; i < 8; i++) {
        if (loc[i]) order[b * SS + lb++] = tid * 8 + i;
        else        order[b * SS + cb++] = tid * 8 + i;
    }
}

// ==================== mma flash attention (compacted rows) ===================
// CTA: 256 thr = 8 warps, 128 compacted q-rows. K dbl-buffered, V single.
// SMEM (uint4): Q hi [0,1024) lo [1024,2048); K buf{0,1} @2048+buf*1280; V @4608.
#define AT_SMEM (5888 * 16)

__global__ __launch_bounds__(256, 2)
void attn_mma(const uint32_t* __restrict__ qph, const uint32_t* __restrict__ qpl,
              const uint4* __restrict__ kp,  const uint4* __restrict__ vp,
              const float* __restrict__ gates, const int* __restrict__ order,
              uint32_t* __restrict__ go) {
    extern __shared__ uint4 sm4[];
    __shared__ int srows[128];
    __shared__ int sminlo, smaxhi;
    uint32_t smb = smem_u32(sm4);
    uint32_t* sQw = (uint32_t*)sm4;

    int t = blockIdx.x, h = blockIdx.y, b = blockIdx.z;
    int tid = threadIdx.x, lane = tid & 31, w = tid >> 5;
    int gid = lane >> 2, tig = lane & 3;
    int kvh = h & 3;

    if (tid == 0) { sminlo = SS; smaxhi = 0; }
    if (tid < 128) srows[tid] = order[b * SS + t * 128 + tid];
    __syncthreads();
    if (tid < 128) {
        int myi = srows[tid];
        bool isl = gates[b * SS + myi] <= 0.5f;
        int lo = isl ? max(0, myi - 64) : 0;
        int hi = isl ? min(SS - 1, myi + 64) : myi;
        atomicMin(&sminlo, lo);
        atomicMax(&smaxhi, hi);
    }

    // ---- Q gather: row-major packed (raw order) -> frag layout ----
    {
        int r = tid >> 1, half = tid & 1;
        int ri = srows[r];
        const uint32_t* src = (half ? qpl : qph) + ((size_t)(b * SS + ri) * 16 + h) * 32;
        uint32_t* dst = sQw + half * 4096;
        int wd = r >> 4, g2 = r & 15;
        int gidq = g2 & 7, hiRow = g2 >> 3;
#pragma unroll
        for (int w32 = 0; w32 < 32; w32++) {
            int ks = w32 >> 3, rem = w32 & 7;
            int tg2 = rem & 3, comp = ((rem >> 2) << 1) | hiRow;
            dst[(((wd * 8 + gidq) * 4 + ks) * 4 + tg2) * 4 + comp] = src[w32];
        }
    }
    __syncthreads();

    int kbStart = sminlo >> 6;
    int kbEnd = (smaxhi >> 6) + 1;

    int i0 = srows[w * 16 + gid], i1 = srows[w * 16 + gid + 8];
    bool isl0 = gates[b * SS + i0] <= 0.5f;
    bool isl1 = gates[b * SS + i1] <= 0.5f;

    float m0 = -1e30f, m1 = -1e30f, l0s = 0.f, l1s = 0.f;
    float o[8][4];
#pragma unroll
    for (int nt = 0; nt < 8; nt++)
#pragma unroll
        for (int c = 0; c < 4; c++) o[nt][c] = 0.f;

    const uint4* kbase = kp + ((size_t)kvh * MM + b * SS) * 16;
    const uint4* vbase = vp + (size_t)(b * RHH + kvh) * 64 * 512;
    int fj = tid >> 2, fq = (tid & 3) * 4;

    {
        const uint4* gk = kbase + ((size_t)(kbStart * 64 + fj)) * 16 + fq;
        const uint4* gv = vbase + (size_t)fj * 512 + kbStart * 16 + fq;
        uint32_t dk = smb + (2048 + fj * 20 + fq) * 16;
        uint32_t dv = smb + (4608 + fj * 20 + fq) * 16;
#pragma unroll
        for (int c = 0; c < 4; c++) { cpa16(dk + c * 16, gk + c); cpa16(dv + c * 16, gv + c); }
        CPA_COMMIT();
    }

    for (int kb = kbStart; kb < kbEnd; kb++) {
        int buf = (kb - kbStart) & 1;
        CPA_WAIT(0);
        __syncthreads();

        if (kb + 1 < kbEnd) {
            const uint4* gk = kbase + ((size_t)((kb + 1) * 64 + fj)) * 16 + fq;
            uint32_t dk = smb + (2048 + (buf ^ 1) * 1280 + fj * 20 + fq) * 16;
#pragma unroll
            for (int c = 0; c < 4; c++) cpa16(dk + c * 16, gk + c);
            CPA_COMMIT();
        }

        const uint4* sK = sm4 + 2048 + buf * 1280;
        const uint4* sV = sm4 + 4608;

        // ---- QK^T ----
        float s[8][4];
#pragma unroll
        for (int nt = 0; nt < 8; nt++)
#pragma unroll
            for (int c = 0; c < 4; c++) s[nt][c] = 0.f;

#pragma unroll
        for (int ks = 0; ks < 4; ks++) {
            uint4 qh = sm4[w * 128 + gid * 16 + ks * 4 + tig];
            uint4 ql = sm4[1024 + w * 128 + gid * 16 + ks * 4 + tig];
#pragma unroll
            for (int nt = 0; nt < 8; nt++) {
                uint4 kk = sK[(nt * 8 + gid) * 20 + ks * 4 + tig];
                mma_bf16(s[nt], qh.x, qh.y, qh.z, qh.w, kk.x, kk.y);
                mma_bf16(s[nt], qh.x, qh.y, qh.z, qh.w, kk.z, kk.w);
                mma_bf16(s[nt], ql.x, ql.y, ql.z, ql.w, kk.x, kk.y);
            }
        }

        // ---- mask + online softmax ----
        float rm0 = -1e30f, rm1 = -1e30f;
#pragma unroll
        for (int nt = 0; nt < 8; nt++) {
            int jb = kb * 64 + nt * 8 + 2 * tig;
#pragma unroll
            for (int c = 0; c < 2; c++) {
                int j = jb + c;
                bool v0 = isl0 ? (abs(i0 - j) <= 64) : (j <= i0);
                s[nt][c] = v0 ? s[nt][c] : -1e30f;
                rm0 = fmaxf(rm0, s[nt][c]);
                bool v1 = isl1 ? (abs(i1 - j) <= 64) : (j <= i1);
                s[nt][2 + c] = v1 ? s[nt][2 + c] : -1e30f;
                rm1 = fmaxf(rm1, s[nt][2 + c]);
            }
        }
        rm0 = fmaxf(rm0, __shfl_xor_sync(0xffffffffu, rm0, 1));
        rm0 = fmaxf(rm0, __shfl_xor_sync(0xffffffffu, rm0, 2));
        rm1 = fmaxf(rm1, __shfl_xor_sync(0xffffffffu, rm1, 1));
        rm1 = fmaxf(rm1, __shfl_xor_sync(0xffffffffu, rm1, 2));

        float mn0 = fmaxf(m0, rm0), mn1 = fmaxf(m1, rm1);
        float al0f = __expf(fmaxf(m0 - mn0, -80.f));
        float al1f = __expf(fmaxf(m1 - mn1, -80.f));
        float rs0 = 0.f, rs1 = 0.f;
#pragma unroll
        for (int nt = 0; nt < 8; nt++) {
#pragma unroll
            for (int c = 0; c < 2; c++) {
                float p0 = __expf(fmaxf(s[nt][c] - mn0, -80.f));
                s[nt][c] = p0; rs0 += p0;
                float p1 = __expf(fmaxf(s[nt][2 + c] - mn1, -80.f));
                s[nt][2 + c] = p1; rs1 += p1;
            }
        }
        rs0 += __shfl_xor_sync(0xffffffffu, rs0, 1);
        rs0 += __shfl_xor_sync(0xffffffffu, rs0, 2);
        rs1 += __shfl_xor_sync(0xffffffffu, rs1, 1);
        rs1 += __shfl_xor_sync(0xffffffffu, rs1, 2);
        m0 = mn0; m1 = mn1;
        l0s = l0s * al0f + rs0;
        l1s = l1s * al1f + rs1;
#pragma unroll
        for (int nt = 0; nt < 8; nt++) {
            o[nt][0] *= al0f; o[nt][1] *= al0f;
            o[nt][2] *= al1f; o[nt][3] *= al1f;
        }

        // ---- PV (P from registers, single V buffer) ----
#pragma unroll
        for (int ks = 0; ks < 4; ks++) {
            uint32_t ah0, al0, ah1, al1, ah2, al2, ah3, al3;
            bf16_split2(s[2 * ks][0],     s[2 * ks][1],     ah0, al0);
            bf16_split2(s[2 * ks][2],     s[2 * ks][3],     ah1, al1);
            bf16_split2(s[2 * ks + 1][0], s[2 * ks + 1][1], ah2, al2);
            bf16_split2(s[2 * ks + 1][2], s[2 * ks + 1][3], ah3, al3);
#pragma unroll
            for (int nt = 0; nt < 8; nt++) {
                uint4 vv = sV[(nt * 8 + gid) * 20 + ks * 4 + tig];
                mma_bf16(o[nt], ah0, ah1, ah2, ah3, vv.x, vv.y);
                mma_bf16(o[nt], ah0, ah1, ah2, ah3, vv.z, vv.w);
                mma_bf16(o[nt], al0, al1, al2, al3, vv.x, vv.y);
            }
        }
        __syncthreads();

        if (kb + 1 < kbEnd) {
            const uint4* gv = vbase + (size_t)fj * 512 + (kb + 1) * 16 + fq;
            uint32_t dv = smb + (4608 + fj * 20 + fq) * 16;
#pragma unroll
            for (int c = 0; c < 4; c++) cpa16(dv + c * 16, gv + c);
            CPA_COMMIT();
        }
    }

    // ---- epilogue: merged interleaved positions (for O-gemm uint4 frags) ----
    float inv0 = (l0s > 0.f) ? 1.f / l0s : 0.f;
    float inv1 = (l1s > 0.f) ? 1.f / l1s : 0.f;
    size_t base0 = (size_t)(b * SS + i0) * 1024 + h * 64;
    size_t base1 = (size_t)(b * SS + i1) * 1024 + h * 64;
#pragma unroll
    for (int nt = 0; nt < 8; nt++) {
        int pos = (nt >> 1) * 16 + tig * 4 + (nt & 1);
        uint32_t h0, l0, h1, l1;
        bf16_split2(o[nt][0] * inv0, o[nt][1] * inv0, h0, l0);
        bf16_split2(o[nt][2] * inv1, o[nt][3] * inv1, h1, l1);
        go[base0 + pos] = h0; go[base0 + pos + 2] = l0;
        go[base1 + pos] = h1; go[base1 + pos + 2] = l1;
    }
}

// ---------------- gate: LN + dot(wg) + sigmoid(clamp) -----------------------
__global__ void gate_kernel(const float* __restrict__ x,
                            const float* __restrict__ wg,
                            const float* __restrict__ bg,
                            const float* __restrict__ gamma,
                            const float* __restrict__ beta,
                            float* __restrict__ gates) {
    int token = blockIdx.x;
    const float* row = x + (size_t)token * HH;
    __shared__ float red[256];
    int tid = threadIdx.x;

    float xr[4];
#pragma unroll
    for (int i = 0; i < 4; i++) xr[i] = row[tid + i * 256];

    float s = xr[0] + xr[1] + xr[2] + xr[3];
    red[tid] = s; __syncthreads();
    for (int o = 128; o > 0; o >>= 1) { if (tid < o) red[tid] += red[tid + o]; __syncthreads(); }
    float mu = red[0] * (1.0f / HH);
    __syncthreads();

    float v = 0.f;
#pragma unroll
    for (int i = 0; i < 4; i++) { float d = xr[i] - mu; v = fmaf(d, d, v); }
    red[tid] = v; __syncthreads();
    for (int o = 128; o > 0; o >>= 1) { if (tid < o) red[tid] += red[tid + o]; __syncthreads(); }
    float rstd = rsqrtf(red[0] * (1.0f / HH) + 1e-5f);
    __syncthreads();

    float dot = 0.f;
#pragma unroll
    for (int i = 0; i < 4; i++) {
        int hh = tid + i * 256;
        float y = fmaf((xr[i] - mu) * rstd, gamma[hh], beta[hh]);
        dot = fmaf(y, wg[hh], dot);
    }
    red[tid] = dot; __syncthreads();
    for (int o = 128; o > 0; o >>= 1) { if (tid < o) red[tid] += red[tid + o]; __syncthreads(); }
    if (tid == 0) {
        float z = red[0] + bg[0];
        z = fminf(10.f, fmaxf(-10.f, z));
        gates[token] = 1.f / (1.f + expf(-z));
    }
}

// ---------------- gate regularization loss ------------------------------------
__global__ void regloss_kernel(const float* __restrict__ gates, float* __restrict__ out,
                               int writeIdx) {
    __shared__ float red[256];
    int tid = threadIdx.x;
    float acc = 0.f;
    for (int t = tid; t < MM; t += 256) {
        float g = gates[t];
        float gs = fminf(fmaxf(g, 1e-5f), 1.f - 1e-5f);
        float binary = g * (1.f - g);
        float ent = g * logf(gs) + (1.f - g) * logf(1.f - gs);
        acc += 0.1f * binary - 0.01f * ent + 0.1f * g;
    }
    red[tid] = acc; __syncthreads();
    for (int o = 128; o > 0; o >>= 1) { if (tid < o) red[tid] += red[tid + o]; __syncthreads(); }
    if (tid == 0) out[writeIdx] = red[0] * (1.0f / MM);
}

// ---------------- launch ------------------------------------------------------
extern "C" void kernel_launch(void* const* d_in, const int* in_sizes, int n_in,
                              void* d_out, int out_size) {
    const float* x     = (const float*)d_in[0];
    const float* Wq    = (const float*)d_in[1];
    const float* Wk    = (const float*)d_in[2];
    const float* Wv    = (const float*)d_in[3];
    const float* Wo    = (const float*)d_in[4];
    const float* Wg    = (const float*)d_in[5];
    const float* bg    = (const float*)d_in[6];
    const float* gamma = (const float*)d_in[7];
    const float* beta  = (const float*)d_in[8];
    float* out = (float*)d_out;

    float *pGates;
    uint32_t *pX, *pWq, *pWk, *pWv, *pWo;
    uint32_t *pQh, *pQl, *pKp, *pO;
    uint4 *pVp;
    int *pOrder;
    cudaGetSymbolAddress((void**)&pGates, g_gates);
    cudaGetSymbolAddress((void**)&pOrder, g_order);
    cudaGetSymbolAddress((void**)&pX,     g_x);
    cudaGetSymbolAddress((void**)&pWq,    g_wq);
    cudaGetSymbolAddress((void**)&pWk,    g_wk);
    cudaGetSymbolAddress((void**)&pWv,    g_wv);
    cudaGetSymbolAddress((void**)&pWo,    g_wo);
    cudaGetSymbolAddress((void**)&pQh,    g_qph);
    cudaGetSymbolAddress((void**)&pQl,    g_qpl);
    cudaGetSymbolAddress((void**)&pKp,    g_kp);
    cudaGetSymbolAddress((void**)&pVp,    g_vp);
    cudaGetSymbolAddress((void**)&pO,     g_o);

    cudaFuncSetAttribute(gemm_mma, cudaFuncAttributeMaxDynamicSharedMemorySize, GM_SMEM);
    cudaFuncSetAttribute(gemm_mma_kv, cudaFuncAttributeMaxDynamicSharedMemorySize, GM_SMEM);
    cudaFuncSetAttribute(attn_mma, cudaFuncAttributeMaxDynamicSharedMemorySize, AT_SMEM);

    gate_kernel<<<MM, 256>>>(x, Wg, bg, gamma, beta, pGates);
    build_order<<<BB, 256>>>(pGates, pOrder);

    split_all<<<1024, 256>>>(x, Wq, Wk, Wv, Wo, pX, pWq, pWk, pWv, pWo);

    gemm_mma<<<dim3(HH / 128, MM / 128), 256, GM_SMEM>>>(
        pX, pWq, nullptr, pQh, pQl, HH, KW, 1);
    gemm_mma_kv<<<dim3((RHH * HDD) / 128, MM / 128, 2), 256, GM_SMEM>>>(
        pX, pWk, pWv, pKp, pVp, RHH * HDD, KW);

    attn_mma<<<dim3(SS / 128, NHD, BB), 256, AT_SMEM>>>(
        pQh, pQl, (const uint4*)pKp, pVp, pGates, pOrder, pO);

    gemm_mma<<<dim3(HH / 128, MM / 128), 256, GM_SMEM>>>(
        pO, pWo, out, nullptr, nullptr, HH, KW, 0);

    if (out_size > MM * HH)
        regloss_kernel<<<1, 256>>>(pGates, out, MM * HH);
}

// round 15
// speedup vs baseline: 3.8739x; 1.0133x over previous
#include <cuda_runtime.h>
#include <cuda_bf16.h>
#include <math.h>
#include <stdint.h>

// Problem constants
#define BB  2
#define SS  2048
#define HH  1024
#define NHD 16      // num heads
#define HDD 64      // head dim
#define RHH 4       // kv heads
#define MM  (BB*SS) // 4096 token rows
#define KW  (HH/2)  // 512 hi-words per row (bf16x2); merged row = 2*KW words

// word counts per tensor (hi-words, for merged split kernel)
#define XW  (MM*KW)
#define WQW (HH*KW)
#define WKW ((RHH*HDD)*KW)
#define TOTW (XW + WQW + 2*WKW + WQW)

// ---------------- scratch (static device memory; no allocs allowed) ----------
__device__ float    g_gates[MM];
__device__ int      g_order[MM];
__device__ uint32_t g_x [(size_t)MM * 2 * KW];          // x merged hi/lo interleaved
__device__ uint32_t g_wq[(size_t)HH * 2 * KW];
__device__ uint32_t g_wk[(size_t)(RHH*HDD) * 2 * KW];
__device__ uint32_t g_wv[(size_t)(RHH*HDD) * 2 * KW];
__device__ uint32_t g_wo[(size_t)HH * 2 * KW];
__device__ uint32_t g_qph[(size_t)MM * 512];            // Q row-packed bf16 hi (raw order)
__device__ uint32_t g_qpl[(size_t)MM * 512];
__device__ uint32_t g_kp [(size_t)RHH * MM * 64];       // K frag-packed (hi+lo interleaved u4)
__device__ uint4    g_vp [(size_t)BB * RHH * HDD * 512];// V transposed frag-packed
__device__ uint32_t g_o  [(size_t)MM * 1024];           // attn out merged hi/lo interleaved

// ---------------- bf16 helpers ----------------------------------------------
__device__ __forceinline__ uint32_t pack_bf16(float lowElem, float highElem) {
    uint32_t r;
    asm("cvt.rn.bf16x2.f32 %0, %1, %2;" : "=r"(r) : "f"(highElem), "f"(lowElem));
    return r;
}
__device__ __forceinline__ float bf16_round(float x) {
    return __bfloat162float(__float2bfloat16(x));
}
__device__ __forceinline__ void bf16_split2(float a, float b, uint32_t& hi, uint32_t& lo) {
    hi = pack_bf16(a, b);
    lo = pack_bf16(a - bf16_round(a), b - bf16_round(b));
}
__device__ __forceinline__ void mma_bf16(float* c, uint32_t a0, uint32_t a1, uint32_t a2,
                                         uint32_t a3, uint32_t b0, uint32_t b1) {
    asm volatile(
        "mma.sync.aligned.m16n8k16.row.col.f32.bf16.bf16.f32 "
        "{%0,%1,%2,%3}, {%4,%5,%6,%7}, {%8,%9}, {%0,%1,%2,%3};"
        : "+f"(c[0]), "+f"(c[1]), "+f"(c[2]), "+f"(c[3])
        : "r"(a0), "r"(a1), "r"(a2), "r"(a3), "r"(b0), "r"(b1));
}
__device__ __forceinline__ uint32_t smem_u32(const void* p) {
    uint32_t a;
    asm("{ .reg .u64 t; cvta.to.shared.u64 t, %1; cvt.u32.u64 %0, t; }" : "=r"(a) : "l"(p));
    return a;
}
__device__ __forceinline__ void cpa16(uint32_t dst, const void* src) {
    asm volatile("cp.async.ca.shared.global [%0], [%1], 16;" :: "r"(dst), "l"(src));
}
#define CPA_COMMIT() asm volatile("cp.async.commit_group;" ::: "memory")
#define CPA_WAIT(n)  asm volatile("cp.async.wait_group %0;" :: "n"(n) : "memory")

// ---------------- merged fp32 -> interleaved hi/lo split ---------------------
__global__ __launch_bounds__(256)
void split_all(const float* __restrict__ x,  const float* __restrict__ Wq,
               const float* __restrict__ Wk, const float* __restrict__ Wv,
               const float* __restrict__ Wo,
               uint32_t* __restrict__ xo,  uint32_t* __restrict__ wqo,
               uint32_t* __restrict__ wko, uint32_t* __restrict__ wvo,
               uint32_t* __restrict__ woo) {
    for (int i = blockIdx.x * 256 + threadIdx.x; i < TOTW; i += gridDim.x * 256) {
        const float* src; uint32_t* dst; int local;
        if (i < XW)                      { src = x;  dst = xo;  local = i; }
        else if (i < XW + WQW)           { src = Wq; dst = wqo; local = i - XW; }
        else if (i < XW + WQW + WKW)     { src = Wk; dst = wko; local = i - XW - WQW; }
        else if (i < XW + WQW + 2*WKW)   { src = Wv; dst = wvo; local = i - XW - WQW - WKW; }
        else                             { src = Wo; dst = woo; local = i - XW - WQW - 2*WKW; }
        float2 v = *(const float2*)(src + 2 * (size_t)local);
        uint32_t h, l;
        bf16_split2(v.x, v.y, h, l);
        int t = local & 7;
        size_t pos = ((size_t)(local >> 3)) * 16 + (t & 3) * 4 + (t >> 2);
        dst[pos] = h; dst[pos + 2] = l;
    }
}

// ==================== tensor-core bf16x3 GEMM (merged interleaved) ===========
#define PWG 48
#define STGW (2 * 128 * PWG)
#define GM_SMEM (2 * STGW * 4)

__device__ __forceinline__ void gemm_body(const uint32_t* __restrict__ A,
                                          const uint32_t* __restrict__ B,
                                          float* __restrict__ C,
                                          uint32_t* __restrict__ outh,
                                          uint32_t* __restrict__ outl,
                                          uint4* __restrict__ vpout,
                                          int N, int Kw, int mode,
                                          int rowBase, int colBase, uint32_t* sm) {
    int tid = threadIdx.x, lane = tid & 31, wid = tid >> 5;
    int gid = lane >> 2, tig = lane & 3;
    int wM = wid >> 1, wN = wid & 1;
    uint32_t smb = smem_u32(sm);

    int lrow = tid >> 1, lh16 = (tid & 1) * 16;
    const uint32_t* pA = A + (size_t)(rowBase + lrow) * (2 * Kw) + lh16;
    const uint32_t* pB = B + (size_t)(colBase + lrow) * (2 * Kw) + lh16;
    uint32_t dstOff = (lrow * PWG + lh16) * 4;

    float acc[2][8][4];
#pragma unroll
    for (int mt = 0; mt < 2; mt++)
#pragma unroll
        for (int nt = 0; nt < 8; nt++)
#pragma unroll
            for (int c = 0; c < 4; c++) acc[mt][nt][c] = 0.f;

    const int NST = Kw / 16;

    {
        uint32_t dA = smb + dstOff;
        uint32_t dB = dA + 128 * PWG * 4;
#pragma unroll
        for (int c = 0; c < 4; c++) { cpa16(dA + c * 16, pA + c * 4); cpa16(dB + c * 16, pB + c * 4); }
        CPA_COMMIT();
    }

    for (int s = 0; s < NST; s++) {
        int buf = s & 1;
        if (s + 1 < NST) {
            int off = (s + 1) * 32;
            uint32_t dA = smb + (buf ^ 1) * STGW * 4 + dstOff;
            uint32_t dB = dA + 128 * PWG * 4;
#pragma unroll
            for (int c = 0; c < 4; c++) {
                cpa16(dA + c * 16, pA + off + c * 4);
                cpa16(dB + c * 16, pB + off + c * 4);
            }
            CPA_COMMIT();
            CPA_WAIT(1);
        } else {
            CPA_WAIT(0);
        }
        __syncthreads();

        uint32_t* sA = sm + buf * STGW;
        uint32_t* sB = sA + 128 * PWG;

#pragma unroll
        for (int ks = 0; ks < 2; ks++) {
            uint32_t ah[2][4], al[2][4];
#pragma unroll
            for (int mt = 0; mt < 2; mt++) {
                int r0 = (wM * 32 + mt * 16 + gid) * PWG + ks * 16 + tig * 4;
                uint4 q1 = *(const uint4*)(sA + r0);
                uint4 q2 = *(const uint4*)(sA + r0 + 8 * PWG);
                ah[mt][0] = q1.x; ah[mt][1] = q2.x; ah[mt][2] = q1.y; ah[mt][3] = q2.y;
                al[mt][0] = q1.z; al[mt][1] = q2.z; al[mt][2] = q1.w; al[mt][3] = q2.w;
            }
#pragma unroll
            for (int nt = 0; nt < 8; nt++) {
                int n0 = (wN * 64 + nt * 8 + gid) * PWG + ks * 16 + tig * 4;
                uint4 qb = *(const uint4*)(sB + n0);
#pragma unroll
                for (int mt = 0; mt < 2; mt++) {
                    mma_bf16(acc[mt][nt], ah[mt][0], ah[mt][1], ah[mt][2], ah[mt][3], qb.x, qb.y);
                    mma_bf16(acc[mt][nt], ah[mt][0], ah[mt][1], ah[mt][2], ah[mt][3], qb.z, qb.w);
                    mma_bf16(acc[mt][nt], al[mt][0], al[mt][1], al[mt][2], al[mt][3], qb.x, qb.y);
                }
            }
        }
        __syncthreads();
    }

    // ---------------- epilogue ----------------
    if (mode == 0) {
#pragma unroll
        for (int mt = 0; mt < 2; mt++) {
            int r0 = rowBase + wM * 32 + mt * 16 + gid;
#pragma unroll
            for (int nt = 0; nt < 8; nt++) {
                int c0 = colBase + wN * 64 + nt * 8 + 2 * tig;
                *(float2*)(C + (size_t)r0 * N + c0) = make_float2(acc[mt][nt][0], acc[mt][nt][1]);
                *(float2*)(C + (size_t)(r0 + 8) * N + c0) = make_float2(acc[mt][nt][2], acc[mt][nt][3]);
            }
        }
    } else if (mode == 1) {   // Q row-packed raw order, scaled 1/8
#pragma unroll
        for (int mt = 0; mt < 2; mt++) {
            int r0 = rowBase + wM * 32 + mt * 16 + gid;
#pragma unroll
            for (int nt = 0; nt < 8; nt++) {
                int c0 = colBase + wN * 64 + nt * 8 + 2 * tig;
                int hh = c0 >> 6, w32 = (c0 & 63) >> 1;
                uint32_t h0, l0, h1, l1;
                bf16_split2(acc[mt][nt][0] * 0.125f, acc[mt][nt][1] * 0.125f, h0, l0);
                bf16_split2(acc[mt][nt][2] * 0.125f, acc[mt][nt][3] * 0.125f, h1, l1);
                size_t i0 = ((size_t)r0 * 16 + hh) * 32 + w32;
                size_t i1 = ((size_t)(r0 + 8) * 16 + hh) * 32 + w32;
                outh[i0] = h0; outl[i0] = l0;
                outh[i1] = h1; outl[i1] = l1;
            }
        }
    } else if (mode == 2) {   // K frag-packed interleaved
#pragma unroll
        for (int mt = 0; mt < 2; mt++) {
            int r0 = rowBase + wM * 32 + mt * 16 + gid;
#pragma unroll
            for (int nt = 0; nt < 8; nt++) {
                int c0 = colBase + wN * 64 + nt * 8 + 2 * tig;
                int kvh = c0 >> 6, wl = (c0 & 63) >> 1;
                int ks = wl >> 3, tigg = wl & 7;
                int tA = tigg & 3, comp = (tigg & 4) ? 1 : 0;
                size_t wi0 = (((size_t)kvh * MM + r0) * 16 + ks * 4 + tA) * 4;
                size_t wi1 = wi0 + 8 * 16 * 4;
                uint32_t h0, l0, h1, l1;
                bf16_split2(acc[mt][nt][0], acc[mt][nt][1], h0, l0);
                bf16_split2(acc[mt][nt][2], acc[mt][nt][3], h1, l1);
                outh[wi0 + comp] = h0; outh[wi0 + comp + 2] = l0;
                outh[wi1 + comp] = h1; outh[wi1 + comp + 2] = l1;
            }
        }
    } else {                  // mode 3: V transposed frag-packed (shfl pair exchange)
#pragma unroll
        for (int mt = 0; mt < 2; mt++) {
            int r = wM * 32 + mt * 16 + gid;
            int tok = rowBase + r;
            int b = tok / SS;
            int j64 = tok % SS;
            int kb = j64 >> 6;
            int j = j64 & 63;
            int ks = j >> 4, tg = (j >> 1) & 3;
            bool even = (gid & 1) == 0;
#pragma unroll
            for (int nt = 0; nt < 8; nt++) {
                int c0 = colBase + wN * 64 + nt * 8 + 2 * tig;
                float p0 = __shfl_xor_sync(0xffffffffu, acc[mt][nt][0], 4);
                float p1 = __shfl_xor_sync(0xffffffffu, acc[mt][nt][1], 4);
                float p2 = __shfl_xor_sync(0xffffffffu, acc[mt][nt][2], 4);
                float p3 = __shfl_xor_sync(0xffffffffu, acc[mt][nt][3], 4);
                float v0, v1, v2, v3; int d;
                if (even) { d = c0;     v0 = acc[mt][nt][0]; v1 = p0; v2 = acc[mt][nt][2]; v3 = p2; }
                else      { d = c0 + 1; v0 = p1; v1 = acc[mt][nt][1]; v2 = p3; v3 = acc[mt][nt][3]; }
                int kvh = d >> 6, dd = d & 63;
                uint32_t hx, lx, hy, ly;
                bf16_split2(v0, v1, hx, lx);
                bf16_split2(v2, v3, hy, ly);
                vpout[((size_t)(b * RHH + kvh) * 64 + dd) * 512 + kb * 16 + ks * 4 + tg] =
                    make_uint4(hx, hy, lx, ly);
            }
        }
    }
}

// fused Q+K+V projection in one launch (wave packing):
// blockIdx.x: [0,256) Q tiles (8x32), [256,320) K tiles (2x32), [320,384) V tiles.
__global__ __launch_bounds__(256, 2)
void gemm_qkv(const uint32_t* __restrict__ xm,  const uint32_t* __restrict__ wqm,
              const uint32_t* __restrict__ wkm, const uint32_t* __restrict__ wvm,
              uint32_t* __restrict__ qh, uint32_t* __restrict__ ql,
              uint32_t* __restrict__ kp, uint4* __restrict__ vpout) {
    extern __shared__ uint32_t smg[];
    int bx = blockIdx.x;
    if (bx < 256) {
        gemm_body(xm, wqm, nullptr, qh, ql, nullptr, HH, KW, 1,
                  (bx >> 3) * 128, (bx & 7) * 128, smg);
    } else if (bx < 320) {
        int c = bx - 256;
        gemm_body(xm, wkm, nullptr, kp, nullptr, nullptr, RHH * HDD, KW, 2,
                  (c >> 1) * 128, (c & 1) * 128, smg);
    } else {
        int c = bx - 320;
        gemm_body(xm, wvm, nullptr, nullptr, nullptr, vpout, RHH * HDD, KW, 3,
                  (c >> 1) * 128, (c & 1) * 128, smg);
    }
}

__global__ __launch_bounds__(256, 2)
void gemm_mma(const uint32_t* __restrict__ A, const uint32_t* __restrict__ B,
              float* __restrict__ C, uint32_t* __restrict__ outh,
              uint32_t* __restrict__ outl, int N, int Kw, int mode) {
    extern __shared__ uint32_t smg[];
    gemm_body(A, B, C, outh, outl, nullptr, N, Kw, mode,
              blockIdx.y * 128, blockIdx.x * 128, smg);
}

// ---------------- build compacted row order: [causal asc | local asc] --------
__global__ __launch_bounds__(256)
void build_order(const float* __restrict__ gates, int* __restrict__ order) {
    int b = blockIdx.x, tid = threadIdx.x;
    __shared__ int cnt[256];
    bool loc[8];
    int c = 0;
#pragma unroll
    for (int i = 0; i < 8; i++) {
        loc[i] = gates[b * SS + tid * 8 + i] <= 0.5f;
        if (!loc[i]) c++;
    }
    cnt[tid] = c;
    __syncthreads();
    for (int off = 1; off < 256; off <<= 1) {
        int add = (tid >= off) ? cnt[tid - off] : 0;
        __syncthreads();
        cnt[tid] += add;
        __syncthreads();
    }
    int nC = cnt[255];
    int cb = cnt[tid] - c;
    int lb = nC + (tid * 8 - cb);
#pragma unroll
    for (int i = 0; i < 8; i++) {
        if (loc[i]) order[b * SS + lb++] = tid * 8 + i;
        else        order[b * SS + cb++] = tid * 8 + i;
    }
}

// ==================== mma flash attention (compacted rows) ===================
#define AT_SMEM (5888 * 16)

__global__ __launch_bounds__(256, 2)
void attn_mma(const uint32_t* __restrict__ qph, const uint32_t* __restrict__ qpl,
              const uint4* __restrict__ kp,  const uint4* __restrict__ vp,
              const float* __restrict__ gates, const int* __restrict__ order,
              uint32_t* __restrict__ go) {
    extern __shared__ uint4 sm4[];
    __shared__ int srows[128];
    __shared__ int sminlo, smaxhi;
    uint32_t smb = smem_u32(sm4);
    uint32_t* sQw = (uint32_t*)sm4;

    // longest-first tile order: causal tiles (low t, duration grows with t)
    // first descending, then local tiles.
    int bx = blockIdx.x;
    int t = (bx < 8) ? (7 - bx) : bx;
    int h = blockIdx.y, b = blockIdx.z;
    int tid = threadIdx.x, lane = tid & 31, w = tid >> 5;
    int gid = lane >> 2, tig = lane & 3;
    int kvh = h & 3;

    if (tid == 0) { sminlo = SS; smaxhi = 0; }
    if (tid < 128) srows[tid] = order[b * SS + t * 128 + tid];
    __syncthreads();
    if (tid < 128) {
        int myi = srows[tid];
        bool isl = gates[b * SS + myi] <= 0.5f;
        int lo = isl ? max(0, myi - 64) : 0;
        int hi = isl ? min(SS - 1, myi + 64) : myi;
        atomicMin(&sminlo, lo);
        atomicMax(&smaxhi, hi);
    }

    // ---- Q gather: row-major packed (raw order) -> frag layout ----
    {
        int r = tid >> 1, half = tid & 1;
        int ri = srows[r];
        const uint32_t* src = (half ? qpl : qph) + ((size_t)(b * SS + ri) * 16 + h) * 32;
        uint32_t* dst = sQw + half * 4096;
        int wd = r >> 4, g2 = r & 15;
        int gidq = g2 & 7, hiRow = g2 >> 3;
#pragma unroll
        for (int w32 = 0; w32 < 32; w32++) {
            int ks = w32 >> 3, rem = w32 & 7;
            int tg2 = rem & 3, comp = ((rem >> 2) << 1) | hiRow;
            dst[(((wd * 8 + gidq) * 4 + ks) * 4 + tg2) * 4 + comp] = src[w32];
        }
    }
    __syncthreads();

    int kbStart = sminlo >> 6;
    int kbEnd = (smaxhi >> 6) + 1;

    int i0 = srows[w * 16 + gid], i1 = srows[w * 16 + gid + 8];
    bool isl0 = gates[b * SS + i0] <= 0.5f;
    bool isl1 = gates[b * SS + i1] <= 0.5f;

    float m0 = -1e30f, m1 = -1e30f, l0s = 0.f, l1s = 0.f;
    float o[8][4];
#pragma unroll
    for (int nt = 0; nt < 8; nt++)
#pragma unroll
        for (int c = 0; c < 4; c++) o[nt][c] = 0.f;

    const uint4* kbase = kp + ((size_t)kvh * MM + b * SS) * 16;
    const uint4* vbase = vp + (size_t)(b * RHH + kvh) * 64 * 512;
    int fj = tid >> 2, fq = (tid & 3) * 4;

    {
        const uint4* gk = kbase + ((size_t)(kbStart * 64 + fj)) * 16 + fq;
        const uint4* gv = vbase + (size_t)fj * 512 + kbStart * 16 + fq;
        uint32_t dk = smb + (2048 + fj * 20 + fq) * 16;
        uint32_t dv = smb + (4608 + fj * 20 + fq) * 16;
#pragma unroll
        for (int c = 0; c < 4; c++) { cpa16(dk + c * 16, gk + c); cpa16(dv + c * 16, gv + c); }
        CPA_COMMIT();
    }

    for (int kb = kbStart; kb < kbEnd; kb++) {
        int buf = (kb - kbStart) & 1;
        CPA_WAIT(0);
        __syncthreads();

        if (kb + 1 < kbEnd) {
            const uint4* gk = kbase + ((size_t)((kb + 1) * 64 + fj)) * 16 + fq;
            uint32_t dk = smb + (2048 + (buf ^ 1) * 1280 + fj * 20 + fq) * 16;
#pragma unroll
            for (int c = 0; c < 4; c++) cpa16(dk + c * 16, gk + c);
            CPA_COMMIT();
        }

        const uint4* sK = sm4 + 2048 + buf * 1280;
        const uint4* sV = sm4 + 4608;

        // ---- QK^T ----
        float s[8][4];
#pragma unroll
        for (int nt = 0; nt < 8; nt++)
#pragma unroll
            for (int c = 0; c < 4; c++) s[nt][c] = 0.f;

#pragma unroll
        for (int ks = 0; ks < 4; ks++) {
            uint4 qh = sm4[w * 128 + gid * 16 + ks * 4 + tig];
            uint4 ql = sm4[1024 + w * 128 + gid * 16 + ks * 4 + tig];
#pragma unroll
            for (int nt = 0; nt < 8; nt++) {
                uint4 kk = sK[(nt * 8 + gid) * 20 + ks * 4 + tig];
                mma_bf16(s[nt], qh.x, qh.y, qh.z, qh.w, kk.x, kk.y);
                mma_bf16(s[nt], qh.x, qh.y, qh.z, qh.w, kk.z, kk.w);
                mma_bf16(s[nt], ql.x, ql.y, ql.z, ql.w, kk.x, kk.y);
            }
        }

        // ---- mask + online softmax ----
        float rm0 = -1e30f, rm1 = -1e30f;
#pragma unroll
        for (int nt = 0; nt < 8; nt++) {
            int jb = kb * 64 + nt * 8 + 2 * tig;
#pragma unroll
            for (int c = 0; c < 2; c++) {
                int j = jb + c;
                bool v0 = isl0 ? (abs(i0 - j) <= 64) : (j <= i0);
                s[nt][c] = v0 ? s[nt][c] : -1e30f;
                rm0 = fmaxf(rm0, s[nt][c]);
                bool v1 = isl1 ? (abs(i1 - j) <= 64) : (j <= i1);
                s[nt][2 + c] = v1 ? s[nt][2 + c] : -1e30f;
                rm1 = fmaxf(rm1, s[nt][2 + c]);
            }
        }
        rm0 = fmaxf(rm0, __shfl_xor_sync(0xffffffffu, rm0, 1));
        rm0 = fmaxf(rm0, __shfl_xor_sync(0xffffffffu, rm0, 2));
        rm1 = fmaxf(rm1, __shfl_xor_sync(0xffffffffu, rm1, 1));
        rm1 = fmaxf(rm1, __shfl_xor_sync(0xffffffffu, rm1, 2));

        float mn0 = fmaxf(m0, rm0), mn1 = fmaxf(m1, rm1);
        float al0f = __expf(fmaxf(m0 - mn0, -80.f));
        float al1f = __expf(fmaxf(m1 - mn1, -80.f));
        float rs0 = 0.f, rs1 = 0.f;
#pragma unroll
        for (int nt = 0; nt < 8; nt++) {
#pragma unroll
            for (int c = 0; c < 2; c++) {
                float p0 = __expf(fmaxf(s[nt][c] - mn0, -80.f));
                s[nt][c] = p0; rs0 += p0;
                float p1 = __expf(fmaxf(s[nt][2 + c] - mn1, -80.f));
                s[nt][2 + c] = p1; rs1 += p1;
            }
        }
        rs0 += __shfl_xor_sync(0xffffffffu, rs0, 1);
        rs0 += __shfl_xor_sync(0xffffffffu, rs0, 2);
        rs1 += __shfl_xor_sync(0xffffffffu, rs1, 1);
        rs1 += __shfl_xor_sync(0xffffffffu, rs1, 2);
        m0 = mn0; m1 = mn1;
        l0s = l0s * al0f + rs0;
        l1s = l1s * al1f + rs1;
#pragma unroll
        for (int nt = 0; nt < 8; nt++) {
            o[nt][0] *= al0f; o[nt][1] *= al0f;
            o[nt][2] *= al1f; o[nt][3] *= al1f;
        }

        // ---- PV (P from registers, single V buffer) ----
#pragma unroll
        for (int ks = 0; ks < 4; ks++) {
            uint32_t ah0, al0, ah1, al1, ah2, al2, ah3, al3;
            bf16_split2(s[2 * ks][0],     s[2 * ks][1],     ah0, al0);
            bf16_split2(s[2 * ks][2],     s[2 * ks][3],     ah1, al1);
            bf16_split2(s[2 * ks + 1][0], s[2 * ks + 1][1], ah2, al2);
            bf16_split2(s[2 * ks + 1][2], s[2 * ks + 1][3], ah3, al3);
#pragma unroll
            for (int nt = 0; nt < 8; nt++) {
                uint4 vv = sV[(nt * 8 + gid) * 20 + ks * 4 + tig];
                mma_bf16(o[nt], ah0, ah1, ah2, ah3, vv.x, vv.y);
                mma_bf16(o[nt], ah0, ah1, ah2, ah3, vv.z, vv.w);
                mma_bf16(o[nt], al0, al1, al2, al3, vv.x, vv.y);
            }
        }
        __syncthreads();

        if (kb + 1 < kbEnd) {
            const uint4* gv = vbase + (size_t)fj * 512 + (kb + 1) * 16 + fq;
            uint32_t dv = smb + (4608 + fj * 20 + fq) * 16;
#pragma unroll
            for (int c = 0; c < 4; c++) cpa16(dv + c * 16, gv + c);
            CPA_COMMIT();
        }
    }

    // ---- epilogue: merged interleaved positions (for O-gemm uint4 frags) ----
    float inv0 = (l0s > 0.f) ? 1.f / l0s : 0.f;
    float inv1 = (l1s > 0.f) ? 1.f / l1s : 0.f;
    size_t base0 = (size_t)(b * SS + i0) * 1024 + h * 64;
    size_t base1 = (size_t)(b * SS + i1) * 1024 + h * 64;
#pragma unroll
    for (int nt = 0; nt < 8; nt++) {
        int pos = (nt >> 1) * 16 + tig * 4 + (nt & 1);
        uint32_t h0, l0, h1, l1;
        bf16_split2(o[nt][0] * inv0, o[nt][1] * inv0, h0, l0);
        bf16_split2(o[nt][2] * inv1, o[nt][3] * inv1, h1, l1);
        go[base0 + pos] = h0; go[base0 + pos + 2] = l0;
        go[base1 + pos] = h1; go[base1 + pos + 2] = l1;
    }
}

// ---------------- gate: LN + dot(wg) + sigmoid(clamp) -----------------------
__global__ void gate_kernel(const float* __restrict__ x,
                            const float* __restrict__ wg,
                            const float* __restrict__ bg,
                            const float* __restrict__ gamma,
                            const float* __restrict__ beta,
                            float* __restrict__ gates) {
    int token = blockIdx.x;
    const float* row = x + (size_t)token * HH;
    __shared__ float red[256];
    int tid = threadIdx.x;

    float xr[4];
#pragma unroll
    for (int i = 0; i < 4; i++) xr[i] = row[tid + i * 256];

    float s = xr[0] + xr[1] + xr[2] + xr[3];
    red[tid] = s; __syncthreads();
    for (int o = 128; o > 0; o >>= 1) { if (tid < o) red[tid] += red[tid + o]; __syncthreads(); }
    float mu = red[0] * (1.0f / HH);
    __syncthreads();

    float v = 0.f;
#pragma unroll
    for (int i = 0; i < 4; i++) { float d = xr[i] - mu; v = fmaf(d, d, v); }
    red[tid] = v; __syncthreads();
    for (int o = 128; o > 0; o >>= 1) { if (tid < o) red[tid] += red[tid + o]; __syncthreads(); }
    float rstd = rsqrtf(red[0] * (1.0f / HH) + 1e-5f);
    __syncthreads();

    float dot = 0.f;
#pragma unroll
    for (int i = 0; i < 4; i++) {
        int hh = tid + i * 256;
        float y = fmaf((xr[i] - mu) * rstd, gamma[hh], beta[hh]);
        dot = fmaf(y, wg[hh], dot);
    }
    red[tid] = dot; __syncthreads();
    for (int o = 128; o > 0; o >>= 1) { if (tid < o) red[tid] += red[tid + o]; __syncthreads(); }
    if (tid == 0) {
        float z = red[0] + bg[0];
        z = fminf(10.f, fmaxf(-10.f, z));
        gates[token] = 1.f / (1.f + expf(-z));
    }
}

// ---------------- gate regularization loss ------------------------------------
__global__ void regloss_kernel(const float* __restrict__ gates, float* __restrict__ out,
                               int writeIdx) {
    __shared__ float red[256];
    int tid = threadIdx.x;
    float acc = 0.f;
    for (int t = tid; t < MM; t += 256) {
        float g = gates[t];
        float gs = fminf(fmaxf(g, 1e-5f), 1.f - 1e-5f);
        float binary = g * (1.f - g);
        float ent = g * logf(gs) + (1.f - g) * logf(1.f - gs);
        acc += 0.1f * binary - 0.01f * ent + 0.1f * g;
    }
    red[tid] = acc; __syncthreads();
    for (int o = 128; o > 0; o >>= 1) { if (tid < o) red[tid] += red[tid + o]; __syncthreads(); }
    if (tid == 0) out[writeIdx] = red[0] * (1.0f / MM);
}

// ---------------- launch ------------------------------------------------------
extern "C" void kernel_launch(void* const* d_in, const int* in_sizes, int n_in,
                              void* d_out, int out_size) {
    const float* x     = (const float*)d_in[0];
    const float* Wq    = (const float*)d_in[1];
    const float* Wk    = (const float*)d_in[2];
    const float* Wv    = (const float*)d_in[3];
    const float* Wo    = (const float*)d_in[4];
    const float* Wg    = (const float*)d_in[5];
    const float* bg    = (const float*)d_in[6];
    const float* gamma = (const float*)d_in[7];
    const float* beta  = (const float*)d_in[8];
    float* out = (float*)d_out;

    float *pGates;
    uint32_t *pX, *pWq, *pWk, *pWv, *pWo;
    uint32_t *pQh, *pQl, *pKp, *pO;
    uint4 *pVp;
    int *pOrder;
    cudaGetSymbolAddress((void**)&pGates, g_gates);
    cudaGetSymbolAddress((void**)&pOrder, g_order);
    cudaGetSymbolAddress((void**)&pX,     g_x);
    cudaGetSymbolAddress((void**)&pWq,    g_wq);
    cudaGetSymbolAddress((void**)&pWk,    g_wk);
    cudaGetSymbolAddress((void**)&pWv,    g_wv);
    cudaGetSymbolAddress((void**)&pWo,    g_wo);
    cudaGetSymbolAddress((void**)&pQh,    g_qph);
    cudaGetSymbolAddress((void**)&pQl,    g_qpl);
    cudaGetSymbolAddress((void**)&pKp,    g_kp);
    cudaGetSymbolAddress((void**)&pVp,    g_vp);
    cudaGetSymbolAddress((void**)&pO,     g_o);

    cudaFuncSetAttribute(gemm_qkv, cudaFuncAttributeMaxDynamicSharedMemorySize, GM_SMEM);
    cudaFuncSetAttribute(gemm_mma, cudaFuncAttributeMaxDynamicSharedMemorySize, GM_SMEM);
    cudaFuncSetAttribute(attn_mma, cudaFuncAttributeMaxDynamicSharedMemorySize, AT_SMEM);

    gate_kernel<<<MM, 256>>>(x, Wg, bg, gamma, beta, pGates);
    build_order<<<BB, 256>>>(pGates, pOrder);

    split_all<<<1024, 256>>>(x, Wq, Wk, Wv, Wo, pX, pWq, pWk, pWv, pWo);

    gemm_qkv<<<384, 256, GM_SMEM>>>(pX, pWq, pWk, pWv, pQh, pQl, pKp, pVp);

    attn_mma<<<dim3(SS / 128, NHD, BB), 256, AT_SMEM>>>(
        pQh, pQl, (const uint4*)pKp, pVp, pGates, pOrder, pO);

    gemm_mma<<<dim3(HH / 128, MM / 128), 256, GM_SMEM>>>(
        pO, pWo, out, nullptr, nullptr, HH, KW, 0);

    if (out_size > MM * HH)
        regloss_kernel<<<1, 256>>>(pGates, out, MM * HH);
}